// round 13
// baseline (speedup 1.0000x reference)
#include <cuda_runtime.h>
#include <cuda_fp16.h>
#include <cstdint>

#define Bc 4
#define Tc 4096
#define Hc 2048
#define Dc 256
#define Nc 32768
#define MGP (Bc*Tc)
#define EPSC 1e-8f
#define BLOB 8192

// ---------------- device scratch ----------------
__device__ unsigned char g_Af[(size_t)128 * 64 * BLOB];
__device__ unsigned char g_Hmhi[(size_t)32 * 64 * BLOB];
__device__ unsigned char g_Hmlo[(size_t)32 * 64 * BLOB];
__device__ unsigned char g_Wcf[(size_t)8 * 64 * BLOB];
__device__ unsigned char g_Wohi[(size_t)2 * 64 * BLOB];
__device__ unsigned char g_Wolo[(size_t)2 * 64 * BLOB];
__device__ unsigned char g_Bb8[(size_t)256 * 4 * BLOB];
__device__ unsigned char g_oang8[(size_t)32 * 4 * BLOB];
__device__ float g_ang[(size_t)Tc * Dc];
__device__ float g_na[Tc];
__device__ float g_bc1[1024];
__device__ float g_wc2[1024];
__device__ float g_obs_mean[(size_t)Tc * Dc];
__device__ float g_part[8 * MGP];
__device__ float g_binv[Nc];
__device__ unsigned char g_active[Nc];
__device__ unsigned long long g_best[Tc];
__device__ int g_weird;
__device__ int g_off4;

// ---------------- helpers ----------------
__device__ __forceinline__ uint32_t smem_u32(const void* p) {
    uint32_t a;
    asm("{ .reg .u64 t; cvta.to.shared.u64 t, %1; cvt.u32.u64 %0, t; }" : "=r"(a) : "l"(p));
    return a;
}
#define LDSM4(R0, R1, R2, R3, A) \
    asm volatile("ldmatrix.sync.aligned.m8n8.x4.shared.b16 {%0,%1,%2,%3}, [%4];" \
        : "=r"(R0), "=r"(R1), "=r"(R2), "=r"(R3) : "r"(A))
#define MMA_F16(D, A, B) \
    asm volatile("mma.sync.aligned.m16n8k16.row.col.f32.f16.f16.f32 " \
        "{%0,%1,%2,%3}, {%4,%5,%6,%7}, {%8,%9}, {%0,%1,%2,%3};" \
        : "+f"((D)[0]), "+f"((D)[1]), "+f"((D)[2]), "+f"((D)[3]) \
        : "r"((A)[0]), "r"((A)[1]), "r"((A)[2]), "r"((A)[3]), "r"((B)[0]), "r"((B)[1]))
#define MMA_F8(D, A, B) \
    asm volatile("mma.sync.aligned.m16n8k32.row.col.f32.e4m3.e4m3.f32 " \
        "{%0,%1,%2,%3}, {%4,%5,%6,%7}, {%8,%9}, {%0,%1,%2,%3};" \
        : "+f"((D)[0]), "+f"((D)[1]), "+f"((D)[2]), "+f"((D)[3]) \
        : "r"((A)[0]), "r"((A)[1]), "r"((A)[2]), "r"((A)[3]), "r"((B)[0]), "r"((B)[1]))
#define CPBULK(DST, SRC, BYTES, MBAR) \
    asm volatile("cp.async.bulk.shared::cta.global.mbarrier::complete_tx::bytes [%0], [%1], %2, [%3];" \
        :: "r"((uint32_t)(DST)), "l"(SRC), "r"((uint32_t)(BYTES)), "r"((uint32_t)(MBAR)) : "memory")
#define MBAR_INIT(mb, n) \
    asm volatile("mbarrier.init.shared.b64 [%0], %1;" :: "r"((uint32_t)(mb)), "r"((uint32_t)(n)) : "memory")
#define MBAR_EXPECT_TX(mb, bytes) \
    asm volatile("mbarrier.arrive.expect_tx.shared.b64 _, [%0], %1;" \
        :: "r"((uint32_t)(mb)), "r"((uint32_t)(bytes)) : "memory")
#define MBAR_WAIT(mb, ph) do { \
    uint32_t _m = (uint32_t)(mb); uint32_t _p = (uint32_t)(ph); uint32_t _d; \
    asm volatile("{\n\t.reg .pred p;\n\t" \
        "mbarrier.try_wait.parity.acquire.cta.shared::cta.b64 p, [%1], %2;\n\t" \
        "selp.b32 %0, 1, 0, p;\n\t}" : "=r"(_d) : "r"(_m), "r"(_p) : "memory"); \
    if (!_d) { \
        asm volatile("{\n\t.reg .pred P1;\n\t" \
            "WL_%=:\n\t" \
            "mbarrier.try_wait.parity.acquire.cta.shared::cta.b64 P1, [%0], %1, 0x989680;\n\t" \
            "@P1 bra.uni WD_%=;\n\t" \
            "bra.uni WL_%=;\n\t" \
            "WD_%=:\n\t}" :: "r"(_m), "r"(_p) : "memory"); \
    } } while (0)

__device__ __forceinline__ unsigned enc_f(float f) {
    unsigned u = __float_as_uint(f);
    return (u & 0x80000000u) ? ~u : (u | 0x80000000u);
}
__device__ __forceinline__ float dec_f(unsigned e) {
    unsigned u = (e & 0x80000000u) ? (e ^ 0x80000000u) : ~e;
    return __uint_as_float(u);
}
__device__ __forceinline__ float sigmoidf_(float x) { return 1.0f / (1.0f + expf(-x)); }
__device__ __forceinline__ float softplusf_(float x) {
    return fmaxf(x, 0.0f) + log1pf(expf(-fabsf(x)));
}
__device__ __forceinline__ uint16_t pack_e4m3(float lo, float hi) {
    uint16_t r;
    asm("cvt.rn.satfinite.e4m3x2.f32 %0, %1, %2;" : "=h"(r) : "f"(hi), "f"(lo));
    return r;
}
__device__ __forceinline__ uint32_t pk_h2(float a, float b) {
    __half2 h = __halves2half2(__float2half_rn(a), __float2half_rn(b));
    return *(uint32_t*)&h;
}

// ---------------- prep kernels ----------------
__global__ void prep_hidden_kernel(const float* __restrict__ hidden) {
    int idx = blockIdx.x * blockDim.x + threadIdx.x;
    int t = idx >> 6, c = idx & 63;
    const int r = t & 127;
    const int sw = (r >> 1) & 3;
    float acc[32];
    #pragma unroll
    for (int j = 0; j < 32; j++) acc[j] = 0.0f;
    #pragma unroll
    for (int b = 0; b < Bc; b++) {
        const float* src = hidden + ((size_t)(b * Tc + t)) * Hc + c * 32;
        float v[32];
        #pragma unroll
        for (int q = 0; q < 8; q++) {
            float4 f = *(const float4*)(src + q * 4);
            v[q*4+0] = f.x; v[q*4+1] = f.y; v[q*4+2] = f.z; v[q*4+3] = f.w;
        }
        #pragma unroll
        for (int j = 0; j < 32; j++) acc[j] += v[j];
        char* dst = (char*)g_Af + ((size_t)(((b * Tc + t) >> 7) * 64 + c)) * BLOB + r * 64;
        #pragma unroll
        for (int k16 = 0; k16 < 4; k16++) {
            uint4 u = make_uint4(pk_h2(v[k16*8+0], v[k16*8+1]), pk_h2(v[k16*8+2], v[k16*8+3]),
                                 pk_h2(v[k16*8+4], v[k16*8+5]), pk_h2(v[k16*8+6], v[k16*8+7]));
            *(uint4*)(dst + ((k16 ^ sw) << 4)) = u;
        }
    }
    float hi[32], lo[32];
    #pragma unroll
    for (int j = 0; j < 32; j++) {
        float m = acc[j] * 0.25f;
        float h = __half2float(__float2half_rn(m));
        hi[j] = m;
        lo[j] = m - h;
    }
    size_t boff = ((size_t)((t >> 7) * 64 + c)) * BLOB + r * 64;
    char* dh = (char*)g_Hmhi + boff;
    char* dl = (char*)g_Hmlo + boff;
    #pragma unroll
    for (int k16 = 0; k16 < 4; k16++) {
        uint4 uh = make_uint4(pk_h2(hi[k16*8+0], hi[k16*8+1]), pk_h2(hi[k16*8+2], hi[k16*8+3]),
                              pk_h2(hi[k16*8+4], hi[k16*8+5]), pk_h2(hi[k16*8+6], hi[k16*8+7]));
        uint4 ul = make_uint4(pk_h2(lo[k16*8+0], lo[k16*8+1]), pk_h2(lo[k16*8+2], lo[k16*8+3]),
                              pk_h2(lo[k16*8+4], lo[k16*8+5]), pk_h2(lo[k16*8+6], lo[k16*8+7]));
        *(uint4*)(dh + ((k16 ^ sw) << 4)) = uh;
        *(uint4*)(dl + ((k16 ^ sw) << 4)) = ul;
    }
}

__global__ void prep_weights_kernel(const float* __restrict__ Wg1, const float* __restrict__ Wp1,
                                    const float* __restrict__ Wobs) {
    int idx = blockIdx.x * blockDim.x + threadIdx.x;
    int row = idx >> 6, c = idx & 63;
    float v[32];
    const float* src;
    if (row < 512)        src = Wg1 + (size_t)row * Hc + c * 32;
    else if (row < 1024)  src = Wp1 + (size_t)(row - 512) * Hc + c * 32;
    else                  src = Wobs + (size_t)(row - 1024) * Hc + c * 32;
    #pragma unroll
    for (int q = 0; q < 8; q++) {
        float4 f = *(const float4*)(src + q * 4);
        v[q*4+0] = f.x; v[q*4+1] = f.y; v[q*4+2] = f.z; v[q*4+3] = f.w;
    }
    if (row < 1024) {
        int r = row & 127, sw = (r >> 1) & 3;
        char* dst = (char*)g_Wcf + ((size_t)((row >> 7) * 64 + c)) * BLOB + r * 64;
        #pragma unroll
        for (int k16 = 0; k16 < 4; k16++) {
            uint4 u = make_uint4(pk_h2(v[k16*8+0], v[k16*8+1]), pk_h2(v[k16*8+2], v[k16*8+3]),
                                 pk_h2(v[k16*8+4], v[k16*8+5]), pk_h2(v[k16*8+6], v[k16*8+7]));
            *(uint4*)(dst + ((k16 ^ sw) << 4)) = u;
        }
    } else {
        int r2 = row - 1024;
        int r = r2 & 127, sw = (r >> 1) & 3;
        size_t boff = ((size_t)((r2 >> 7) * 64 + c)) * BLOB + r * 64;
        char* dh = (char*)g_Wohi + boff;
        char* dl = (char*)g_Wolo + boff;
        float hi[32], lo[32];
        #pragma unroll
        for (int j = 0; j < 32; j++) {
            float h = __half2float(__float2half_rn(v[j]));
            hi[j] = v[j];
            lo[j] = v[j] - h;
        }
        #pragma unroll
        for (int k16 = 0; k16 < 4; k16++) {
            uint4 uh = make_uint4(pk_h2(hi[k16*8+0], hi[k16*8+1]), pk_h2(hi[k16*8+2], hi[k16*8+3]),
                                  pk_h2(hi[k16*8+4], hi[k16*8+5]), pk_h2(hi[k16*8+6], hi[k16*8+7]));
            uint4 ul = make_uint4(pk_h2(lo[k16*8+0], lo[k16*8+1]), pk_h2(lo[k16*8+2], lo[k16*8+3]),
                                  pk_h2(lo[k16*8+4], lo[k16*8+5]), pk_h2(lo[k16*8+6], lo[k16*8+7]));
            *(uint4*)(dh + ((k16 ^ sw) << 4)) = uh;
            *(uint4*)(dl + ((k16 ^ sw) << 4)) = ul;
        }
    }
}

__global__ void prep_small_kernel(const float* __restrict__ bg1, const float* __restrict__ bp1,
                                  const float* __restrict__ Wg2, const float* __restrict__ Wp2) {
    int i = blockIdx.x * blockDim.x + threadIdx.x;
    if (i < 1024) {
        g_bc1[i] = (i < 512) ? bg1[i] : bp1[i - 512];
        g_wc2[i] = (i < 512) ? Wg2[i] : Wp2[i - 512];
    }
}

__global__ void prep_beliefs_kernel(const float* __restrict__ beliefs) {
    int idx = blockIdx.x * blockDim.x + threadIdx.x;
    int n = idx >> 2, c = idx & 3;
    int r = n & 127, sw = (r >> 1) & 3;
    float bi = g_binv[n];
    const float* src = beliefs + (size_t)n * Dc + c * 64;
    char* dst = (char*)g_Bb8 + ((size_t)((n >> 7) * 4 + c)) * BLOB + r * 64;
    #pragma unroll
    for (int k16 = 0; k16 < 4; k16++) {
        uint32_t w[4];
        #pragma unroll
        for (int q = 0; q < 4; q++) {
            float4 f = *(const float4*)(src + k16 * 16 + q * 4);
            uint16_t a = pack_e4m3(f.x * bi, f.y * bi);
            uint16_t b = pack_e4m3(f.z * bi, f.w * bi);
            w[q] = ((uint32_t)b << 16) | a;
        }
        *(uint4*)(dst + ((k16 ^ sw) << 4)) = make_uint4(w[0], w[1], w[2], w[3]);
    }
}

__global__ void detect_mask_kernel(const unsigned char* __restrict__ m) {
    int i = blockIdx.x * blockDim.x + threadIdx.x;
    unsigned char c = m[i];
    int w = 0, o = 0;
    if (c > 1) w = 1;
    if (c != 0 && (i & 3)) o = 1;
    w = __reduce_or_sync(0xffffffffu, w);
    o = __reduce_or_sync(0xffffffffu, o);
    if ((threadIdx.x & 31) == 0) {
        if (w) atomicOr(&g_weird, 1);
        if (o) atomicOr(&g_off4, 1);
    }
}
__global__ void convert_mask_kernel(const void* __restrict__ m) {
    int i = blockIdx.x * blockDim.x + threadIdx.x;
    if (i >= Nc) return;
    int fmt = g_weird ? 2 : (g_off4 ? 1 : 0);
    unsigned char a;
    if (fmt == 0)      a = (((const int*)m)[i] != 0);
    else if (fmt == 1) a = (((const unsigned char*)m)[i] != 0);
    else               a = (((const float*)m)[i] != 0.0f);
    g_active[i] = a;
}
__global__ void binv_kernel(const float* __restrict__ beliefs) {
    int row = blockIdx.x * 8 + (threadIdx.x >> 5);
    int lane = threadIdx.x & 31;
    const float4* p = reinterpret_cast<const float4*>(beliefs + (size_t)row * Dc);
    float s = 0.0f;
    #pragma unroll
    for (int r = 0; r < 2; r++) {
        float4 v = p[lane + r * 32];
        s += v.x * v.x + v.y * v.y + v.z * v.z + v.w * v.w;
    }
    #pragma unroll
    for (int o = 16; o > 0; o >>= 1) s += __shfl_down_sync(0xffffffffu, s, o);
    if (lane == 0)
        g_binv[row] = g_active[row] ? (16.0f / fmaxf(sqrtf(s), EPSC)) : 0.0f;
}

__global__ void init_best_kernel() {
    int i = blockIdx.x * blockDim.x + threadIdx.x;
    if (i < Tc) g_best[i] = 0ULL;
    if (i == 0) { g_weird = 0; g_off4 = 0; }
}

// ============ gp GEMM: fp16 single-term, k128 chunks, 3-stage ============
#define GP_STAGE2 32768
#define GP_SMEM 98304
__global__ __launch_bounds__(256, 2) void gp_mma_kernel() {
    extern __shared__ __align__(128) char dsm[];
    __shared__ float s_b1[128], s_w2[128], s_red[128];
    __shared__ __align__(8) unsigned long long s_mbar[3];

    const int tid = threadIdx.x, lane = tid & 31, wid = tid >> 5;
    const int warp_m = (wid >> 1) * 32;
    const int warp_n = (wid & 1) * 64;
    const uint32_t sbase = smem_u32(dsm);
    const uint32_t mb = smem_u32(s_mbar);

    const int rowA = warp_m + (lane & 15);
    const uint32_t cA = (uint32_t)(lane >> 4);
    const uint32_t swA = (uint32_t)((rowA >> 1) & 3);
    const uint32_t aoff = (uint32_t)rowA * 64;
    const int rowB = warp_n + ((lane >> 4) << 3) + (lane & 7);
    const uint32_t cB = (uint32_t)((lane >> 3) & 1);
    const uint32_t swB = (uint32_t)((rowB >> 1) & 3);
    const uint32_t boff = (uint32_t)rowB * 64;

    const int nt = blockIdx.x;
    const int mt = blockIdx.y;
    const int m0 = mt * 128, nbase = nt * 128;
    const int qr = lane >> 2;
    const int qc = (lane & 3) * 2;

    float acc[2][8][4];
    #pragma unroll
    for (int i = 0; i < 2; i++)
        #pragma unroll
        for (int j = 0; j < 8; j++)
            #pragma unroll
            for (int k = 0; k < 4; k++) acc[i][j][k] = 0.0f;

    if (tid < 128) {
        s_b1[tid] = g_bc1[nbase + tid];
        s_w2[tid] = g_wc2[nbase + tid];
        s_red[tid] = 0.0f;
    }
    const char* gA = (const char*)g_Af + (size_t)mt * 64 * BLOB;
    const char* gB = (const char*)g_Wcf + (size_t)nt * 64 * BLOB;

    if (tid == 0) {
        #pragma unroll
        for (int s = 0; s < 3; s++) MBAR_INIT(mb + s * 8, 1);
    }
    __syncthreads();
    if (tid == 0) {
        #pragma unroll
        for (int c = 0; c < 2; c++) {
            const uint32_t st = sbase + c * GP_STAGE2;
            MBAR_EXPECT_TX(mb + c * 8, GP_STAGE2);
            CPBULK(st,         gA + (size_t)(2*c)     * BLOB, BLOB, mb + c * 8);
            CPBULK(st + 8192,  gA + (size_t)(2*c + 1) * BLOB, BLOB, mb + c * 8);
            CPBULK(st + 16384, gB + (size_t)(2*c)     * BLOB, BLOB, mb + c * 8);
            CPBULK(st + 24576, gB + (size_t)(2*c + 1) * BLOB, BLOB, mb + c * 8);
        }
    }

    for (int c = 0; c < 32; c++) {
        MBAR_WAIT(mb + (c % 3) * 8, (c / 3) & 1);
        __syncthreads();
        if (tid == 0 && c + 2 < 32) {
            const int s = (c + 2) % 3;
            const uint32_t st = sbase + s * GP_STAGE2;
            MBAR_EXPECT_TX(mb + s * 8, GP_STAGE2);
            CPBULK(st,         gA + (size_t)(2*(c+2))     * BLOB, BLOB, mb + s * 8);
            CPBULK(st + 8192,  gA + (size_t)(2*(c+2) + 1) * BLOB, BLOB, mb + s * 8);
            CPBULK(st + 16384, gB + (size_t)(2*(c+2))     * BLOB, BLOB, mb + s * 8);
            CPBULK(st + 24576, gB + (size_t)(2*(c+2) + 1) * BLOB, BLOB, mb + s * 8);
        }
        const uint32_t uS = sbase + (c % 3) * GP_STAGE2;
        #pragma unroll
        for (int h = 0; h < 2; h++) {
            const uint32_t uA = uS + (uint32_t)h * 8192;
            const uint32_t uB = uS + 16384 + (uint32_t)h * 8192;
            #pragma unroll
            for (int ks = 0; ks < 2; ks++) {
                const uint32_t oa = ((cA | (ks << 1)) ^ swA) << 4;
                const uint32_t ob = ((cB | (ks << 1)) ^ swB) << 4;
                uint32_t a[2][4];
                LDSM4(a[0][0], a[0][1], a[0][2], a[0][3], uA + aoff + oa);
                LDSM4(a[1][0], a[1][1], a[1][2], a[1][3], uA + aoff + 1024 + oa);
                uint32_t b[8][2];
                #pragma unroll
                for (int jp = 0; jp < 4; jp++) {
                    LDSM4(b[2*jp][0], b[2*jp][1], b[2*jp+1][0], b[2*jp+1][1],
                          uB + boff + (uint32_t)jp * 1024 + ob);
                }
                #pragma unroll
                for (int mt2 = 0; mt2 < 2; mt2++)
                    #pragma unroll
                    for (int nj = 0; nj < 8; nj++)
                        MMA_F16(acc[mt2][nj], a[mt2], b[nj]);
            }
        }
    }
    __syncthreads();

    #pragma unroll
    for (int mt2 = 0; mt2 < 2; mt2++) {
        float p0 = 0.0f, p1 = 0.0f;
        #pragma unroll
        for (int nj = 0; nj < 8; nj++) {
            int col = warp_n + nj * 8 + qc;
            p0 += fmaxf(acc[mt2][nj][0] + s_b1[col], 0.0f) * s_w2[col]
                + fmaxf(acc[mt2][nj][1] + s_b1[col + 1], 0.0f) * s_w2[col + 1];
            p1 += fmaxf(acc[mt2][nj][2] + s_b1[col], 0.0f) * s_w2[col]
                + fmaxf(acc[mt2][nj][3] + s_b1[col + 1], 0.0f) * s_w2[col + 1];
        }
        p0 += __shfl_xor_sync(0xffffffffu, p0, 1);
        p0 += __shfl_xor_sync(0xffffffffu, p0, 2);
        p1 += __shfl_xor_sync(0xffffffffu, p1, 1);
        p1 += __shfl_xor_sync(0xffffffffu, p1, 2);
        if ((lane & 3) == 0) {
            atomicAdd(&s_red[warp_m + mt2 * 16 + qr], p0);
            atomicAdd(&s_red[warp_m + mt2 * 16 + 8 + qr], p1);
        }
    }
    __syncthreads();
    if (tid < 128) g_part[nt * MGP + m0 + tid] = s_red[tid];
}

// ============ obs GEMM: fp16 3-term hi/lo, 2-stage ============
#define OB_STAGE 32768
#define OB_SMEM 65536
__global__ __launch_bounds__(256, 2) void obs_mma_kernel() {
    extern __shared__ __align__(128) char dsm[];
    __shared__ __align__(8) unsigned long long s_mbar[2];

    const int tid = threadIdx.x, lane = tid & 31, wid = tid >> 5;
    const int id = blockIdx.x;
    const int nt = id & 1;
    const int mt = id >> 1;
    const int m0 = mt * 128, nbase = nt * 128;
    const int warp_m = (wid >> 1) * 32;
    const int warp_n = (wid & 1) * 64;
    const uint32_t sbase = smem_u32(dsm);
    const uint32_t mb = smem_u32(s_mbar);

    const int rowA = warp_m + (lane & 15);
    const uint32_t cA = (uint32_t)(lane >> 4);
    const uint32_t swA = (uint32_t)((rowA >> 1) & 3);
    const uint32_t aoff = (uint32_t)rowA * 64;
    const int rowB = warp_n + ((lane >> 4) << 3) + (lane & 7);
    const uint32_t cB = (uint32_t)((lane >> 3) & 1);
    const uint32_t swB = (uint32_t)((rowB >> 1) & 3);
    const uint32_t boff = (uint32_t)rowB * 64;

    const char* gAh = (const char*)g_Hmhi + (size_t)mt * 64 * BLOB;
    const char* gAl = (const char*)g_Hmlo + (size_t)mt * 64 * BLOB;
    const char* gBh = (const char*)g_Wohi + (size_t)nt * 64 * BLOB;
    const char* gBl = (const char*)g_Wolo + (size_t)nt * 64 * BLOB;

    float acc[2][8][4];
    #pragma unroll
    for (int i = 0; i < 2; i++)
        #pragma unroll
        for (int j = 0; j < 8; j++)
            #pragma unroll
            for (int k = 0; k < 4; k++) acc[i][j][k] = 0.0f;

    if (tid == 0) { MBAR_INIT(mb, 1); MBAR_INIT(mb + 8, 1); }
    __syncthreads();
    if (tid == 0) {
        MBAR_EXPECT_TX(mb, OB_STAGE);
        CPBULK(sbase,         gAh, BLOB, mb);
        CPBULK(sbase + 8192,  gAl, BLOB, mb);
        CPBULK(sbase + 16384, gBh, BLOB, mb);
        CPBULK(sbase + 24576, gBl, BLOB, mb);
    }

    for (int c = 0; c < 64; c++) {
        MBAR_WAIT(mb + (c & 1) * 8, (c >> 1) & 1);
        __syncthreads();
        if (tid == 0 && c + 1 < 64) {
            const int s = (c + 1) & 1;
            const uint32_t st = sbase + s * OB_STAGE;
            MBAR_EXPECT_TX(mb + s * 8, OB_STAGE);
            CPBULK(st,         gAh + (size_t)(c + 1) * BLOB, BLOB, mb + s * 8);
            CPBULK(st + 8192,  gAl + (size_t)(c + 1) * BLOB, BLOB, mb + s * 8);
            CPBULK(st + 16384, gBh + (size_t)(c + 1) * BLOB, BLOB, mb + s * 8);
            CPBULK(st + 24576, gBl + (size_t)(c + 1) * BLOB, BLOB, mb + s * 8);
        }
        const uint32_t uS = sbase + (c & 1) * OB_STAGE;
        #pragma unroll
        for (int tr = 0; tr < 3; tr++) {
            const uint32_t uA = uS + (tr == 2 ? 8192u : 0u);
            const uint32_t uB = uS + 16384u + (tr == 1 ? 8192u : 0u);
            #pragma unroll
            for (int ks = 0; ks < 2; ks++) {
                const uint32_t oa = ((cA | (ks << 1)) ^ swA) << 4;
                const uint32_t ob = ((cB | (ks << 1)) ^ swB) << 4;
                uint32_t a[2][4];
                LDSM4(a[0][0], a[0][1], a[0][2], a[0][3], uA + aoff + oa);
                LDSM4(a[1][0], a[1][1], a[1][2], a[1][3], uA + aoff + 1024 + oa);
                uint32_t b[8][2];
                #pragma unroll
                for (int jp = 0; jp < 4; jp++) {
                    LDSM4(b[2*jp][0], b[2*jp][1], b[2*jp+1][0], b[2*jp+1][1],
                          uB + boff + (uint32_t)jp * 1024 + ob);
                }
                #pragma unroll
                for (int mt2 = 0; mt2 < 2; mt2++)
                    #pragma unroll
                    for (int nj = 0; nj < 8; nj++)
                        MMA_F16(acc[mt2][nj], a[mt2], b[nj]);
            }
        }
    }

    const int qr = lane >> 2;
    const int qc = (lane & 3) * 2;
    #pragma unroll
    for (int mt2 = 0; mt2 < 2; mt2++)
        #pragma unroll
        for (int nj = 0; nj < 8; nj++) {
            int row = m0 + warp_m + mt2 * 16 + qr;
            int col = nbase + warp_n + nj * 8 + qc;
            *(float2*)(g_obs_mean + (size_t)row * Dc + col) = make_float2(acc[mt2][nj][0], acc[mt2][nj][1]);
            *(float2*)(g_obs_mean + (size_t)(row + 8) * Dc + col) = make_float2(acc[mt2][nj][2], acc[mt2][nj][3]);
        }
}

// ============ angles ============
__global__ __launch_bounds__(256) void angles_kernel() {
    __shared__ float sred[256];
    __shared__ float s_inv;
    int t = blockIdx.x;
    int d = threadIdx.x;
    float v = g_obs_mean[(size_t)t * Dc + d];
    sred[d] = v * v;
    __syncthreads();
    for (int s = 128; s > 0; s >>= 1) {
        if (d < s) sred[d] += sred[d + s];
        __syncthreads();
    }
    if (d == 0) {
        float nrm = sqrtf(sred[0]);
        s_inv = 1.0f / fmaxf(nrm, EPSC);
        g_na[t] = nrm * s_inv;
    }
    __syncthreads();
    float ang = v * s_inv;
    g_ang[(size_t)t * Dc + d] = ang;
    uint16_t pk = pack_e4m3(ang * 16.0f, 0.0f);
    int mt = t >> 7, r = t & 127, sw = (r >> 1) & 3;
    int c = d >> 6;
    int pos = d & 63;
    int k16 = pos >> 4;
    size_t off = ((size_t)(mt * 4 + c)) * BLOB + r * 64 + ((k16 ^ sw) << 4) + (pos & 15);
    g_oang8[off] = (unsigned char)(pk & 0xFF);
}

// ============ sims GEMM ============
#define SIMS_B_OFF 32768
#define SIMS_SMEM 65536
__global__ __launch_bounds__(256, 2) void sims_mma_kernel() {
    extern __shared__ __align__(128) char dsm[];
    __shared__ __align__(8) unsigned long long s_mbar[5];

    const int tid = threadIdx.x, lane = tid & 31, wid = tid >> 5;
    const int ng = blockIdx.x;
    const int mt = blockIdx.y;
    const int n_base = ng * 1024, m0 = mt * 128;
    const int warp_m = (wid >> 1) * 32;
    const int warp_n = (wid & 1) * 64;
    const uint32_t sbase = smem_u32(dsm);
    const uint32_t mb = smem_u32(s_mbar);

    const int rowA = warp_m + (lane & 15);
    const uint32_t cA = (uint32_t)(lane >> 4);
    const uint32_t swA = (uint32_t)((rowA >> 1) & 3);
    const uint32_t aoff = (uint32_t)rowA * 64;
    const int rowB = warp_n + ((lane >> 4) << 3) + (lane & 7);
    const uint32_t cB = (uint32_t)((lane >> 3) & 1);
    const uint32_t swB = (uint32_t)((rowB >> 1) & 3);
    const uint32_t boff = (uint32_t)rowB * 64;

    const char* gA = (const char*)g_oang8 + (size_t)mt * 4 * BLOB;
    const char* gB = (const char*)g_Bb8 + (size_t)ng * 32 * BLOB;

    const int qr = lane >> 2;
    const int qc = (lane & 3) * 2;

    if (tid == 0) {
        #pragma unroll
        for (int s = 0; s < 5; s++) MBAR_INIT(mb + s * 8, 1);
    }
    __syncthreads();
    if (tid == 0) {
        MBAR_EXPECT_TX(mb + 32, 4 * BLOB);
        #pragma unroll
        for (int c = 0; c < 4; c++)
            CPBULK(sbase + c * BLOB, gA + (size_t)c * BLOB, BLOB, mb + 32);
        #pragma unroll
        for (int j = 0; j < 3; j++) {
            MBAR_EXPECT_TX(mb + j * 8, BLOB);
            CPBULK(sbase + SIMS_B_OFF + j * BLOB, gB + (size_t)j * BLOB, BLOB, mb + j * 8);
        }
    }
    MBAR_WAIT(mb + 32, 0);

    unsigned long long rb[4] = {0ULL, 0ULL, 0ULL, 0ULL};
    float acc[2][8][4];

    for (int j = 0; j < 32; j++) {
        const int c = j & 3;
        const int g = j >> 2;
        if (c == 0) {
            #pragma unroll
            for (int i = 0; i < 2; i++)
                #pragma unroll
                for (int jj = 0; jj < 8; jj++)
                    #pragma unroll
                    for (int k = 0; k < 4; k++) acc[i][jj][k] = 0.0f;
        }
        MBAR_WAIT(mb + (j & 3) * 8, (j >> 2) & 1);
        __syncthreads();
        if (tid == 0 && j + 3 < 32) {
            const int s = (j + 3) & 3;
            MBAR_EXPECT_TX(mb + s * 8, BLOB);
            CPBULK(sbase + SIMS_B_OFF + s * BLOB, gB + (size_t)(j + 3) * BLOB, BLOB, mb + s * 8);
        }
        const uint32_t uA = sbase + (uint32_t)c * BLOB;
        const uint32_t uB = sbase + SIMS_B_OFF + (uint32_t)(j & 3) * BLOB;
        #pragma unroll
        for (int ks = 0; ks < 2; ks++) {
            const uint32_t oa = ((cA | (ks << 1)) ^ swA) << 4;
            const uint32_t ob = ((cB | (ks << 1)) ^ swB) << 4;
            uint32_t a[2][4];
            LDSM4(a[0][0], a[0][1], a[0][2], a[0][3], uA + aoff + oa);
            LDSM4(a[1][0], a[1][1], a[1][2], a[1][3], uA + aoff + 1024 + oa);
            uint32_t b[8][2];
            #pragma unroll
            for (int jp = 0; jp < 4; jp++) {
                LDSM4(b[2*jp][0], b[2*jp][1], b[2*jp+1][0], b[2*jp+1][1],
                      uB + boff + (uint32_t)jp * 1024 + ob);
            }
            #pragma unroll
            for (int mt2 = 0; mt2 < 2; mt2++)
                #pragma unroll
                for (int nj = 0; nj < 8; nj++)
                    MMA_F8(acc[mt2][nj], a[mt2], b[nj]);
        }
        if (c == 3) {
            const unsigned keyb = 0xFFFFFFFFu - (unsigned)(n_base + g * 128 + warp_n + qc);
            #pragma unroll
            for (int mt2 = 0; mt2 < 2; mt2++) {
                unsigned long long b0 = rb[mt2 * 2], b1 = rb[mt2 * 2 + 1];
                #pragma unroll
                for (int nj = 0; nj < 8; nj++) {
                    #pragma unroll
                    for (int p = 0; p < 2; p++) {
                        const unsigned key2 = keyb - (unsigned)(nj * 8 + p);
                        unsigned long long q0 = ((unsigned long long)enc_f(acc[mt2][nj][p]) << 32) | key2;
                        if (q0 > b0) b0 = q0;
                        unsigned long long q1 = ((unsigned long long)enc_f(acc[mt2][nj][2 + p]) << 32) | key2;
                        if (q1 > b1) b1 = q1;
                    }
                }
                rb[mt2 * 2] = b0;
                rb[mt2 * 2 + 1] = b1;
            }
        }
    }

    #pragma unroll
    for (int mt2 = 0; mt2 < 2; mt2++) {
        unsigned long long b0 = rb[mt2 * 2], b1 = rb[mt2 * 2 + 1];
        unsigned long long t;
        t = __shfl_xor_sync(0xffffffffu, b0, 1); if (t > b0) b0 = t;
        t = __shfl_xor_sync(0xffffffffu, b0, 2); if (t > b0) b0 = t;
        t = __shfl_xor_sync(0xffffffffu, b1, 1); if (t > b1) b1 = t;
        t = __shfl_xor_sync(0xffffffffu, b1, 2); if (t > b1) b1 = t;
        if ((lane & 3) == 0) {
            if (b0) atomicMax(&g_best[m0 + warp_m + mt2 * 16 + qr], b0);
            if (b1) atomicMax(&g_best[m0 + warp_m + mt2 * 16 + 8 + qr], b1);
        }
    }
}

// ============ finalize ============
__global__ __launch_bounds__(256) void finalize_out_kernel(
    const float* __restrict__ bg2, const float* __restrict__ bp2,
    float* __restrict__ out_obs, float* __restrict__ out_sims,
    float* __restrict__ out_slots, float* __restrict__ out_meaning, int write_extra)
{
    __shared__ float s_pm;
    int t = blockIdx.x;
    int d = threadIdx.x;
    if (d == 0) {
        float pm = 0.0f;
        float bg2v = bg2[0], bp2v = bp2[0];
        #pragma unroll
        for (int b = 0; b < Bc; b++) {
            int row = b * Tc + t;
            float gl = bg2v, pl = bp2v;
            #pragma unroll
            for (int jt = 0; jt < 4; jt++) gl += g_part[jt * MGP + row];
            #pragma unroll
            for (int jt = 4; jt < 8; jt++) pl += g_part[jt * MGP + row];
            pm += sigmoidf_(gl) * softplusf_(pl);
        }
        s_pm = pm * 0.25f;
    }
    __syncthreads();
    float pm = s_pm;
    out_obs[(size_t)t * Dc + d] = g_ang[(size_t)t * Dc + d] * pm;
    if (d == 0 && write_extra) {
        float rad = pm * g_na[t];
        out_meaning[t] = (rad > 0.05f) ? 1.0f : 0.0f;
        unsigned long long b = g_best[t];
        float sim = 0.0f;
        int idx = -1;
        bool has = (b != 0ULL);
        if (has) {
            sim = dec_f((unsigned)(b >> 32)) * 0.00390625f;
            idx = (int)(0xFFFFFFFFu - (unsigned)(b & 0xFFFFFFFFu));
        }
        bool matched = has && (rad > 0.05f) && (sim > 0.5f);
        out_sims[t]  = matched ? sim : 0.0f;
        out_slots[t] = matched ? (float)idx : -1.0f;
    }
}

// ---------------- launcher ----------------
extern "C" void kernel_launch(void* const* d_in, const int* in_sizes, int n_in,
                              void* d_out, int out_size)
{
    const float* hidden  = (const float*)d_in[0];
    const float* beliefs = (const float*)d_in[1];
    const void*  maskp   = d_in[2];
    const float* W_obs   = (const float*)d_in[3];
    const float* W_g1    = (const float*)d_in[4];
    const float* b_g1    = (const float*)d_in[5];
    const float* W_g2    = (const float*)d_in[6];
    const float* b_g2    = (const float*)d_in[7];
    const float* W_p1    = (const float*)d_in[8];
    const float* b_p1    = (const float*)d_in[9];
    const float* W_p2    = (const float*)d_in[10];
    const float* b_p2    = (const float*)d_in[11];
    float* out = (float*)d_out;

    static cudaStream_t s2 = nullptr;
    static cudaEvent_t evF = nullptr, evA = nullptr, evJ = nullptr;
    static int attr_set = 0;
    if (!attr_set) {
        cudaFuncSetAttribute(gp_mma_kernel, cudaFuncAttributeMaxDynamicSharedMemorySize, GP_SMEM);
        cudaFuncSetAttribute(obs_mma_kernel, cudaFuncAttributeMaxDynamicSharedMemorySize, OB_SMEM);
        cudaFuncSetAttribute(sims_mma_kernel, cudaFuncAttributeMaxDynamicSharedMemorySize, SIMS_SMEM);
        cudaStreamCreateWithFlags(&s2, cudaStreamNonBlocking);
        cudaEventCreateWithFlags(&evF, cudaEventDisableTiming);
        cudaEventCreateWithFlags(&evA, cudaEventDisableTiming);
        cudaEventCreateWithFlags(&evJ, cudaEventDisableTiming);
        attr_set = 1;
    }

    const size_t base = (size_t)Tc * Dc;
    const int write_extra = (out_size >= (int)(base + 3 * Tc)) ? 1 : 0;
    float* out_obs     = out;
    float* out_sims    = out + base;
    float* out_slots   = out + base + Tc;
    float* out_meaning = out + base + 2 * Tc;

    // fork s2 for the hidden-independent chain
    cudaEventRecord(evF, 0);
    cudaStreamWaitEvent(s2, evF, 0);
    init_best_kernel<<<Tc / 256, 256, 0, s2>>>();
    detect_mask_kernel<<<Nc / 256, 256, 0, s2>>>((const unsigned char*)maskp);
    convert_mask_kernel<<<Nc / 256, 256, 0, s2>>>(maskp);
    binv_kernel<<<Nc / 8, 256, 0, s2>>>(beliefs);
    prep_beliefs_kernel<<<(Nc * 4) / 256, 256, 0, s2>>>(beliefs);

    // stream 0: heavy preps
    prep_hidden_kernel<<<(Tc * 64) / 256, 256>>>(hidden);
    prep_weights_kernel<<<(1280 * 64) / 256, 256>>>(W_g1, W_p1, W_obs);
    prep_small_kernel<<<4, 256>>>(b_g1, b_p1, W_g2, W_p2);

    // s2 waits for preps, then runs obs -> angles -> sims; stream 0 runs gp concurrently
    cudaEventRecord(evA, 0);
    cudaStreamWaitEvent(s2, evA, 0);
    obs_mma_kernel<<<64, 256, OB_SMEM, s2>>>();
    angles_kernel<<<Tc, 256, 0, s2>>>();
    sims_mma_kernel<<<dim3(32, 32), 256, SIMS_SMEM, s2>>>();

    gp_mma_kernel<<<dim3(8, 128), 256, GP_SMEM>>>();

    // join and finalize
    cudaEventRecord(evJ, s2);
    cudaStreamWaitEvent(0, evJ, 0);
    finalize_out_kernel<<<Tc, 256>>>(b_g2, b_p2, out_obs, out_sims, out_slots, out_meaning, write_extra);
}

// round 14
// speedup vs baseline: 1.0612x; 1.0612x over previous
#include <cuda_runtime.h>
#include <cuda_fp16.h>
#include <cstdint>

#define Bc 4
#define Tc 4096
#define Hc 2048
#define Dc 256
#define Nc 32768
#define MGP (Bc*Tc)
#define EPSC 1e-8f
#define BLOB 8192            // one operand tile-chunk: 128 rows x 64B, SW64 swizzled

// ---------------- device scratch ----------------
__device__ unsigned char g_Af[(size_t)128 * 64 * BLOB];
__device__ unsigned char g_Hmhi[(size_t)32 * 64 * BLOB];
__device__ unsigned char g_Hmlo[(size_t)32 * 64 * BLOB];
__device__ unsigned char g_Wcf[(size_t)8 * 64 * BLOB];
__device__ unsigned char g_Wohi[(size_t)2 * 64 * BLOB];
__device__ unsigned char g_Wolo[(size_t)2 * 64 * BLOB];
__device__ unsigned char g_Bb8[(size_t)256 * 4 * BLOB];    // normalized beliefs e4m3 (x16, inactive=0)
__device__ unsigned char g_oang8[(size_t)32 * 4 * BLOB];
__device__ float g_bc1[1024];
__device__ float g_wc2[1024];
__device__ float g_obs_mean[(size_t)Tc * Dc];
__device__ float g_part[8 * MGP];
__device__ float g_binv[Nc];
__device__ unsigned char g_active[Nc];
__device__ unsigned long long g_best[Tc];
__device__ float g_rad[Tc];
__device__ int g_weird;
__device__ int g_off4;

// ---------------- helpers ----------------
__device__ __forceinline__ uint32_t smem_u32(const void* p) {
    uint32_t a;
    asm("{ .reg .u64 t; cvta.to.shared.u64 t, %1; cvt.u32.u64 %0, t; }" : "=r"(a) : "l"(p));
    return a;
}
#define LDSM4(R0, R1, R2, R3, A) \
    asm volatile("ldmatrix.sync.aligned.m8n8.x4.shared.b16 {%0,%1,%2,%3}, [%4];" \
        : "=r"(R0), "=r"(R1), "=r"(R2), "=r"(R3) : "r"(A))
#define MMA_F16(D, A, B) \
    asm volatile("mma.sync.aligned.m16n8k16.row.col.f32.f16.f16.f32 " \
        "{%0,%1,%2,%3}, {%4,%5,%6,%7}, {%8,%9}, {%0,%1,%2,%3};" \
        : "+f"((D)[0]), "+f"((D)[1]), "+f"((D)[2]), "+f"((D)[3]) \
        : "r"((A)[0]), "r"((A)[1]), "r"((A)[2]), "r"((A)[3]), "r"((B)[0]), "r"((B)[1]))
#define MMA_F8(D, A, B) \
    asm volatile("mma.sync.aligned.m16n8k32.row.col.f32.e4m3.e4m3.f32 " \
        "{%0,%1,%2,%3}, {%4,%5,%6,%7}, {%8,%9}, {%0,%1,%2,%3};" \
        : "+f"((D)[0]), "+f"((D)[1]), "+f"((D)[2]), "+f"((D)[3]) \
        : "r"((A)[0]), "r"((A)[1]), "r"((A)[2]), "r"((A)[3]), "r"((B)[0]), "r"((B)[1]))
#define CPBULK(DST, SRC, BYTES, MBAR) \
    asm volatile("cp.async.bulk.shared::cta.global.mbarrier::complete_tx::bytes [%0], [%1], %2, [%3];" \
        :: "r"((uint32_t)(DST)), "l"(SRC), "r"((uint32_t)(BYTES)), "r"((uint32_t)(MBAR)) : "memory")
#define MBAR_INIT(mb, n) \
    asm volatile("mbarrier.init.shared.b64 [%0], %1;" :: "r"((uint32_t)(mb)), "r"((uint32_t)(n)) : "memory")
#define MBAR_EXPECT_TX(mb, bytes) \
    asm volatile("mbarrier.arrive.expect_tx.shared.b64 _, [%0], %1;" \
        :: "r"((uint32_t)(mb)), "r"((uint32_t)(bytes)) : "memory")
#define MBAR_WAIT(mb, ph) do { \
    uint32_t _m = (uint32_t)(mb); uint32_t _p = (uint32_t)(ph); uint32_t _d; \
    asm volatile("{\n\t.reg .pred p;\n\t" \
        "mbarrier.try_wait.parity.acquire.cta.shared::cta.b64 p, [%1], %2;\n\t" \
        "selp.b32 %0, 1, 0, p;\n\t}" : "=r"(_d) : "r"(_m), "r"(_p) : "memory"); \
    if (!_d) { \
        asm volatile("{\n\t.reg .pred P1;\n\t" \
            "WL_%=:\n\t" \
            "mbarrier.try_wait.parity.acquire.cta.shared::cta.b64 P1, [%0], %1, 0x989680;\n\t" \
            "@P1 bra.uni WD_%=;\n\t" \
            "bra.uni WL_%=;\n\t" \
            "WD_%=:\n\t}" :: "r"(_m), "r"(_p) : "memory"); \
    } } while (0)

__device__ __forceinline__ unsigned enc_f(float f) {
    unsigned u = __float_as_uint(f);
    return (u & 0x80000000u) ? ~u : (u | 0x80000000u);
}
__device__ __forceinline__ float dec_f(unsigned e) {
    unsigned u = (e & 0x80000000u) ? (e ^ 0x80000000u) : ~e;
    return __uint_as_float(u);
}
__device__ __forceinline__ float sigmoidf_(float x) { return 1.0f / (1.0f + expf(-x)); }
__device__ __forceinline__ float softplusf_(float x) {
    return fmaxf(x, 0.0f) + log1pf(expf(-fabsf(x)));
}
__device__ __forceinline__ uint16_t pack_e4m3(float lo, float hi) {
    uint16_t r;
    asm("cvt.rn.satfinite.e4m3x2.f32 %0, %1, %2;" : "=h"(r) : "f"(hi), "f"(lo));
    return r;
}
__device__ __forceinline__ uint32_t pk_h2(float a, float b) {
    __half2 h = __halves2half2(__float2half_rn(a), __float2half_rn(b));
    return *(uint32_t*)&h;
}

// ---------------- prep kernels ----------------
__global__ void prep_hidden_kernel(const float* __restrict__ hidden) {
    int idx = blockIdx.x * blockDim.x + threadIdx.x;
    int t = idx >> 6, c = idx & 63;
    const int r = t & 127;
    const int sw = (r >> 1) & 3;
    float acc[32];
    #pragma unroll
    for (int j = 0; j < 32; j++) acc[j] = 0.0f;
    #pragma unroll
    for (int b = 0; b < Bc; b++) {
        const float* src = hidden + ((size_t)(b * Tc + t)) * Hc + c * 32;
        float v[32];
        #pragma unroll
        for (int q = 0; q < 8; q++) {
            float4 f = *(const float4*)(src + q * 4);
            v[q*4+0] = f.x; v[q*4+1] = f.y; v[q*4+2] = f.z; v[q*4+3] = f.w;
        }
        #pragma unroll
        for (int j = 0; j < 32; j++) acc[j] += v[j];
        char* dst = (char*)g_Af + ((size_t)(((b * Tc + t) >> 7) * 64 + c)) * BLOB + r * 64;
        #pragma unroll
        for (int k16 = 0; k16 < 4; k16++) {
            uint4 u = make_uint4(pk_h2(v[k16*8+0], v[k16*8+1]), pk_h2(v[k16*8+2], v[k16*8+3]),
                                 pk_h2(v[k16*8+4], v[k16*8+5]), pk_h2(v[k16*8+6], v[k16*8+7]));
            *(uint4*)(dst + ((k16 ^ sw) << 4)) = u;
        }
    }
    float hi[32], lo[32];
    #pragma unroll
    for (int j = 0; j < 32; j++) {
        float m = acc[j] * 0.25f;
        float h = __half2float(__float2half_rn(m));
        hi[j] = m;
        lo[j] = m - h;
    }
    size_t boff = ((size_t)((t >> 7) * 64 + c)) * BLOB + r * 64;
    char* dh = (char*)g_Hmhi + boff;
    char* dl = (char*)g_Hmlo + boff;
    #pragma unroll
    for (int k16 = 0; k16 < 4; k16++) {
        uint4 uh = make_uint4(pk_h2(hi[k16*8+0], hi[k16*8+1]), pk_h2(hi[k16*8+2], hi[k16*8+3]),
                              pk_h2(hi[k16*8+4], hi[k16*8+5]), pk_h2(hi[k16*8+6], hi[k16*8+7]));
        uint4 ul = make_uint4(pk_h2(lo[k16*8+0], lo[k16*8+1]), pk_h2(lo[k16*8+2], lo[k16*8+3]),
                              pk_h2(lo[k16*8+4], lo[k16*8+5]), pk_h2(lo[k16*8+6], lo[k16*8+7]));
        *(uint4*)(dh + ((k16 ^ sw) << 4)) = uh;
        *(uint4*)(dl + ((k16 ^ sw) << 4)) = ul;
    }
}

__global__ void prep_weights_kernel(const float* __restrict__ Wg1, const float* __restrict__ Wp1,
                                    const float* __restrict__ Wobs) {
    int idx = blockIdx.x * blockDim.x + threadIdx.x;
    int row = idx >> 6, c = idx & 63;
    float v[32];
    const float* src;
    if (row < 512)        src = Wg1 + (size_t)row * Hc + c * 32;
    else if (row < 1024)  src = Wp1 + (size_t)(row - 512) * Hc + c * 32;
    else                  src = Wobs + (size_t)(row - 1024) * Hc + c * 32;
    #pragma unroll
    for (int q = 0; q < 8; q++) {
        float4 f = *(const float4*)(src + q * 4);
        v[q*4+0] = f.x; v[q*4+1] = f.y; v[q*4+2] = f.z; v[q*4+3] = f.w;
    }
    if (row < 1024) {
        int r = row & 127, sw = (r >> 1) & 3;
        char* dst = (char*)g_Wcf + ((size_t)((row >> 7) * 64 + c)) * BLOB + r * 64;
        #pragma unroll
        for (int k16 = 0; k16 < 4; k16++) {
            uint4 u = make_uint4(pk_h2(v[k16*8+0], v[k16*8+1]), pk_h2(v[k16*8+2], v[k16*8+3]),
                                 pk_h2(v[k16*8+4], v[k16*8+5]), pk_h2(v[k16*8+6], v[k16*8+7]));
            *(uint4*)(dst + ((k16 ^ sw) << 4)) = u;
        }
    } else {
        int r2 = row - 1024;
        int r = r2 & 127, sw = (r >> 1) & 3;
        size_t boff = ((size_t)((r2 >> 7) * 64 + c)) * BLOB + r * 64;
        char* dh = (char*)g_Wohi + boff;
        char* dl = (char*)g_Wolo + boff;
        float hi[32], lo[32];
        #pragma unroll
        for (int j = 0; j < 32; j++) {
            float h = __half2float(__float2half_rn(v[j]));
            hi[j] = v[j];
            lo[j] = v[j] - h;
        }
        #pragma unroll
        for (int k16 = 0; k16 < 4; k16++) {
            uint4 uh = make_uint4(pk_h2(hi[k16*8+0], hi[k16*8+1]), pk_h2(hi[k16*8+2], hi[k16*8+3]),
                                  pk_h2(hi[k16*8+4], hi[k16*8+5]), pk_h2(hi[k16*8+6], hi[k16*8+7]));
            uint4 ul = make_uint4(pk_h2(lo[k16*8+0], lo[k16*8+1]), pk_h2(lo[k16*8+2], lo[k16*8+3]),
                                  pk_h2(lo[k16*8+4], lo[k16*8+5]), pk_h2(lo[k16*8+6], lo[k16*8+7]));
            *(uint4*)(dh + ((k16 ^ sw) << 4)) = uh;
            *(uint4*)(dl + ((k16 ^ sw) << 4)) = ul;
        }
    }
}

__global__ void prep_small_kernel(const float* __restrict__ bg1, const float* __restrict__ bp1,
                                  const float* __restrict__ Wg2, const float* __restrict__ Wp2) {
    int i = blockIdx.x * blockDim.x + threadIdx.x;
    if (i < 1024) {
        g_bc1[i] = (i < 512) ? bg1[i] : bp1[i - 512];
        g_wc2[i] = (i < 512) ? Wg2[i] : Wp2[i - 512];
    }
}

__global__ void prep_beliefs_kernel(const float* __restrict__ beliefs) {
    int idx = blockIdx.x * blockDim.x + threadIdx.x;
    int n = idx >> 2, c = idx & 3;
    int r = n & 127, sw = (r >> 1) & 3;
    float bi = g_binv[n];
    const float* src = beliefs + (size_t)n * Dc + c * 64;
    char* dst = (char*)g_Bb8 + ((size_t)((n >> 7) * 4 + c)) * BLOB + r * 64;
    #pragma unroll
    for (int k16 = 0; k16 < 4; k16++) {
        uint32_t w[4];
        #pragma unroll
        for (int q = 0; q < 4; q++) {
            float4 f = *(const float4*)(src + k16 * 16 + q * 4);
            uint16_t a = pack_e4m3(f.x * bi, f.y * bi);
            uint16_t b = pack_e4m3(f.z * bi, f.w * bi);
            w[q] = ((uint32_t)b << 16) | a;
        }
        *(uint4*)(dst + ((k16 ^ sw) << 4)) = make_uint4(w[0], w[1], w[2], w[3]);
    }
}

__global__ void detect_mask_kernel(const unsigned char* __restrict__ m) {
    int i = blockIdx.x * blockDim.x + threadIdx.x;
    unsigned char c = m[i];
    int w = 0, o = 0;
    if (c > 1) w = 1;
    if (c != 0 && (i & 3)) o = 1;
    w = __reduce_or_sync(0xffffffffu, w);
    o = __reduce_or_sync(0xffffffffu, o);
    if ((threadIdx.x & 31) == 0) {
        if (w) atomicOr(&g_weird, 1);
        if (o) atomicOr(&g_off4, 1);
    }
}
__global__ void convert_mask_kernel(const void* __restrict__ m) {
    int i = blockIdx.x * blockDim.x + threadIdx.x;
    if (i >= Nc) return;
    int fmt = g_weird ? 2 : (g_off4 ? 1 : 0);
    unsigned char a;
    if (fmt == 0)      a = (((const int*)m)[i] != 0);
    else if (fmt == 1) a = (((const unsigned char*)m)[i] != 0);
    else               a = (((const float*)m)[i] != 0.0f);
    g_active[i] = a;
}
__global__ void binv_kernel(const float* __restrict__ beliefs) {
    int row = blockIdx.x * 8 + (threadIdx.x >> 5);
    int lane = threadIdx.x & 31;
    const float4* p = reinterpret_cast<const float4*>(beliefs + (size_t)row * Dc);
    float s = 0.0f;
    #pragma unroll
    for (int r = 0; r < 2; r++) {
        float4 v = p[lane + r * 32];
        s += v.x * v.x + v.y * v.y + v.z * v.z + v.w * v.w;
    }
    #pragma unroll
    for (int o = 16; o > 0; o >>= 1) s += __shfl_down_sync(0xffffffffu, s, o);
    if (lane == 0)
        g_binv[row] = g_active[row] ? (16.0f / fmaxf(sqrtf(s), EPSC)) : 0.0f;
}

__global__ void init_best_kernel() {
    int i = blockIdx.x * blockDim.x + threadIdx.x;
    if (i < Tc) g_best[i] = 0ULL;
    if (i == 0) { g_weird = 0; g_off4 = 0; }
}

// ============ merged gate/prec + obs GEMM kernel ============
#define GP_STAGE2 32768
#define OB_STAGE 32768
#define DYN_SMEM 98304

__global__ __launch_bounds__(256, 2) void gpobs_mma_kernel() {
    extern __shared__ __align__(128) char dsm[];
    __shared__ float s_b1[128], s_w2[128], s_red[128];
    __shared__ __align__(8) unsigned long long s_mbar[4];

    const int tid = threadIdx.x, lane = tid & 31, wid = tid >> 5;
    const int warp_m = (wid >> 1) * 32;
    const int warp_n = (wid & 1) * 64;
    const uint32_t sbase = smem_u32(dsm);
    const uint32_t mb = smem_u32(s_mbar);

    const int rowA = warp_m + (lane & 15);
    const uint32_t cA = (uint32_t)(lane >> 4);
    const uint32_t swA = (uint32_t)((rowA >> 1) & 3);
    const uint32_t aoff = (uint32_t)rowA * 64;
    const int rowB = warp_n + ((lane >> 4) << 3) + (lane & 7);
    const uint32_t cB = (uint32_t)((lane >> 3) & 1);
    const uint32_t swB = (uint32_t)((rowB >> 1) & 3);
    const uint32_t boff = (uint32_t)rowB * 64;

    float acc[2][8][4];
    #pragma unroll
    for (int i = 0; i < 2; i++)
        #pragma unroll
        for (int j = 0; j < 8; j++)
            #pragma unroll
            for (int k = 0; k < 4; k++) acc[i][j][k] = 0.0f;

    const int qr = lane >> 2;
    const int qc = (lane & 3) * 2;

    if (blockIdx.x < 8) {
        const int nt = blockIdx.x;
        const int mt = blockIdx.y;
        const int m0 = mt * 128, nbase = nt * 128;
        if (tid < 128) {
            s_b1[tid] = g_bc1[nbase + tid];
            s_w2[tid] = g_wc2[nbase + tid];
            s_red[tid] = 0.0f;
        }
        const char* gA = (const char*)g_Af + (size_t)mt * 64 * BLOB;
        const char* gB = (const char*)g_Wcf + (size_t)nt * 64 * BLOB;

        if (tid == 0) {
            #pragma unroll
            for (int s = 0; s < 3; s++) MBAR_INIT(mb + s * 8, 1);
        }
        __syncthreads();
        if (tid == 0) {
            #pragma unroll
            for (int c = 0; c < 2; c++) {
                const uint32_t st = sbase + c * GP_STAGE2;
                MBAR_EXPECT_TX(mb + c * 8, GP_STAGE2);
                CPBULK(st,         gA + (size_t)(2*c)     * BLOB, BLOB, mb + c * 8);
                CPBULK(st + 8192,  gA + (size_t)(2*c + 1) * BLOB, BLOB, mb + c * 8);
                CPBULK(st + 16384, gB + (size_t)(2*c)     * BLOB, BLOB, mb + c * 8);
                CPBULK(st + 24576, gB + (size_t)(2*c + 1) * BLOB, BLOB, mb + c * 8);
            }
        }

        for (int c = 0; c < 32; c++) {
            MBAR_WAIT(mb + (c % 3) * 8, (c / 3) & 1);
            __syncthreads();
            if (tid == 0 && c + 2 < 32) {
                const int s = (c + 2) % 3;
                const uint32_t st = sbase + s * GP_STAGE2;
                MBAR_EXPECT_TX(mb + s * 8, GP_STAGE2);
                CPBULK(st,         gA + (size_t)(2*(c+2))     * BLOB, BLOB, mb + s * 8);
                CPBULK(st + 8192,  gA + (size_t)(2*(c+2) + 1) * BLOB, BLOB, mb + s * 8);
                CPBULK(st + 16384, gB + (size_t)(2*(c+2))     * BLOB, BLOB, mb + s * 8);
                CPBULK(st + 24576, gB + (size_t)(2*(c+2) + 1) * BLOB, BLOB, mb + s * 8);
            }
            const uint32_t uS = sbase + (c % 3) * GP_STAGE2;
            #pragma unroll
            for (int h = 0; h < 2; h++) {
                const uint32_t uA = uS + (uint32_t)h * 8192;
                const uint32_t uB = uS + 16384 + (uint32_t)h * 8192;
                #pragma unroll
                for (int ks = 0; ks < 2; ks++) {
                    const uint32_t oa = ((cA | (ks << 1)) ^ swA) << 4;
                    const uint32_t ob = ((cB | (ks << 1)) ^ swB) << 4;
                    uint32_t a[2][4];
                    LDSM4(a[0][0], a[0][1], a[0][2], a[0][3], uA + aoff + oa);
                    LDSM4(a[1][0], a[1][1], a[1][2], a[1][3], uA + aoff + 1024 + oa);
                    uint32_t b[8][2];
                    #pragma unroll
                    for (int jp = 0; jp < 4; jp++) {
                        LDSM4(b[2*jp][0], b[2*jp][1], b[2*jp+1][0], b[2*jp+1][1],
                              uB + boff + (uint32_t)jp * 1024 + ob);
                    }
                    #pragma unroll
                    for (int mt2 = 0; mt2 < 2; mt2++)
                        #pragma unroll
                        for (int nj = 0; nj < 8; nj++)
                            MMA_F16(acc[mt2][nj], a[mt2], b[nj]);
                }
            }
        }
        __syncthreads();

        #pragma unroll
        for (int mt2 = 0; mt2 < 2; mt2++) {
            float p0 = 0.0f, p1 = 0.0f;
            #pragma unroll
            for (int nj = 0; nj < 8; nj++) {
                int col = warp_n + nj * 8 + qc;
                p0 += fmaxf(acc[mt2][nj][0] + s_b1[col], 0.0f) * s_w2[col]
                    + fmaxf(acc[mt2][nj][1] + s_b1[col + 1], 0.0f) * s_w2[col + 1];
                p1 += fmaxf(acc[mt2][nj][2] + s_b1[col], 0.0f) * s_w2[col]
                    + fmaxf(acc[mt2][nj][3] + s_b1[col + 1], 0.0f) * s_w2[col + 1];
            }
            p0 += __shfl_xor_sync(0xffffffffu, p0, 1);
            p0 += __shfl_xor_sync(0xffffffffu, p0, 2);
            p1 += __shfl_xor_sync(0xffffffffu, p1, 1);
            p1 += __shfl_xor_sync(0xffffffffu, p1, 2);
            if ((lane & 3) == 0) {
                atomicAdd(&s_red[warp_m + mt2 * 16 + qr], p0);
                atomicAdd(&s_red[warp_m + mt2 * 16 + 8 + qr], p1);
            }
        }
        __syncthreads();
        if (tid < 128) g_part[nt * MGP + m0 + tid] = s_red[tid];
    } else {
        const int id = blockIdx.y;
        if (id >= 64) return;
        const int nt = id & 1;
        const int mt = id >> 1;
        const int m0 = mt * 128, nbase = nt * 128;
        const char* gAh = (const char*)g_Hmhi + (size_t)mt * 64 * BLOB;
        const char* gAl = (const char*)g_Hmlo + (size_t)mt * 64 * BLOB;
        const char* gBh = (const char*)g_Wohi + (size_t)nt * 64 * BLOB;
        const char* gBl = (const char*)g_Wolo + (size_t)nt * 64 * BLOB;

        if (tid == 0) {
            MBAR_INIT(mb, 1);
            MBAR_INIT(mb + 8, 1);
        }
        __syncthreads();
        if (tid == 0) {
            MBAR_EXPECT_TX(mb, OB_STAGE);
            CPBULK(sbase,         gAh, BLOB, mb);
            CPBULK(sbase + 8192,  gAl, BLOB, mb);
            CPBULK(sbase + 16384, gBh, BLOB, mb);
            CPBULK(sbase + 24576, gBl, BLOB, mb);
        }

        for (int c = 0; c < 64; c++) {
            MBAR_WAIT(mb + (c & 1) * 8, (c >> 1) & 1);
            __syncthreads();
            if (tid == 0 && c + 1 < 64) {
                const int s = (c + 1) & 1;
                const uint32_t st = sbase + s * OB_STAGE;
                MBAR_EXPECT_TX(mb + s * 8, OB_STAGE);
                CPBULK(st,         gAh + (size_t)(c + 1) * BLOB, BLOB, mb + s * 8);
                CPBULK(st + 8192,  gAl + (size_t)(c + 1) * BLOB, BLOB, mb + s * 8);
                CPBULK(st + 16384, gBh + (size_t)(c + 1) * BLOB, BLOB, mb + s * 8);
                CPBULK(st + 24576, gBl + (size_t)(c + 1) * BLOB, BLOB, mb + s * 8);
            }
            const uint32_t uS = sbase + (c & 1) * OB_STAGE;
            #pragma unroll
            for (int tr = 0; tr < 3; tr++) {
                const uint32_t uA = uS + (tr == 2 ? 8192u : 0u);
                const uint32_t uB = uS + 16384u + (tr == 1 ? 8192u : 0u);
                #pragma unroll
                for (int ks = 0; ks < 2; ks++) {
                    const uint32_t oa = ((cA | (ks << 1)) ^ swA) << 4;
                    const uint32_t ob = ((cB | (ks << 1)) ^ swB) << 4;
                    uint32_t a[2][4];
                    LDSM4(a[0][0], a[0][1], a[0][2], a[0][3], uA + aoff + oa);
                    LDSM4(a[1][0], a[1][1], a[1][2], a[1][3], uA + aoff + 1024 + oa);
                    uint32_t b[8][2];
                    #pragma unroll
                    for (int jp = 0; jp < 4; jp++) {
                        LDSM4(b[2*jp][0], b[2*jp][1], b[2*jp+1][0], b[2*jp+1][1],
                              uB + boff + (uint32_t)jp * 1024 + ob);
                    }
                    #pragma unroll
                    for (int mt2 = 0; mt2 < 2; mt2++)
                        #pragma unroll
                        for (int nj = 0; nj < 8; nj++)
                            MMA_F16(acc[mt2][nj], a[mt2], b[nj]);
                }
            }
        }

        #pragma unroll
        for (int mt2 = 0; mt2 < 2; mt2++)
            #pragma unroll
            for (int nj = 0; nj < 8; nj++) {
                int row = m0 + warp_m + mt2 * 16 + qr;
                int col = nbase + warp_n + nj * 8 + qc;
                *(float2*)(g_obs_mean + (size_t)row * Dc + col) = make_float2(acc[mt2][nj][0], acc[mt2][nj][1]);
                *(float2*)(g_obs_mean + (size_t)(row + 8) * Dc + col) = make_float2(acc[mt2][nj][2], acc[mt2][nj][3]);
            }
    }
}

// ============ sims GEMM v3: 16KB B stages (2 blobs), float/idx fold ============
#define SIMS_B_OFF 32768
#define SIMS_STG 16384
#define SIMS_SMEM 98304
__global__ __launch_bounds__(256, 2) void sims_mma_kernel() {
    extern __shared__ __align__(128) char dsm[];
    __shared__ __align__(8) unsigned long long s_mbar[5];

    const int tid = threadIdx.x, lane = tid & 31, wid = tid >> 5;
    const int ng = blockIdx.x;                 // 0..31 n-group (8 n-tiles each)
    const int mt = blockIdx.y;                 // 0..31 m-tile
    const int n_base = ng * 1024, m0 = mt * 128;
    const int warp_m = (wid >> 1) * 32;
    const int warp_n = (wid & 1) * 64;
    const uint32_t sbase = smem_u32(dsm);
    const uint32_t mb = smem_u32(s_mbar);

    const int rowA = warp_m + (lane & 15);
    const uint32_t cA = (uint32_t)(lane >> 4);
    const uint32_t swA = (uint32_t)((rowA >> 1) & 3);
    const uint32_t aoff = (uint32_t)rowA * 64;
    const int rowB = warp_n + ((lane >> 4) << 3) + (lane & 7);
    const uint32_t cB = (uint32_t)((lane >> 3) & 1);
    const uint32_t swB = (uint32_t)((rowB >> 1) & 3);
    const uint32_t boff = (uint32_t)rowB * 64;

    const char* gA = (const char*)g_oang8 + (size_t)mt * 4 * BLOB;
    const char* gB = (const char*)g_Bb8 + (size_t)ng * 32 * BLOB;

    const int qr = lane >> 2;
    const int qc = (lane & 3) * 2;

    if (tid == 0) {
        #pragma unroll
        for (int s = 0; s < 5; s++) MBAR_INIT(mb + s * 8, 1);
    }
    __syncthreads();
    if (tid == 0) {
        MBAR_EXPECT_TX(mb + 32, 4 * BLOB);
        #pragma unroll
        for (int c = 0; c < 4; c++)
            CPBULK(sbase + c * BLOB, gA + (size_t)c * BLOB, BLOB, mb + 32);
        #pragma unroll
        for (int j = 0; j < 3; j++) {
            MBAR_EXPECT_TX(mb + j * 8, SIMS_STG);
            CPBULK(sbase + SIMS_B_OFF + j * SIMS_STG,        gB + (size_t)(2*j)     * BLOB, BLOB, mb + j * 8);
            CPBULK(sbase + SIMS_B_OFF + j * SIMS_STG + BLOB, gB + (size_t)(2*j + 1) * BLOB, BLOB, mb + j * 8);
        }
    }
    MBAR_WAIT(mb + 32, 0);

    float bv[4];
    int bidx[4];
    #pragma unroll
    for (int i = 0; i < 4; i++) { bv[i] = -3.0e38f; bidx[i] = 0; }
    float acc[2][8][4];

    for (int jj = 0; jj < 16; jj++) {
        const int half = jj & 1;           // which chunk pair of the n-tile
        const int g = jj >> 1;             // n-tile within group
        if (half == 0) {
            #pragma unroll
            for (int i = 0; i < 2; i++)
                #pragma unroll
                for (int j2 = 0; j2 < 8; j2++)
                    #pragma unroll
                    for (int k = 0; k < 4; k++) acc[i][j2][k] = 0.0f;
        }
        MBAR_WAIT(mb + (jj & 3) * 8, (jj >> 2) & 1);
        __syncthreads();
        if (tid == 0 && jj + 3 < 16) {
            const int s = (jj + 3) & 3;
            const uint32_t st = sbase + SIMS_B_OFF + s * SIMS_STG;
            MBAR_EXPECT_TX(mb + s * 8, SIMS_STG);
            CPBULK(st,        gB + (size_t)(2*(jj+3))     * BLOB, BLOB, mb + s * 8);
            CPBULK(st + BLOB, gB + (size_t)(2*(jj+3) + 1) * BLOB, BLOB, mb + s * 8);
        }
        const uint32_t uBs = sbase + SIMS_B_OFF + (uint32_t)(jj & 3) * SIMS_STG;
        #pragma unroll
        for (int h = 0; h < 2; h++) {
            const uint32_t uA = sbase + (uint32_t)(2 * half + h) * BLOB;
            const uint32_t uB = uBs + (uint32_t)h * BLOB;
            #pragma unroll
            for (int ks = 0; ks < 2; ks++) {
                const uint32_t oa = ((cA | (ks << 1)) ^ swA) << 4;
                const uint32_t ob = ((cB | (ks << 1)) ^ swB) << 4;
                uint32_t a[2][4];
                LDSM4(a[0][0], a[0][1], a[0][2], a[0][3], uA + aoff + oa);
                LDSM4(a[1][0], a[1][1], a[1][2], a[1][3], uA + aoff + 1024 + oa);
                uint32_t b[8][2];
                #pragma unroll
                for (int jp = 0; jp < 4; jp++) {
                    LDSM4(b[2*jp][0], b[2*jp][1], b[2*jp+1][0], b[2*jp+1][1],
                          uB + boff + (uint32_t)jp * 1024 + ob);
                }
                #pragma unroll
                for (int mt2 = 0; mt2 < 2; mt2++)
                    #pragma unroll
                    for (int nj = 0; nj < 8; nj++)
                        MMA_F8(acc[mt2][nj], a[mt2], b[nj]);
            }
        }
        if (half == 1) {
            // float/idx fold: indices visited in strictly ascending order ->
            // strict > keeps the earliest (smallest) index on ties, matching argmax.
            const int ib = n_base + g * 128 + warp_n + qc;
            #pragma unroll
            for (int mt2 = 0; mt2 < 2; mt2++) {
                float v0 = bv[mt2 * 2], v1 = bv[mt2 * 2 + 1];
                int i0 = bidx[mt2 * 2], i1 = bidx[mt2 * 2 + 1];
                #pragma unroll
                for (int nj = 0; nj < 8; nj++) {
                    #pragma unroll
                    for (int p = 0; p < 2; p++) {
                        const int ix = ib + nj * 8 + p;
                        float x0 = acc[mt2][nj][p];
                        if (x0 > v0) { v0 = x0; i0 = ix; }
                        float x1 = acc[mt2][nj][2 + p];
                        if (x1 > v1) { v1 = x1; i1 = ix; }
                    }
                }
                bv[mt2 * 2] = v0;  bidx[mt2 * 2] = i0;
                bv[mt2 * 2 + 1] = v1; bidx[mt2 * 2 + 1] = i1;
            }
        }
    }

    // cross-lane reduce (quad over lanes with same qr) + one atomicMax per row
    #pragma unroll
    for (int h = 0; h < 4; h++) {
        float v = bv[h];
        int i = bidx[h];
        #pragma unroll
        for (int off = 1; off <= 2; off <<= 1) {
            float v2 = __shfl_xor_sync(0xffffffffu, v, off);
            int i2 = __shfl_xor_sync(0xffffffffu, i, off);
            if (v2 > v || (v2 == v && i2 < i)) { v = v2; i = i2; }
        }
        if ((lane & 3) == 0) {
            const int mt2 = h >> 1;
            const int row = m0 + warp_m + mt2 * 16 + ((h & 1) ? 8 : 0) + qr;
            unsigned long long q = ((unsigned long long)enc_f(v) << 32)
                                 | (0xFFFFFFFFu - (unsigned)i);
            atomicMax(&g_best[row], q);
        }
    }
}

// ---------------- finalize ----------------
__global__ __launch_bounds__(256) void finalize1_kernel(
    const float* __restrict__ bg2, const float* __restrict__ bp2,
    float* __restrict__ out_obs, float* __restrict__ out_meaning, int write_extra)
{
    __shared__ float sred[256];
    __shared__ float s_pm, s_inv, s_rinv;
    int t = blockIdx.x;
    int d = threadIdx.x;
    float v = g_obs_mean[(size_t)t * Dc + d];

    sred[d] = v * v;
    __syncthreads();
    for (int s = 128; s > 0; s >>= 1) {
        if (d < s) sred[d] += sred[d + s];
        __syncthreads();
    }
    if (d == 0) {
        float pm = 0.0f;
        float bg2v = bg2[0], bp2v = bp2[0];
        #pragma unroll
        for (int b = 0; b < Bc; b++) {
            int row = b * Tc + t;
            float gl = bg2v, pl = bp2v;
            #pragma unroll
            for (int jt = 0; jt < 4; jt++) gl += g_part[jt * MGP + row];
            #pragma unroll
            for (int jt = 4; jt < 8; jt++) pl += g_part[jt * MGP + row];
            pm += sigmoidf_(gl) * softplusf_(pl);
        }
        pm *= 0.25f;
        s_pm = pm;
        s_inv = 1.0f / fmaxf(sqrtf(sred[0]), EPSC);
    }
    __syncthreads();
    float ob = v * s_inv * s_pm;
    out_obs[(size_t)t * Dc + d] = ob;

    __syncthreads();
    sred[d] = ob * ob;
    __syncthreads();
    for (int s = 128; s > 0; s >>= 1) {
        if (d < s) sred[d] += sred[d + s];
        __syncthreads();
    }
    if (d == 0) {
        float rr = sqrtf(sred[0]);
        g_rad[t] = rr;
        s_rinv = 1.0f / fmaxf(rr, EPSC);
        if (write_extra) out_meaning[t] = (rr > 0.05f) ? 1.0f : 0.0f;
    }
    __syncthreads();
    {
        uint16_t pk = pack_e4m3(ob * s_rinv * 16.0f, 0.0f);
        int mt = t >> 7, r = t & 127, sw = (r >> 1) & 3;
        int c = d >> 6;
        int pos = d & 63;
        int k16 = pos >> 4;
        size_t off = ((size_t)(mt * 4 + c)) * BLOB + r * 64 + ((k16 ^ sw) << 4) + (pos & 15);
        g_oang8[off] = (unsigned char)(pk & 0xFF);
    }
}

__global__ void finalize2_kernel(float* __restrict__ out_sims, float* __restrict__ out_slots) {
    int t = blockIdx.x * blockDim.x + threadIdx.x;
    if (t >= Tc) return;
    unsigned long long b = g_best[t];
    float sim = 0.0f;
    int idx = -1;
    bool has = (b != 0ULL);
    if (has) {
        sim = dec_f((unsigned)(b >> 32)) * 0.00390625f;   // acc = 256*sim
        idx = (int)(0xFFFFFFFFu - (unsigned)(b & 0xFFFFFFFFu));
    }
    bool matched = has && (g_rad[t] > 0.05f) && (sim > 0.5f);
    out_sims[t]  = matched ? sim : 0.0f;
    out_slots[t] = matched ? (float)idx : -1.0f;
}

// ---------------- launcher ----------------
extern "C" void kernel_launch(void* const* d_in, const int* in_sizes, int n_in,
                              void* d_out, int out_size)
{
    const float* hidden  = (const float*)d_in[0];
    const float* beliefs = (const float*)d_in[1];
    const void*  maskp   = d_in[2];
    const float* W_obs   = (const float*)d_in[3];
    const float* W_g1    = (const float*)d_in[4];
    const float* b_g1    = (const float*)d_in[5];
    const float* W_g2    = (const float*)d_in[6];
    const float* b_g2    = (const float*)d_in[7];
    const float* W_p1    = (const float*)d_in[8];
    const float* b_p1    = (const float*)d_in[9];
    const float* W_p2    = (const float*)d_in[10];
    const float* b_p2    = (const float*)d_in[11];
    float* out = (float*)d_out;

    static int attr_set = 0;
    if (!attr_set) {
        cudaFuncSetAttribute(gpobs_mma_kernel, cudaFuncAttributeMaxDynamicSharedMemorySize, DYN_SMEM);
        cudaFuncSetAttribute(sims_mma_kernel, cudaFuncAttributeMaxDynamicSharedMemorySize, SIMS_SMEM);
        attr_set = 1;
    }

    const size_t base = (size_t)Tc * Dc;
    const int write_extra = (out_size >= (int)(base + 3 * Tc)) ? 1 : 0;
    float* out_obs     = out;
    float* out_sims    = out + base;
    float* out_slots   = out + base + Tc;
    float* out_meaning = out + base + 2 * Tc;

    init_best_kernel<<<Tc / 256, 256>>>();
    prep_hidden_kernel<<<(Tc * 64) / 256, 256>>>(hidden);
    prep_weights_kernel<<<(1280 * 64) / 256, 256>>>(W_g1, W_p1, W_obs);
    prep_small_kernel<<<4, 256>>>(b_g1, b_p1, W_g2, W_p2);
    gpobs_mma_kernel<<<dim3(9, MGP / 128), 256, DYN_SMEM>>>();
    detect_mask_kernel<<<Nc / 256, 256>>>((const unsigned char*)maskp);
    convert_mask_kernel<<<Nc / 256, 256>>>(maskp);
    binv_kernel<<<Nc / 8, 256>>>(beliefs);
    prep_beliefs_kernel<<<(Nc * 4) / 256, 256>>>(beliefs);
    finalize1_kernel<<<Tc, 256>>>(b_g2, b_p2, out_obs, out_meaning, write_extra);
    sims_mma_kernel<<<dim3(32, 32), 256, SIMS_SMEM>>>();
    if (write_extra) {
        finalize2_kernel<<<Tc / 256, 256>>>(out_sims, out_slots);
    }
}

// round 15
// speedup vs baseline: 1.0968x; 1.0335x over previous
#include <cuda_runtime.h>
#include <cuda_fp16.h>
#include <cstdint>

#define Bc 4
#define Tc 4096
#define Hc 2048
#define Dc 256
#define Nc 32768
#define MGP (Bc*Tc)
#define EPSC 1e-8f
#define BLOB 8192            // one operand tile-chunk: 128 rows x 64B, SW64 swizzled

// ---------------- device scratch ----------------
__device__ unsigned char g_Af[(size_t)128 * 64 * BLOB];
__device__ unsigned char g_Hmhi[(size_t)32 * 64 * BLOB];
__device__ unsigned char g_Hmlo[(size_t)32 * 64 * BLOB];
__device__ unsigned char g_Wcf[(size_t)8 * 64 * BLOB];
__device__ unsigned char g_Wohi[(size_t)2 * 64 * BLOB];
__device__ unsigned char g_Wolo[(size_t)2 * 64 * BLOB];
__device__ unsigned char g_Bb8[(size_t)256 * 4 * BLOB];    // normalized beliefs e4m3 (x16, inactive=0)
__device__ unsigned char g_oang8[(size_t)32 * 4 * BLOB];
__device__ float g_bc1[1024];
__device__ float g_wc2[1024];
__device__ float g_obs_mean[(size_t)Tc * Dc];
__device__ float g_part[8 * MGP];
__device__ float g_binv[Nc];
__device__ unsigned char g_active[Nc];
__device__ unsigned long long g_best[Tc];
__device__ float g_rad[Tc];
__device__ int g_weird;
__device__ int g_off4;

// ---------------- helpers ----------------
__device__ __forceinline__ uint32_t smem_u32(const void* p) {
    uint32_t a;
    asm("{ .reg .u64 t; cvta.to.shared.u64 t, %1; cvt.u32.u64 %0, t; }" : "=r"(a) : "l"(p));
    return a;
}
#define LDSM4(R0, R1, R2, R3, A) \
    asm volatile("ldmatrix.sync.aligned.m8n8.x4.shared.b16 {%0,%1,%2,%3}, [%4];" \
        : "=r"(R0), "=r"(R1), "=r"(R2), "=r"(R3) : "r"(A))
#define MMA_F16(D, A, B) \
    asm volatile("mma.sync.aligned.m16n8k16.row.col.f32.f16.f16.f32 " \
        "{%0,%1,%2,%3}, {%4,%5,%6,%7}, {%8,%9}, {%0,%1,%2,%3};" \
        : "+f"((D)[0]), "+f"((D)[1]), "+f"((D)[2]), "+f"((D)[3]) \
        : "r"((A)[0]), "r"((A)[1]), "r"((A)[2]), "r"((A)[3]), "r"((B)[0]), "r"((B)[1]))
#define MMA_F8(D, A, B) \
    asm volatile("mma.sync.aligned.m16n8k32.row.col.f32.e4m3.e4m3.f32 " \
        "{%0,%1,%2,%3}, {%4,%5,%6,%7}, {%8,%9}, {%0,%1,%2,%3};" \
        : "+f"((D)[0]), "+f"((D)[1]), "+f"((D)[2]), "+f"((D)[3]) \
        : "r"((A)[0]), "r"((A)[1]), "r"((A)[2]), "r"((A)[3]), "r"((B)[0]), "r"((B)[1]))
#define CPBULK(DST, SRC, BYTES, MBAR) \
    asm volatile("cp.async.bulk.shared::cta.global.mbarrier::complete_tx::bytes [%0], [%1], %2, [%3];" \
        :: "r"((uint32_t)(DST)), "l"(SRC), "r"((uint32_t)(BYTES)), "r"((uint32_t)(MBAR)) : "memory")
#define MBAR_INIT(mb, n) \
    asm volatile("mbarrier.init.shared.b64 [%0], %1;" :: "r"((uint32_t)(mb)), "r"((uint32_t)(n)) : "memory")
#define MBAR_EXPECT_TX(mb, bytes) \
    asm volatile("mbarrier.arrive.expect_tx.shared.b64 _, [%0], %1;" \
        :: "r"((uint32_t)(mb)), "r"((uint32_t)(bytes)) : "memory")
#define MBAR_WAIT(mb, ph) do { \
    uint32_t _m = (uint32_t)(mb); uint32_t _p = (uint32_t)(ph); uint32_t _d; \
    asm volatile("{\n\t.reg .pred p;\n\t" \
        "mbarrier.try_wait.parity.acquire.cta.shared::cta.b64 p, [%1], %2;\n\t" \
        "selp.b32 %0, 1, 0, p;\n\t}" : "=r"(_d) : "r"(_m), "r"(_p) : "memory"); \
    if (!_d) { \
        asm volatile("{\n\t.reg .pred P1;\n\t" \
            "WL_%=:\n\t" \
            "mbarrier.try_wait.parity.acquire.cta.shared::cta.b64 P1, [%0], %1, 0x989680;\n\t" \
            "@P1 bra.uni WD_%=;\n\t" \
            "bra.uni WL_%=;\n\t" \
            "WD_%=:\n\t}" :: "r"(_m), "r"(_p) : "memory"); \
    } } while (0)

__device__ __forceinline__ unsigned enc_f(float f) {
    unsigned u = __float_as_uint(f);
    return (u & 0x80000000u) ? ~u : (u | 0x80000000u);
}
__device__ __forceinline__ float dec_f(unsigned e) {
    unsigned u = (e & 0x80000000u) ? (e ^ 0x80000000u) : ~e;
    return __uint_as_float(u);
}
__device__ __forceinline__ float sigmoidf_(float x) { return 1.0f / (1.0f + expf(-x)); }
__device__ __forceinline__ float softplusf_(float x) {
    return fmaxf(x, 0.0f) + log1pf(expf(-fabsf(x)));
}
__device__ __forceinline__ uint16_t pack_e4m3(float lo, float hi) {
    uint16_t r;
    asm("cvt.rn.satfinite.e4m3x2.f32 %0, %1, %2;" : "=h"(r) : "f"(hi), "f"(lo));
    return r;
}
__device__ __forceinline__ uint32_t pk_h2(float a, float b) {
    __half2 h = __halves2half2(__float2half_rn(a), __float2half_rn(b));
    return *(uint32_t*)&h;
}

// ---------------- prep kernels ----------------
__global__ void prep_hidden_kernel(const float* __restrict__ hidden) {
    int idx = blockIdx.x * blockDim.x + threadIdx.x;
    int t = idx >> 6, c = idx & 63;
    const int r = t & 127;
    const int sw = (r >> 1) & 3;
    float acc[32];
    #pragma unroll
    for (int j = 0; j < 32; j++) acc[j] = 0.0f;
    #pragma unroll
    for (int b = 0; b < Bc; b++) {
        const float* src = hidden + ((size_t)(b * Tc + t)) * Hc + c * 32;
        float v[32];
        #pragma unroll
        for (int q = 0; q < 8; q++) {
            float4 f = *(const float4*)(src + q * 4);
            v[q*4+0] = f.x; v[q*4+1] = f.y; v[q*4+2] = f.z; v[q*4+3] = f.w;
        }
        #pragma unroll
        for (int j = 0; j < 32; j++) acc[j] += v[j];
        char* dst = (char*)g_Af + ((size_t)(((b * Tc + t) >> 7) * 64 + c)) * BLOB + r * 64;
        #pragma unroll
        for (int k16 = 0; k16 < 4; k16++) {
            uint4 u = make_uint4(pk_h2(v[k16*8+0], v[k16*8+1]), pk_h2(v[k16*8+2], v[k16*8+3]),
                                 pk_h2(v[k16*8+4], v[k16*8+5]), pk_h2(v[k16*8+6], v[k16*8+7]));
            *(uint4*)(dst + ((k16 ^ sw) << 4)) = u;
        }
    }
    float hi[32], lo[32];
    #pragma unroll
    for (int j = 0; j < 32; j++) {
        float m = acc[j] * 0.25f;
        float h = __half2float(__float2half_rn(m));
        hi[j] = m;
        lo[j] = m - h;
    }
    size_t boff = ((size_t)((t >> 7) * 64 + c)) * BLOB + r * 64;
    char* dh = (char*)g_Hmhi + boff;
    char* dl = (char*)g_Hmlo + boff;
    #pragma unroll
    for (int k16 = 0; k16 < 4; k16++) {
        uint4 uh = make_uint4(pk_h2(hi[k16*8+0], hi[k16*8+1]), pk_h2(hi[k16*8+2], hi[k16*8+3]),
                              pk_h2(hi[k16*8+4], hi[k16*8+5]), pk_h2(hi[k16*8+6], hi[k16*8+7]));
        uint4 ul = make_uint4(pk_h2(lo[k16*8+0], lo[k16*8+1]), pk_h2(lo[k16*8+2], lo[k16*8+3]),
                              pk_h2(lo[k16*8+4], lo[k16*8+5]), pk_h2(lo[k16*8+6], lo[k16*8+7]));
        *(uint4*)(dh + ((k16 ^ sw) << 4)) = uh;
        *(uint4*)(dl + ((k16 ^ sw) << 4)) = ul;
    }
}

__global__ void prep_weights_kernel(const float* __restrict__ Wg1, const float* __restrict__ Wp1,
                                    const float* __restrict__ Wobs) {
    int idx = blockIdx.x * blockDim.x + threadIdx.x;
    int row = idx >> 6, c = idx & 63;
    float v[32];
    const float* src;
    if (row < 512)        src = Wg1 + (size_t)row * Hc + c * 32;
    else if (row < 1024)  src = Wp1 + (size_t)(row - 512) * Hc + c * 32;
    else                  src = Wobs + (size_t)(row - 1024) * Hc + c * 32;
    #pragma unroll
    for (int q = 0; q < 8; q++) {
        float4 f = *(const float4*)(src + q * 4);
        v[q*4+0] = f.x; v[q*4+1] = f.y; v[q*4+2] = f.z; v[q*4+3] = f.w;
    }
    if (row < 1024) {
        int r = row & 127, sw = (r >> 1) & 3;
        char* dst = (char*)g_Wcf + ((size_t)((row >> 7) * 64 + c)) * BLOB + r * 64;
        #pragma unroll
        for (int k16 = 0; k16 < 4; k16++) {
            uint4 u = make_uint4(pk_h2(v[k16*8+0], v[k16*8+1]), pk_h2(v[k16*8+2], v[k16*8+3]),
                                 pk_h2(v[k16*8+4], v[k16*8+5]), pk_h2(v[k16*8+6], v[k16*8+7]));
            *(uint4*)(dst + ((k16 ^ sw) << 4)) = u;
        }
    } else {
        int r2 = row - 1024;
        int r = r2 & 127, sw = (r >> 1) & 3;
        size_t boff = ((size_t)((r2 >> 7) * 64 + c)) * BLOB + r * 64;
        char* dh = (char*)g_Wohi + boff;
        char* dl = (char*)g_Wolo + boff;
        float hi[32], lo[32];
        #pragma unroll
        for (int j = 0; j < 32; j++) {
            float h = __half2float(__float2half_rn(v[j]));
            hi[j] = v[j];
            lo[j] = v[j] - h;
        }
        #pragma unroll
        for (int k16 = 0; k16 < 4; k16++) {
            uint4 uh = make_uint4(pk_h2(hi[k16*8+0], hi[k16*8+1]), pk_h2(hi[k16*8+2], hi[k16*8+3]),
                                  pk_h2(hi[k16*8+4], hi[k16*8+5]), pk_h2(hi[k16*8+6], hi[k16*8+7]));
            uint4 ul = make_uint4(pk_h2(lo[k16*8+0], lo[k16*8+1]), pk_h2(lo[k16*8+2], lo[k16*8+3]),
                                  pk_h2(lo[k16*8+4], lo[k16*8+5]), pk_h2(lo[k16*8+6], lo[k16*8+7]));
            *(uint4*)(dh + ((k16 ^ sw) << 4)) = uh;
            *(uint4*)(dl + ((k16 ^ sw) << 4)) = ul;
        }
    }
}

// init: zero best array + fill small vectors (merged prep_small)
__global__ void init_best_kernel(const float* __restrict__ bg1, const float* __restrict__ bp1,
                                 const float* __restrict__ Wg2, const float* __restrict__ Wp2) {
    int i = blockIdx.x * blockDim.x + threadIdx.x;
    if (i < Tc) g_best[i] = 0ULL;
    if (i < 1024) {
        g_bc1[i] = (i < 512) ? bg1[i] : bp1[i - 512];
        g_wc2[i] = (i < 512) ? Wg2[i] : Wp2[i - 512];
    }
}

__global__ void zero_flags_kernel() {
    g_weird = 0;
    g_off4 = 0;
}

__global__ void prep_beliefs_kernel(const float* __restrict__ beliefs) {
    int idx = blockIdx.x * blockDim.x + threadIdx.x;
    int n = idx >> 2, c = idx & 3;
    int r = n & 127, sw = (r >> 1) & 3;
    float bi = g_binv[n];
    const float* src = beliefs + (size_t)n * Dc + c * 64;
    char* dst = (char*)g_Bb8 + ((size_t)((n >> 7) * 4 + c)) * BLOB + r * 64;
    #pragma unroll
    for (int k16 = 0; k16 < 4; k16++) {
        uint32_t w[4];
        #pragma unroll
        for (int q = 0; q < 4; q++) {
            float4 f = *(const float4*)(src + k16 * 16 + q * 4);
            uint16_t a = pack_e4m3(f.x * bi, f.y * bi);
            uint16_t b = pack_e4m3(f.z * bi, f.w * bi);
            w[q] = ((uint32_t)b << 16) | a;
        }
        *(uint4*)(dst + ((k16 ^ sw) << 4)) = make_uint4(w[0], w[1], w[2], w[3]);
    }
}

__global__ void detect_mask_kernel(const unsigned char* __restrict__ m) {
    int i = blockIdx.x * blockDim.x + threadIdx.x;
    unsigned char c = m[i];
    int w = 0, o = 0;
    if (c > 1) w = 1;
    if (c != 0 && (i & 3)) o = 1;
    w = __reduce_or_sync(0xffffffffu, w);
    o = __reduce_or_sync(0xffffffffu, o);
    if ((threadIdx.x & 31) == 0) {
        if (w) atomicOr(&g_weird, 1);
        if (o) atomicOr(&g_off4, 1);
    }
}
__global__ void convert_mask_kernel(const void* __restrict__ m) {
    int i = blockIdx.x * blockDim.x + threadIdx.x;
    if (i >= Nc) return;
    int fmt = g_weird ? 2 : (g_off4 ? 1 : 0);
    unsigned char a;
    if (fmt == 0)      a = (((const int*)m)[i] != 0);
    else if (fmt == 1) a = (((const unsigned char*)m)[i] != 0);
    else               a = (((const float*)m)[i] != 0.0f);
    g_active[i] = a;
}
__global__ void binv_kernel(const float* __restrict__ beliefs) {
    int row = blockIdx.x * 8 + (threadIdx.x >> 5);
    int lane = threadIdx.x & 31;
    const float4* p = reinterpret_cast<const float4*>(beliefs + (size_t)row * Dc);
    float s = 0.0f;
    #pragma unroll
    for (int r = 0; r < 2; r++) {
        float4 v = p[lane + r * 32];
        s += v.x * v.x + v.y * v.y + v.z * v.z + v.w * v.w;
    }
    #pragma unroll
    for (int o = 16; o > 0; o >>= 1) s += __shfl_down_sync(0xffffffffu, s, o);
    if (lane == 0)
        g_binv[row] = g_active[row] ? (16.0f / fmaxf(sqrtf(s), EPSC)) : 0.0f;
}

// ============ merged gate/prec + obs GEMM kernel ============
#define GP_STAGE2 32768
#define OB_STAGE 32768
#define DYN_SMEM 98304

__global__ __launch_bounds__(256, 2) void gpobs_mma_kernel() {
    extern __shared__ __align__(128) char dsm[];
    __shared__ float s_b1[128], s_w2[128], s_red[128];
    __shared__ __align__(8) unsigned long long s_mbar[4];

    const int tid = threadIdx.x, lane = tid & 31, wid = tid >> 5;
    const int warp_m = (wid >> 1) * 32;
    const int warp_n = (wid & 1) * 64;
    const uint32_t sbase = smem_u32(dsm);
    const uint32_t mb = smem_u32(s_mbar);

    const int rowA = warp_m + (lane & 15);
    const uint32_t cA = (uint32_t)(lane >> 4);
    const uint32_t swA = (uint32_t)((rowA >> 1) & 3);
    const uint32_t aoff = (uint32_t)rowA * 64;
    const int rowB = warp_n + ((lane >> 4) << 3) + (lane & 7);
    const uint32_t cB = (uint32_t)((lane >> 3) & 1);
    const uint32_t swB = (uint32_t)((rowB >> 1) & 3);
    const uint32_t boff = (uint32_t)rowB * 64;

    float acc[2][8][4];
    #pragma unroll
    for (int i = 0; i < 2; i++)
        #pragma unroll
        for (int j = 0; j < 8; j++)
            #pragma unroll
            for (int k = 0; k < 4; k++) acc[i][j][k] = 0.0f;

    const int qr = lane >> 2;
    const int qc = (lane & 3) * 2;

    if (blockIdx.x < 8) {
        const int nt = blockIdx.x;
        const int mt = blockIdx.y;
        const int m0 = mt * 128, nbase = nt * 128;
        if (tid < 128) {
            s_b1[tid] = g_bc1[nbase + tid];
            s_w2[tid] = g_wc2[nbase + tid];
            s_red[tid] = 0.0f;
        }
        const char* gA = (const char*)g_Af + (size_t)mt * 64 * BLOB;
        const char* gB = (const char*)g_Wcf + (size_t)nt * 64 * BLOB;

        if (tid == 0) {
            #pragma unroll
            for (int s = 0; s < 3; s++) MBAR_INIT(mb + s * 8, 1);
        }
        __syncthreads();
        if (tid == 0) {
            #pragma unroll
            for (int c = 0; c < 2; c++) {
                const uint32_t st = sbase + c * GP_STAGE2;
                MBAR_EXPECT_TX(mb + c * 8, GP_STAGE2);
                CPBULK(st,         gA + (size_t)(2*c)     * BLOB, BLOB, mb + c * 8);
                CPBULK(st + 8192,  gA + (size_t)(2*c + 1) * BLOB, BLOB, mb + c * 8);
                CPBULK(st + 16384, gB + (size_t)(2*c)     * BLOB, BLOB, mb + c * 8);
                CPBULK(st + 24576, gB + (size_t)(2*c + 1) * BLOB, BLOB, mb + c * 8);
            }
        }

        for (int c = 0; c < 32; c++) {
            MBAR_WAIT(mb + (c % 3) * 8, (c / 3) & 1);
            __syncthreads();
            if (tid == 0 && c + 2 < 32) {
                const int s = (c + 2) % 3;
                const uint32_t st = sbase + s * GP_STAGE2;
                MBAR_EXPECT_TX(mb + s * 8, GP_STAGE2);
                CPBULK(st,         gA + (size_t)(2*(c+2))     * BLOB, BLOB, mb + s * 8);
                CPBULK(st + 8192,  gA + (size_t)(2*(c+2) + 1) * BLOB, BLOB, mb + s * 8);
                CPBULK(st + 16384, gB + (size_t)(2*(c+2))     * BLOB, BLOB, mb + s * 8);
                CPBULK(st + 24576, gB + (size_t)(2*(c+2) + 1) * BLOB, BLOB, mb + s * 8);
            }
            const uint32_t uS = sbase + (c % 3) * GP_STAGE2;
            #pragma unroll
            for (int h = 0; h < 2; h++) {
                const uint32_t uA = uS + (uint32_t)h * 8192;
                const uint32_t uB = uS + 16384 + (uint32_t)h * 8192;
                #pragma unroll
                for (int ks = 0; ks < 2; ks++) {
                    const uint32_t oa = ((cA | (ks << 1)) ^ swA) << 4;
                    const uint32_t ob = ((cB | (ks << 1)) ^ swB) << 4;
                    uint32_t a[2][4];
                    LDSM4(a[0][0], a[0][1], a[0][2], a[0][3], uA + aoff + oa);
                    LDSM4(a[1][0], a[1][1], a[1][2], a[1][3], uA + aoff + 1024 + oa);
                    uint32_t b[8][2];
                    #pragma unroll
                    for (int jp = 0; jp < 4; jp++) {
                        LDSM4(b[2*jp][0], b[2*jp][1], b[2*jp+1][0], b[2*jp+1][1],
                              uB + boff + (uint32_t)jp * 1024 + ob);
                    }
                    #pragma unroll
                    for (int mt2 = 0; mt2 < 2; mt2++)
                        #pragma unroll
                        for (int nj = 0; nj < 8; nj++)
                            MMA_F16(acc[mt2][nj], a[mt2], b[nj]);
                }
            }
        }
        __syncthreads();

        #pragma unroll
        for (int mt2 = 0; mt2 < 2; mt2++) {
            float p0 = 0.0f, p1 = 0.0f;
            #pragma unroll
            for (int nj = 0; nj < 8; nj++) {
                int col = warp_n + nj * 8 + qc;
                p0 += fmaxf(acc[mt2][nj][0] + s_b1[col], 0.0f) * s_w2[col]
                    + fmaxf(acc[mt2][nj][1] + s_b1[col + 1], 0.0f) * s_w2[col + 1];
                p1 += fmaxf(acc[mt2][nj][2] + s_b1[col], 0.0f) * s_w2[col]
                    + fmaxf(acc[mt2][nj][3] + s_b1[col + 1], 0.0f) * s_w2[col + 1];
            }
            p0 += __shfl_xor_sync(0xffffffffu, p0, 1);
            p0 += __shfl_xor_sync(0xffffffffu, p0, 2);
            p1 += __shfl_xor_sync(0xffffffffu, p1, 1);
            p1 += __shfl_xor_sync(0xffffffffu, p1, 2);
            if ((lane & 3) == 0) {
                atomicAdd(&s_red[warp_m + mt2 * 16 + qr], p0);
                atomicAdd(&s_red[warp_m + mt2 * 16 + 8 + qr], p1);
            }
        }
        __syncthreads();
        if (tid < 128) g_part[nt * MGP + m0 + tid] = s_red[tid];
    } else {
        const int id = blockIdx.y;
        if (id >= 64) return;
        const int nt = id & 1;
        const int mt = id >> 1;
        const int m0 = mt * 128, nbase = nt * 128;
        const char* gAh = (const char*)g_Hmhi + (size_t)mt * 64 * BLOB;
        const char* gAl = (const char*)g_Hmlo + (size_t)mt * 64 * BLOB;
        const char* gBh = (const char*)g_Wohi + (size_t)nt * 64 * BLOB;
        const char* gBl = (const char*)g_Wolo + (size_t)nt * 64 * BLOB;

        if (tid == 0) {
            MBAR_INIT(mb, 1);
            MBAR_INIT(mb + 8, 1);
        }
        __syncthreads();
        if (tid == 0) {
            MBAR_EXPECT_TX(mb, OB_STAGE);
            CPBULK(sbase,         gAh, BLOB, mb);
            CPBULK(sbase + 8192,  gAl, BLOB, mb);
            CPBULK(sbase + 16384, gBh, BLOB, mb);
            CPBULK(sbase + 24576, gBl, BLOB, mb);
        }

        for (int c = 0; c < 64; c++) {
            MBAR_WAIT(mb + (c & 1) * 8, (c >> 1) & 1);
            __syncthreads();
            if (tid == 0 && c + 1 < 64) {
                const int s = (c + 1) & 1;
                const uint32_t st = sbase + s * OB_STAGE;
                MBAR_EXPECT_TX(mb + s * 8, OB_STAGE);
                CPBULK(st,         gAh + (size_t)(c + 1) * BLOB, BLOB, mb + s * 8);
                CPBULK(st + 8192,  gAl + (size_t)(c + 1) * BLOB, BLOB, mb + s * 8);
                CPBULK(st + 16384, gBh + (size_t)(c + 1) * BLOB, BLOB, mb + s * 8);
                CPBULK(st + 24576, gBl + (size_t)(c + 1) * BLOB, BLOB, mb + s * 8);
            }
            const uint32_t uS = sbase + (c & 1) * OB_STAGE;
            #pragma unroll
            for (int tr = 0; tr < 3; tr++) {
                const uint32_t uA = uS + (tr == 2 ? 8192u : 0u);
                const uint32_t uB = uS + 16384u + (tr == 1 ? 8192u : 0u);
                #pragma unroll
                for (int ks = 0; ks < 2; ks++) {
                    const uint32_t oa = ((cA | (ks << 1)) ^ swA) << 4;
                    const uint32_t ob = ((cB | (ks << 1)) ^ swB) << 4;
                    uint32_t a[2][4];
                    LDSM4(a[0][0], a[0][1], a[0][2], a[0][3], uA + aoff + oa);
                    LDSM4(a[1][0], a[1][1], a[1][2], a[1][3], uA + aoff + 1024 + oa);
                    uint32_t b[8][2];
                    #pragma unroll
                    for (int jp = 0; jp < 4; jp++) {
                        LDSM4(b[2*jp][0], b[2*jp][1], b[2*jp+1][0], b[2*jp+1][1],
                              uB + boff + (uint32_t)jp * 1024 + ob);
                    }
                    #pragma unroll
                    for (int mt2 = 0; mt2 < 2; mt2++)
                        #pragma unroll
                        for (int nj = 0; nj < 8; nj++)
                            MMA_F16(acc[mt2][nj], a[mt2], b[nj]);
                }
            }
        }

        #pragma unroll
        for (int mt2 = 0; mt2 < 2; mt2++)
            #pragma unroll
            for (int nj = 0; nj < 8; nj++) {
                int row = m0 + warp_m + mt2 * 16 + qr;
                int col = nbase + warp_n + nj * 8 + qc;
                *(float2*)(g_obs_mean + (size_t)row * Dc + col) = make_float2(acc[mt2][nj][0], acc[mt2][nj][1]);
                *(float2*)(g_obs_mean + (size_t)(row + 8) * Dc + col) = make_float2(acc[mt2][nj][2], acc[mt2][nj][3]);
            }
    }
}

// ============ sims GEMM: 16KB B stages (2 blobs), float/idx fold ============
#define SIMS_B_OFF 32768
#define SIMS_STG 16384
#define SIMS_SMEM 98304
__global__ __launch_bounds__(256, 2) void sims_mma_kernel() {
    extern __shared__ __align__(128) char dsm[];
    __shared__ __align__(8) unsigned long long s_mbar[5];

    const int tid = threadIdx.x, lane = tid & 31, wid = tid >> 5;
    const int ng = blockIdx.x;
    const int mt = blockIdx.y;
    const int n_base = ng * 1024, m0 = mt * 128;
    const int warp_m = (wid >> 1) * 32;
    const int warp_n = (wid & 1) * 64;
    const uint32_t sbase = smem_u32(dsm);
    const uint32_t mb = smem_u32(s_mbar);

    const int rowA = warp_m + (lane & 15);
    const uint32_t cA = (uint32_t)(lane >> 4);
    const uint32_t swA = (uint32_t)((rowA >> 1) & 3);
    const uint32_t aoff = (uint32_t)rowA * 64;
    const int rowB = warp_n + ((lane >> 4) << 3) + (lane & 7);
    const uint32_t cB = (uint32_t)((lane >> 3) & 1);
    const uint32_t swB = (uint32_t)((rowB >> 1) & 3);
    const uint32_t boff = (uint32_t)rowB * 64;

    const char* gA = (const char*)g_oang8 + (size_t)mt * 4 * BLOB;
    const char* gB = (const char*)g_Bb8 + (size_t)ng * 32 * BLOB;

    const int qr = lane >> 2;
    const int qc = (lane & 3) * 2;

    if (tid == 0) {
        #pragma unroll
        for (int s = 0; s < 5; s++) MBAR_INIT(mb + s * 8, 1);
    }
    __syncthreads();
    if (tid == 0) {
        MBAR_EXPECT_TX(mb + 32, 4 * BLOB);
        #pragma unroll
        for (int c = 0; c < 4; c++)
            CPBULK(sbase + c * BLOB, gA + (size_t)c * BLOB, BLOB, mb + 32);
        #pragma unroll
        for (int j = 0; j < 3; j++) {
            MBAR_EXPECT_TX(mb + j * 8, SIMS_STG);
            CPBULK(sbase + SIMS_B_OFF + j * SIMS_STG,        gB + (size_t)(2*j)     * BLOB, BLOB, mb + j * 8);
            CPBULK(sbase + SIMS_B_OFF + j * SIMS_STG + BLOB, gB + (size_t)(2*j + 1) * BLOB, BLOB, mb + j * 8);
        }
    }
    MBAR_WAIT(mb + 32, 0);

    float bv[4];
    int bidx[4];
    #pragma unroll
    for (int i = 0; i < 4; i++) { bv[i] = -3.0e38f; bidx[i] = 0; }
    float acc[2][8][4];

    for (int jj = 0; jj < 16; jj++) {
        const int half = jj & 1;
        const int g = jj >> 1;
        if (half == 0) {
            #pragma unroll
            for (int i = 0; i < 2; i++)
                #pragma unroll
                for (int j2 = 0; j2 < 8; j2++)
                    #pragma unroll
                    for (int k = 0; k < 4; k++) acc[i][j2][k] = 0.0f;
        }
        MBAR_WAIT(mb + (jj & 3) * 8, (jj >> 2) & 1);
        __syncthreads();
        if (tid == 0 && jj + 3 < 16) {
            const int s = (jj + 3) & 3;
            const uint32_t st = sbase + SIMS_B_OFF + s * SIMS_STG;
            MBAR_EXPECT_TX(mb + s * 8, SIMS_STG);
            CPBULK(st,        gB + (size_t)(2*(jj+3))     * BLOB, BLOB, mb + s * 8);
            CPBULK(st + BLOB, gB + (size_t)(2*(jj+3) + 1) * BLOB, BLOB, mb + s * 8);
        }
        const uint32_t uBs = sbase + SIMS_B_OFF + (uint32_t)(jj & 3) * SIMS_STG;
        #pragma unroll
        for (int h = 0; h < 2; h++) {
            const uint32_t uA = sbase + (uint32_t)(2 * half + h) * BLOB;
            const uint32_t uB = uBs + (uint32_t)h * BLOB;
            #pragma unroll
            for (int ks = 0; ks < 2; ks++) {
                const uint32_t oa = ((cA | (ks << 1)) ^ swA) << 4;
                const uint32_t ob = ((cB | (ks << 1)) ^ swB) << 4;
                uint32_t a[2][4];
                LDSM4(a[0][0], a[0][1], a[0][2], a[0][3], uA + aoff + oa);
                LDSM4(a[1][0], a[1][1], a[1][2], a[1][3], uA + aoff + 1024 + oa);
                uint32_t b[8][2];
                #pragma unroll
                for (int jp = 0; jp < 4; jp++) {
                    LDSM4(b[2*jp][0], b[2*jp][1], b[2*jp+1][0], b[2*jp+1][1],
                          uB + boff + (uint32_t)jp * 1024 + ob);
                }
                #pragma unroll
                for (int mt2 = 0; mt2 < 2; mt2++)
                    #pragma unroll
                    for (int nj = 0; nj < 8; nj++)
                        MMA_F8(acc[mt2][nj], a[mt2], b[nj]);
            }
        }
        if (half == 1) {
            const int ib = n_base + g * 128 + warp_n + qc;
            #pragma unroll
            for (int mt2 = 0; mt2 < 2; mt2++) {
                float v0 = bv[mt2 * 2], v1 = bv[mt2 * 2 + 1];
                int i0 = bidx[mt2 * 2], i1 = bidx[mt2 * 2 + 1];
                #pragma unroll
                for (int nj = 0; nj < 8; nj++) {
                    #pragma unroll
                    for (int p = 0; p < 2; p++) {
                        const int ix = ib + nj * 8 + p;
                        float x0 = acc[mt2][nj][p];
                        if (x0 > v0) { v0 = x0; i0 = ix; }
                        float x1 = acc[mt2][nj][2 + p];
                        if (x1 > v1) { v1 = x1; i1 = ix; }
                    }
                }
                bv[mt2 * 2] = v0;  bidx[mt2 * 2] = i0;
                bv[mt2 * 2 + 1] = v1; bidx[mt2 * 2 + 1] = i1;
            }
        }
    }

    #pragma unroll
    for (int h = 0; h < 4; h++) {
        float v = bv[h];
        int i = bidx[h];
        #pragma unroll
        for (int off = 1; off <= 2; off <<= 1) {
            float v2 = __shfl_xor_sync(0xffffffffu, v, off);
            int i2 = __shfl_xor_sync(0xffffffffu, i, off);
            if (v2 > v || (v2 == v && i2 < i)) { v = v2; i = i2; }
        }
        if ((lane & 3) == 0) {
            const int mt2 = h >> 1;
            const int row = m0 + warp_m + mt2 * 16 + ((h & 1) ? 8 : 0) + qr;
            unsigned long long q = ((unsigned long long)enc_f(v) << 32)
                                 | (0xFFFFFFFFu - (unsigned)i);
            atomicMax(&g_best[row], q);
        }
    }
}

// ---------------- finalize ----------------
__global__ __launch_bounds__(256) void finalize1_kernel(
    const float* __restrict__ bg2, const float* __restrict__ bp2,
    float* __restrict__ out_obs, float* __restrict__ out_meaning, int write_extra)
{
    __shared__ float sred[256];
    __shared__ float s_pm, s_inv, s_rinv;
    int t = blockIdx.x;
    int d = threadIdx.x;
    float v = g_obs_mean[(size_t)t * Dc + d];

    sred[d] = v * v;
    __syncthreads();
    for (int s = 128; s > 0; s >>= 1) {
        if (d < s) sred[d] += sred[d + s];
        __syncthreads();
    }
    if (d == 0) {
        float pm = 0.0f;
        float bg2v = bg2[0], bp2v = bp2[0];
        #pragma unroll
        for (int b = 0; b < Bc; b++) {
            int row = b * Tc + t;
            float gl = bg2v, pl = bp2v;
            #pragma unroll
            for (int jt = 0; jt < 4; jt++) gl += g_part[jt * MGP + row];
            #pragma unroll
            for (int jt = 4; jt < 8; jt++) pl += g_part[jt * MGP + row];
            pm += sigmoidf_(gl) * softplusf_(pl);
        }
        pm *= 0.25f;
        s_pm = pm;
        s_inv = 1.0f / fmaxf(sqrtf(sred[0]), EPSC);
    }
    __syncthreads();
    float ob = v * s_inv * s_pm;
    out_obs[(size_t)t * Dc + d] = ob;

    __syncthreads();
    sred[d] = ob * ob;
    __syncthreads();
    for (int s = 128; s > 0; s >>= 1) {
        if (d < s) sred[d] += sred[d + s];
        __syncthreads();
    }
    if (d == 0) {
        float rr = sqrtf(sred[0]);
        g_rad[t] = rr;
        s_rinv = 1.0f / fmaxf(rr, EPSC);
        if (write_extra) out_meaning[t] = (rr > 0.05f) ? 1.0f : 0.0f;
    }
    __syncthreads();
    {
        uint16_t pk = pack_e4m3(ob * s_rinv * 16.0f, 0.0f);
        int mt = t >> 7, r = t & 127, sw = (r >> 1) & 3;
        int c = d >> 6;
        int pos = d & 63;
        int k16 = pos >> 4;
        size_t off = ((size_t)(mt * 4 + c)) * BLOB + r * 64 + ((k16 ^ sw) << 4) + (pos & 15);
        g_oang8[off] = (unsigned char)(pk & 0xFF);
    }
}

__global__ void finalize2_kernel(float* __restrict__ out_sims, float* __restrict__ out_slots) {
    int t = blockIdx.x * blockDim.x + threadIdx.x;
    if (t >= Tc) return;
    unsigned long long b = g_best[t];
    float sim = 0.0f;
    int idx = -1;
    bool has = (b != 0ULL);
    if (has) {
        sim = dec_f((unsigned)(b >> 32)) * 0.00390625f;
        idx = (int)(0xFFFFFFFFu - (unsigned)(b & 0xFFFFFFFFu));
    }
    bool matched = has && (g_rad[t] > 0.05f) && (sim > 0.5f);
    out_sims[t]  = matched ? sim : 0.0f;
    out_slots[t] = matched ? (float)idx : -1.0f;
}

// ---------------- launcher ----------------
extern "C" void kernel_launch(void* const* d_in, const int* in_sizes, int n_in,
                              void* d_out, int out_size)
{
    const float* hidden  = (const float*)d_in[0];
    const float* beliefs = (const float*)d_in[1];
    const void*  maskp   = d_in[2];
    const float* W_obs   = (const float*)d_in[3];
    const float* W_g1    = (const float*)d_in[4];
    const float* b_g1    = (const float*)d_in[5];
    const float* W_g2    = (const float*)d_in[6];
    const float* b_g2    = (const float*)d_in[7];
    const float* W_p1    = (const float*)d_in[8];
    const float* b_p1    = (const float*)d_in[9];
    const float* W_p2    = (const float*)d_in[10];
    const float* b_p2    = (const float*)d_in[11];
    float* out = (float*)d_out;

    static cudaStream_t s2 = nullptr;
    static cudaEvent_t evF = nullptr, evJ = nullptr;
    static int attr_set = 0;
    if (!attr_set) {
        cudaFuncSetAttribute(gpobs_mma_kernel, cudaFuncAttributeMaxDynamicSharedMemorySize, DYN_SMEM);
        cudaFuncSetAttribute(sims_mma_kernel, cudaFuncAttributeMaxDynamicSharedMemorySize, SIMS_SMEM);
        cudaStreamCreateWithFlags(&s2, cudaStreamNonBlocking);
        cudaEventCreateWithFlags(&evF, cudaEventDisableTiming);
        cudaEventCreateWithFlags(&evJ, cudaEventDisableTiming);
        attr_set = 1;
    }

    const size_t base = (size_t)Tc * Dc;
    const int write_extra = (out_size >= (int)(base + 3 * Tc)) ? 1 : 0;
    float* out_obs     = out;
    float* out_sims    = out + base;
    float* out_slots   = out + base + Tc;
    float* out_meaning = out + base + 2 * Tc;

    // fork: mask/beliefs chain on s2 (DRAM-bound), overlaps tensor-bound gpobs
    cudaEventRecord(evF, 0);
    cudaStreamWaitEvent(s2, evF, 0);
    zero_flags_kernel<<<1, 1, 0, s2>>>();
    detect_mask_kernel<<<Nc / 256, 256, 0, s2>>>((const unsigned char*)maskp);
    convert_mask_kernel<<<Nc / 256, 256, 0, s2>>>(maskp);
    binv_kernel<<<Nc / 8, 256, 0, s2>>>(beliefs);
    prep_beliefs_kernel<<<(Nc * 4) / 256, 256, 0, s2>>>(beliefs);

    // stream 0: main chain
    init_best_kernel<<<Tc / 256, 256>>>(b_g1, b_p1, W_g2, W_p2);
    prep_hidden_kernel<<<(Tc * 64) / 256, 256>>>(hidden);
    prep_weights_kernel<<<(1280 * 64) / 256, 256>>>(W_g1, W_p1, W_obs);
    gpobs_mma_kernel<<<dim3(9, MGP / 128), 256, DYN_SMEM>>>();
    finalize1_kernel<<<Tc, 256>>>(b_g2, b_p2, out_obs, out_meaning, write_extra);

    // join before sims (needs prep_beliefs from s2)
    cudaEventRecord(evJ, s2);
    cudaStreamWaitEvent(0, evJ, 0);
    sims_mma_kernel<<<dim3(32, 32), 256, SIMS_SMEM>>>();
    if (write_extra) {
        finalize2_kernel<<<Tc / 256, 256>>>(out_sims, out_slots);
    }
}

// round 16
// speedup vs baseline: 1.3167x; 1.2005x over previous
#include <cuda_runtime.h>
#include <cuda_fp16.h>
#include <cstdint>

#define Bc 4
#define Tc 4096
#define Hc 2048
#define Dc 256
#define Nc 32768
#define MGP (Bc*Tc)
#define EPSC 1e-8f
#define BLOB 8192            // one operand tile-chunk: 128 rows x 64B, SW64 swizzled

// ---------------- device scratch ----------------
__device__ unsigned char g_Af[(size_t)128 * 64 * BLOB];
__device__ unsigned char g_Hmhi[(size_t)32 * 64 * BLOB];
__device__ unsigned char g_Hmlo[(size_t)32 * 64 * BLOB];
__device__ unsigned char g_Wcf[(size_t)8 * 64 * BLOB];
__device__ unsigned char g_Wohi[(size_t)2 * 64 * BLOB];
__device__ unsigned char g_Wolo[(size_t)2 * 64 * BLOB];
__device__ unsigned char g_Bb8[(size_t)256 * 4 * BLOB];    // COMPACTED normalized beliefs e4m3 (x16)
__device__ unsigned char g_oang8[(size_t)32 * 4 * BLOB];
__device__ float g_bc1[1024];
__device__ float g_wc2[1024];
__device__ float g_obs_mean[(size_t)Tc * Dc];
__device__ float g_part[8 * MGP];
__device__ float g_binv[Nc];
__device__ unsigned char g_active[Nc];
__device__ unsigned long long g_best[Tc];
__device__ float g_rad[Tc];
__device__ int g_weird;
__device__ int g_off4;
// compaction
__device__ int g_lpos[Nc];
__device__ int g_bcnt[128];
__device__ int g_boff[128];
__device__ int g_nact;
__device__ int g_ngroups;
__device__ int g_origidx[Nc];

// ---------------- helpers ----------------
__device__ __forceinline__ uint32_t smem_u32(const void* p) {
    uint32_t a;
    asm("{ .reg .u64 t; cvta.to.shared.u64 t, %1; cvt.u32.u64 %0, t; }" : "=r"(a) : "l"(p));
    return a;
}
#define LDSM4(R0, R1, R2, R3, A) \
    asm volatile("ldmatrix.sync.aligned.m8n8.x4.shared.b16 {%0,%1,%2,%3}, [%4];" \
        : "=r"(R0), "=r"(R1), "=r"(R2), "=r"(R3) : "r"(A))
#define MMA_F16(D, A, B) \
    asm volatile("mma.sync.aligned.m16n8k16.row.col.f32.f16.f16.f32 " \
        "{%0,%1,%2,%3}, {%4,%5,%6,%7}, {%8,%9}, {%0,%1,%2,%3};" \
        : "+f"((D)[0]), "+f"((D)[1]), "+f"((D)[2]), "+f"((D)[3]) \
        : "r"((A)[0]), "r"((A)[1]), "r"((A)[2]), "r"((A)[3]), "r"((B)[0]), "r"((B)[1]))
#define MMA_F8(D, A, B) \
    asm volatile("mma.sync.aligned.m16n8k32.row.col.f32.e4m3.e4m3.f32 " \
        "{%0,%1,%2,%3}, {%4,%5,%6,%7}, {%8,%9}, {%0,%1,%2,%3};" \
        : "+f"((D)[0]), "+f"((D)[1]), "+f"((D)[2]), "+f"((D)[3]) \
        : "r"((A)[0]), "r"((A)[1]), "r"((A)[2]), "r"((A)[3]), "r"((B)[0]), "r"((B)[1]))
#define CPBULK(DST, SRC, BYTES, MBAR) \
    asm volatile("cp.async.bulk.shared::cta.global.mbarrier::complete_tx::bytes [%0], [%1], %2, [%3];" \
        :: "r"((uint32_t)(DST)), "l"(SRC), "r"((uint32_t)(BYTES)), "r"((uint32_t)(MBAR)) : "memory")
#define MBAR_INIT(mb, n) \
    asm volatile("mbarrier.init.shared.b64 [%0], %1;" :: "r"((uint32_t)(mb)), "r"((uint32_t)(n)) : "memory")
#define MBAR_EXPECT_TX(mb, bytes) \
    asm volatile("mbarrier.arrive.expect_tx.shared.b64 _, [%0], %1;" \
        :: "r"((uint32_t)(mb)), "r"((uint32_t)(bytes)) : "memory")
#define MBAR_WAIT(mb, ph) do { \
    uint32_t _m = (uint32_t)(mb); uint32_t _p = (uint32_t)(ph); uint32_t _d; \
    asm volatile("{\n\t.reg .pred p;\n\t" \
        "mbarrier.try_wait.parity.acquire.cta.shared::cta.b64 p, [%1], %2;\n\t" \
        "selp.b32 %0, 1, 0, p;\n\t}" : "=r"(_d) : "r"(_m), "r"(_p) : "memory"); \
    if (!_d) { \
        asm volatile("{\n\t.reg .pred P1;\n\t" \
            "WL_%=:\n\t" \
            "mbarrier.try_wait.parity.acquire.cta.shared::cta.b64 P1, [%0], %1, 0x989680;\n\t" \
            "@P1 bra.uni WD_%=;\n\t" \
            "bra.uni WL_%=;\n\t" \
            "WD_%=:\n\t}" :: "r"(_m), "r"(_p) : "memory"); \
    } } while (0)

__device__ __forceinline__ unsigned enc_f(float f) {
    unsigned u = __float_as_uint(f);
    return (u & 0x80000000u) ? ~u : (u | 0x80000000u);
}
__device__ __forceinline__ float dec_f(unsigned e) {
    unsigned u = (e & 0x80000000u) ? (e ^ 0x80000000u) : ~e;
    return __uint_as_float(u);
}
__device__ __forceinline__ float sigmoidf_(float x) { return 1.0f / (1.0f + expf(-x)); }
__device__ __forceinline__ float softplusf_(float x) {
    return fmaxf(x, 0.0f) + log1pf(expf(-fabsf(x)));
}
__device__ __forceinline__ uint16_t pack_e4m3(float lo, float hi) {
    uint16_t r;
    asm("cvt.rn.satfinite.e4m3x2.f32 %0, %1, %2;" : "=h"(r) : "f"(hi), "f"(lo));
    return r;
}
// packed f32x2 -> f16x2 (lo in low half, hi in high half)
__device__ __forceinline__ uint32_t pk_h2(float lo, float hi) {
    uint32_t r;
    asm("cvt.rn.f16x2.f32 %0, %1, %2;" : "=r"(r) : "f"(hi), "f"(lo));
    return r;
}

// ---------------- prep kernels ----------------
__global__ void prep_hidden_kernel(const float* __restrict__ hidden) {
    int idx = blockIdx.x * blockDim.x + threadIdx.x;
    int t = idx >> 6, c = idx & 63;
    const int r = t & 127;
    const int sw = (r >> 1) & 3;
    float acc[32];
    #pragma unroll
    for (int j = 0; j < 32; j++) acc[j] = 0.0f;
    #pragma unroll
    for (int b = 0; b < Bc; b++) {
        const float* src = hidden + ((size_t)(b * Tc + t)) * Hc + c * 32;
        float v[32];
        #pragma unroll
        for (int q = 0; q < 8; q++) {
            float4 f = *(const float4*)(src + q * 4);
            v[q*4+0] = f.x; v[q*4+1] = f.y; v[q*4+2] = f.z; v[q*4+3] = f.w;
        }
        #pragma unroll
        for (int j = 0; j < 32; j++) acc[j] += v[j];
        char* dst = (char*)g_Af + ((size_t)(((b * Tc + t) >> 7) * 64 + c)) * BLOB + r * 64;
        #pragma unroll
        for (int k16 = 0; k16 < 4; k16++) {
            uint4 u = make_uint4(pk_h2(v[k16*8+0], v[k16*8+1]), pk_h2(v[k16*8+2], v[k16*8+3]),
                                 pk_h2(v[k16*8+4], v[k16*8+5]), pk_h2(v[k16*8+6], v[k16*8+7]));
            *(uint4*)(dst + ((k16 ^ sw) << 4)) = u;
        }
    }
    float hi[32], lo[32];
    #pragma unroll
    for (int j = 0; j < 32; j++) {
        float m = acc[j] * 0.25f;
        float h = __half2float(__float2half_rn(m));
        hi[j] = m;
        lo[j] = m - h;
    }
    size_t boff = ((size_t)((t >> 7) * 64 + c)) * BLOB + r * 64;
    char* dh = (char*)g_Hmhi + boff;
    char* dl = (char*)g_Hmlo + boff;
    #pragma unroll
    for (int k16 = 0; k16 < 4; k16++) {
        uint4 uh = make_uint4(pk_h2(hi[k16*8+0], hi[k16*8+1]), pk_h2(hi[k16*8+2], hi[k16*8+3]),
                              pk_h2(hi[k16*8+4], hi[k16*8+5]), pk_h2(hi[k16*8+6], hi[k16*8+7]));
        uint4 ul = make_uint4(pk_h2(lo[k16*8+0], lo[k16*8+1]), pk_h2(lo[k16*8+2], lo[k16*8+3]),
                              pk_h2(lo[k16*8+4], lo[k16*8+5]), pk_h2(lo[k16*8+6], lo[k16*8+7]));
        *(uint4*)(dh + ((k16 ^ sw) << 4)) = uh;
        *(uint4*)(dl + ((k16 ^ sw) << 4)) = ul;
    }
}

__global__ void prep_weights_kernel(const float* __restrict__ Wg1, const float* __restrict__ Wp1,
                                    const float* __restrict__ Wobs) {
    int idx = blockIdx.x * blockDim.x + threadIdx.x;
    int row = idx >> 6, c = idx & 63;
    float v[32];
    const float* src;
    if (row < 512)        src = Wg1 + (size_t)row * Hc + c * 32;
    else if (row < 1024)  src = Wp1 + (size_t)(row - 512) * Hc + c * 32;
    else                  src = Wobs + (size_t)(row - 1024) * Hc + c * 32;
    #pragma unroll
    for (int q = 0; q < 8; q++) {
        float4 f = *(const float4*)(src + q * 4);
        v[q*4+0] = f.x; v[q*4+1] = f.y; v[q*4+2] = f.z; v[q*4+3] = f.w;
    }
    if (row < 1024) {
        int r = row & 127, sw = (r >> 1) & 3;
        char* dst = (char*)g_Wcf + ((size_t)((row >> 7) * 64 + c)) * BLOB + r * 64;
        #pragma unroll
        for (int k16 = 0; k16 < 4; k16++) {
            uint4 u = make_uint4(pk_h2(v[k16*8+0], v[k16*8+1]), pk_h2(v[k16*8+2], v[k16*8+3]),
                                 pk_h2(v[k16*8+4], v[k16*8+5]), pk_h2(v[k16*8+6], v[k16*8+7]));
            *(uint4*)(dst + ((k16 ^ sw) << 4)) = u;
        }
    } else {
        int r2 = row - 1024;
        int r = r2 & 127, sw = (r >> 1) & 3;
        size_t boff = ((size_t)((r2 >> 7) * 64 + c)) * BLOB + r * 64;
        char* dh = (char*)g_Wohi + boff;
        char* dl = (char*)g_Wolo + boff;
        float hi[32], lo[32];
        #pragma unroll
        for (int j = 0; j < 32; j++) {
            float h = __half2float(__float2half_rn(v[j]));
            hi[j] = v[j];
            lo[j] = v[j] - h;
        }
        #pragma unroll
        for (int k16 = 0; k16 < 4; k16++) {
            uint4 uh = make_uint4(pk_h2(hi[k16*8+0], hi[k16*8+1]), pk_h2(hi[k16*8+2], hi[k16*8+3]),
                                  pk_h2(hi[k16*8+4], hi[k16*8+5]), pk_h2(hi[k16*8+6], hi[k16*8+7]));
            uint4 ul = make_uint4(pk_h2(lo[k16*8+0], lo[k16*8+1]), pk_h2(lo[k16*8+2], lo[k16*8+3]),
                                  pk_h2(lo[k16*8+4], lo[k16*8+5]), pk_h2(lo[k16*8+6], lo[k16*8+7]));
            *(uint4*)(dh + ((k16 ^ sw) << 4)) = uh;
            *(uint4*)(dl + ((k16 ^ sw) << 4)) = ul;
        }
    }
}

// init: zero best array + fill small vectors
__global__ void init_best_kernel(const float* __restrict__ bg1, const float* __restrict__ bp1,
                                 const float* __restrict__ Wg2, const float* __restrict__ Wp2) {
    int i = blockIdx.x * blockDim.x + threadIdx.x;
    if (i < Tc) g_best[i] = 0ULL;
    if (i < 1024) {
        g_bc1[i] = (i < 512) ? bg1[i] : bp1[i - 512];
        g_wc2[i] = (i < 512) ? Wg2[i] : Wp2[i - 512];
    }
}

__global__ void zero_flags_kernel() {
    g_weird = 0;
    g_off4 = 0;
}

__global__ void detect_mask_kernel(const unsigned char* __restrict__ m) {
    int i = blockIdx.x * blockDim.x + threadIdx.x;
    unsigned char c = m[i];
    int w = 0, o = 0;
    if (c > 1) w = 1;
    if (c != 0 && (i & 3)) o = 1;
    w = __reduce_or_sync(0xffffffffu, w);
    o = __reduce_or_sync(0xffffffffu, o);
    if ((threadIdx.x & 31) == 0) {
        if (w) atomicOr(&g_weird, 1);
        if (o) atomicOr(&g_off4, 1);
    }
}
__global__ void convert_mask_kernel(const void* __restrict__ m) {
    int i = blockIdx.x * blockDim.x + threadIdx.x;
    if (i >= Nc) return;
    int fmt = g_weird ? 2 : (g_off4 ? 1 : 0);
    unsigned char a;
    if (fmt == 0)      a = (((const int*)m)[i] != 0);
    else if (fmt == 1) a = (((const unsigned char*)m)[i] != 0);
    else               a = (((const float*)m)[i] != 0.0f);
    g_active[i] = a;
}

// stable block-level scan of active flags: local exclusive prefix + block counts
__global__ void scan1_kernel() {
    __shared__ int sdata[256];
    int n = blockIdx.x * 256 + threadIdx.x;
    int a = g_active[n];
    sdata[threadIdx.x] = a;
    __syncthreads();
    for (int off = 1; off < 256; off <<= 1) {
        int v = (threadIdx.x >= off) ? sdata[threadIdx.x - off] : 0;
        __syncthreads();
        sdata[threadIdx.x] += v;
        __syncthreads();
    }
    g_lpos[n] = sdata[threadIdx.x] - a;
    if (threadIdx.x == 255) g_bcnt[blockIdx.x] = sdata[255];
}

// scan block counts -> exclusive offsets + totals
__global__ void scan2_kernel() {
    __shared__ int sdata[128];
    int i = threadIdx.x;
    int cnt = g_bcnt[i];
    sdata[i] = cnt;
    __syncthreads();
    for (int off = 1; off < 128; off <<= 1) {
        int v = (i >= off) ? sdata[i - off] : 0;
        __syncthreads();
        sdata[i] += v;
        __syncthreads();
    }
    g_boff[i] = sdata[i] - cnt;
    if (i == 127) {
        g_nact = sdata[127];
        g_ngroups = (sdata[127] + 1023) >> 10;
    }
}

// write original index per compacted slot
__global__ void posmap_kernel() {
    int n = blockIdx.x * 256 + threadIdx.x;
    if (g_active[n]) g_origidx[g_boff[n >> 8] + g_lpos[n]] = n;
}

__global__ void binv_kernel(const float* __restrict__ beliefs) {
    int row = blockIdx.x * 8 + (threadIdx.x >> 5);
    int lane = threadIdx.x & 31;
    const float4* p = reinterpret_cast<const float4*>(beliefs + (size_t)row * Dc);
    float s = 0.0f;
    #pragma unroll
    for (int r = 0; r < 2; r++) {
        float4 v = p[lane + r * 32];
        s += v.x * v.x + v.y * v.y + v.z * v.z + v.w * v.w;
    }
    #pragma unroll
    for (int o = 16; o > 0; o >>= 1) s += __shfl_down_sync(0xffffffffu, s, o);
    if (lane == 0)
        g_binv[row] = 16.0f / fmaxf(sqrtf(s), EPSC);
}

// write compacted normalized beliefs; zero-pad last partial group
__global__ void prep_beliefs_kernel(const float* __restrict__ beliefs) {
    int idx = blockIdx.x * blockDim.x + threadIdx.x;   // Nc*4
    int s = idx >> 2, c = idx & 3;
    const int nact = g_nact;
    const int lim = g_ngroups << 10;
    if (s >= lim) return;
    int r = s & 127, sw = (r >> 1) & 3;
    char* dst = (char*)g_Bb8 + ((size_t)((s >> 7) * 4 + c)) * BLOB + r * 64;
    if (s < nact) {
        int n = g_origidx[s];
        float bi = g_binv[n];
        const float* src = beliefs + (size_t)n * Dc + c * 64;
        #pragma unroll
        for (int k16 = 0; k16 < 4; k16++) {
            uint32_t w[4];
            #pragma unroll
            for (int q = 0; q < 4; q++) {
                float4 f = *(const float4*)(src + k16 * 16 + q * 4);
                uint16_t a = pack_e4m3(f.x * bi, f.y * bi);
                uint16_t b = pack_e4m3(f.z * bi, f.w * bi);
                w[q] = ((uint32_t)b << 16) | a;
            }
            *(uint4*)(dst + ((k16 ^ sw) << 4)) = make_uint4(w[0], w[1], w[2], w[3]);
        }
    } else {
        uint4 z = make_uint4(0, 0, 0, 0);
        *(uint4*)(dst)      = z;
        *(uint4*)(dst + 16) = z;
        *(uint4*)(dst + 32) = z;
        *(uint4*)(dst + 48) = z;
    }
}

// ============ merged gate/prec + obs GEMM kernel ============
#define GP_STAGE2 32768
#define OB_STAGE 32768
#define DYN_SMEM 98304

__global__ __launch_bounds__(256, 2) void gpobs_mma_kernel() {
    extern __shared__ __align__(128) char dsm[];
    __shared__ float s_b1[128], s_w2[128], s_red[128];
    __shared__ __align__(8) unsigned long long s_mbar[4];

    const int tid = threadIdx.x, lane = tid & 31, wid = tid >> 5;
    const int warp_m = (wid >> 1) * 32;
    const int warp_n = (wid & 1) * 64;
    const uint32_t sbase = smem_u32(dsm);
    const uint32_t mb = smem_u32(s_mbar);

    const int rowA = warp_m + (lane & 15);
    const uint32_t cA = (uint32_t)(lane >> 4);
    const uint32_t swA = (uint32_t)((rowA >> 1) & 3);
    const uint32_t aoff = (uint32_t)rowA * 64;
    const int rowB = warp_n + ((lane >> 4) << 3) + (lane & 7);
    const uint32_t cB = (uint32_t)((lane >> 3) & 1);
    const uint32_t swB = (uint32_t)((rowB >> 1) & 3);
    const uint32_t boff = (uint32_t)rowB * 64;

    float acc[2][8][4];
    #pragma unroll
    for (int i = 0; i < 2; i++)
        #pragma unroll
        for (int j = 0; j < 8; j++)
            #pragma unroll
            for (int k = 0; k < 4; k++) acc[i][j][k] = 0.0f;

    const int qr = lane >> 2;
    const int qc = (lane & 3) * 2;

    if (blockIdx.x < 8) {
        const int nt = blockIdx.x;
        const int mt = blockIdx.y;
        const int m0 = mt * 128, nbase = nt * 128;
        if (tid < 128) {
            s_b1[tid] = g_bc1[nbase + tid];
            s_w2[tid] = g_wc2[nbase + tid];
            s_red[tid] = 0.0f;
        }
        const char* gA = (const char*)g_Af + (size_t)mt * 64 * BLOB;
        const char* gB = (const char*)g_Wcf + (size_t)nt * 64 * BLOB;

        if (tid == 0) {
            #pragma unroll
            for (int s = 0; s < 3; s++) MBAR_INIT(mb + s * 8, 1);
        }
        __syncthreads();
        if (tid == 0) {
            #pragma unroll
            for (int c = 0; c < 2; c++) {
                const uint32_t st = sbase + c * GP_STAGE2;
                MBAR_EXPECT_TX(mb + c * 8, GP_STAGE2);
                CPBULK(st,         gA + (size_t)(2*c)     * BLOB, BLOB, mb + c * 8);
                CPBULK(st + 8192,  gA + (size_t)(2*c + 1) * BLOB, BLOB, mb + c * 8);
                CPBULK(st + 16384, gB + (size_t)(2*c)     * BLOB, BLOB, mb + c * 8);
                CPBULK(st + 24576, gB + (size_t)(2*c + 1) * BLOB, BLOB, mb + c * 8);
            }
        }

        for (int c = 0; c < 32; c++) {
            MBAR_WAIT(mb + (c % 3) * 8, (c / 3) & 1);
            __syncthreads();
            if (tid == 0 && c + 2 < 32) {
                const int s = (c + 2) % 3;
                const uint32_t st = sbase + s * GP_STAGE2;
                MBAR_EXPECT_TX(mb + s * 8, GP_STAGE2);
                CPBULK(st,         gA + (size_t)(2*(c+2))     * BLOB, BLOB, mb + s * 8);
                CPBULK(st + 8192,  gA + (size_t)(2*(c+2) + 1) * BLOB, BLOB, mb + s * 8);
                CPBULK(st + 16384, gB + (size_t)(2*(c+2))     * BLOB, BLOB, mb + s * 8);
                CPBULK(st + 24576, gB + (size_t)(2*(c+2) + 1) * BLOB, BLOB, mb + s * 8);
            }
            const uint32_t uS = sbase + (c % 3) * GP_STAGE2;
            #pragma unroll
            for (int h = 0; h < 2; h++) {
                const uint32_t uA = uS + (uint32_t)h * 8192;
                const uint32_t uB = uS + 16384 + (uint32_t)h * 8192;
                #pragma unroll
                for (int ks = 0; ks < 2; ks++) {
                    const uint32_t oa = ((cA | (ks << 1)) ^ swA) << 4;
                    const uint32_t ob = ((cB | (ks << 1)) ^ swB) << 4;
                    uint32_t a[2][4];
                    LDSM4(a[0][0], a[0][1], a[0][2], a[0][3], uA + aoff + oa);
                    LDSM4(a[1][0], a[1][1], a[1][2], a[1][3], uA + aoff + 1024 + oa);
                    uint32_t b[8][2];
                    #pragma unroll
                    for (int jp = 0; jp < 4; jp++) {
                        LDSM4(b[2*jp][0], b[2*jp][1], b[2*jp+1][0], b[2*jp+1][1],
                              uB + boff + (uint32_t)jp * 1024 + ob);
                    }
                    #pragma unroll
                    for (int mt2 = 0; mt2 < 2; mt2++)
                        #pragma unroll
                        for (int nj = 0; nj < 8; nj++)
                            MMA_F16(acc[mt2][nj], a[mt2], b[nj]);
                }
            }
        }
        __syncthreads();

        #pragma unroll
        for (int mt2 = 0; mt2 < 2; mt2++) {
            float p0 = 0.0f, p1 = 0.0f;
            #pragma unroll
            for (int nj = 0; nj < 8; nj++) {
                int col = warp_n + nj * 8 + qc;
                p0 += fmaxf(acc[mt2][nj][0] + s_b1[col], 0.0f) * s_w2[col]
                    + fmaxf(acc[mt2][nj][1] + s_b1[col + 1], 0.0f) * s_w2[col + 1];
                p1 += fmaxf(acc[mt2][nj][2] + s_b1[col], 0.0f) * s_w2[col]
                    + fmaxf(acc[mt2][nj][3] + s_b1[col + 1], 0.0f) * s_w2[col + 1];
            }
            p0 += __shfl_xor_sync(0xffffffffu, p0, 1);
            p0 += __shfl_xor_sync(0xffffffffu, p0, 2);
            p1 += __shfl_xor_sync(0xffffffffu, p1, 1);
            p1 += __shfl_xor_sync(0xffffffffu, p1, 2);
            if ((lane & 3) == 0) {
                atomicAdd(&s_red[warp_m + mt2 * 16 + qr], p0);
                atomicAdd(&s_red[warp_m + mt2 * 16 + 8 + qr], p1);
            }
        }
        __syncthreads();
        if (tid < 128) g_part[nt * MGP + m0 + tid] = s_red[tid];
    } else {
        const int id = blockIdx.y;
        if (id >= 64) return;
        const int nt = id & 1;
        const int mt = id >> 1;
        const int m0 = mt * 128, nbase = nt * 128;
        const char* gAh = (const char*)g_Hmhi + (size_t)mt * 64 * BLOB;
        const char* gAl = (const char*)g_Hmlo + (size_t)mt * 64 * BLOB;
        const char* gBh = (const char*)g_Wohi + (size_t)nt * 64 * BLOB;
        const char* gBl = (const char*)g_Wolo + (size_t)nt * 64 * BLOB;

        if (tid == 0) {
            MBAR_INIT(mb, 1);
            MBAR_INIT(mb + 8, 1);
        }
        __syncthreads();
        if (tid == 0) {
            MBAR_EXPECT_TX(mb, OB_STAGE);
            CPBULK(sbase,         gAh, BLOB, mb);
            CPBULK(sbase + 8192,  gAl, BLOB, mb);
            CPBULK(sbase + 16384, gBh, BLOB, mb);
            CPBULK(sbase + 24576, gBl, BLOB, mb);
        }

        for (int c = 0; c < 64; c++) {
            MBAR_WAIT(mb + (c & 1) * 8, (c >> 1) & 1);
            __syncthreads();
            if (tid == 0 && c + 1 < 64) {
                const int s = (c + 1) & 1;
                const uint32_t st = sbase + s * OB_STAGE;
                MBAR_EXPECT_TX(mb + s * 8, OB_STAGE);
                CPBULK(st,         gAh + (size_t)(c + 1) * BLOB, BLOB, mb + s * 8);
                CPBULK(st + 8192,  gAl + (size_t)(c + 1) * BLOB, BLOB, mb + s * 8);
                CPBULK(st + 16384, gBh + (size_t)(c + 1) * BLOB, BLOB, mb + s * 8);
                CPBULK(st + 24576, gBl + (size_t)(c + 1) * BLOB, BLOB, mb + s * 8);
            }
            const uint32_t uS = sbase + (c & 1) * OB_STAGE;
            #pragma unroll
            for (int tr = 0; tr < 3; tr++) {
                const uint32_t uA = uS + (tr == 2 ? 8192u : 0u);
                const uint32_t uB = uS + 16384u + (tr == 1 ? 8192u : 0u);
                #pragma unroll
                for (int ks = 0; ks < 2; ks++) {
                    const uint32_t oa = ((cA | (ks << 1)) ^ swA) << 4;
                    const uint32_t ob = ((cB | (ks << 1)) ^ swB) << 4;
                    uint32_t a[2][4];
                    LDSM4(a[0][0], a[0][1], a[0][2], a[0][3], uA + aoff + oa);
                    LDSM4(a[1][0], a[1][1], a[1][2], a[1][3], uA + aoff + 1024 + oa);
                    uint32_t b[8][2];
                    #pragma unroll
                    for (int jp = 0; jp < 4; jp++) {
                        LDSM4(b[2*jp][0], b[2*jp][1], b[2*jp+1][0], b[2*jp+1][1],
                              uB + boff + (uint32_t)jp * 1024 + ob);
                    }
                    #pragma unroll
                    for (int mt2 = 0; mt2 < 2; mt2++)
                        #pragma unroll
                        for (int nj = 0; nj < 8; nj++)
                            MMA_F16(acc[mt2][nj], a[mt2], b[nj]);
                }
            }
        }

        #pragma unroll
        for (int mt2 = 0; mt2 < 2; mt2++)
            #pragma unroll
            for (int nj = 0; nj < 8; nj++) {
                int row = m0 + warp_m + mt2 * 16 + qr;
                int col = nbase + warp_n + nj * 8 + qc;
                *(float2*)(g_obs_mean + (size_t)row * Dc + col) = make_float2(acc[mt2][nj][0], acc[mt2][nj][1]);
                *(float2*)(g_obs_mean + (size_t)(row + 8) * Dc + col) = make_float2(acc[mt2][nj][2], acc[mt2][nj][3]);
            }
    }
}

// ============ sims GEMM: compacted B, 16KB stages, float/idx fold ============
#define SIMS_B_OFF 32768
#define SIMS_STG 16384
#define SIMS_SMEM 98304
__global__ __launch_bounds__(256, 2) void sims_mma_kernel() {
    extern __shared__ __align__(128) char dsm[];
    __shared__ __align__(8) unsigned long long s_mbar[5];

    const int ng = blockIdx.x;
    if (ng >= g_ngroups) return;
    const int tid = threadIdx.x, lane = tid & 31, wid = tid >> 5;
    const int mt = blockIdx.y;
    const int n_base = ng * 1024, m0 = mt * 128;
    const int warp_m = (wid >> 1) * 32;
    const int warp_n = (wid & 1) * 64;
    const uint32_t sbase = smem_u32(dsm);
    const uint32_t mb = smem_u32(s_mbar);

    const int rowA = warp_m + (lane & 15);
    const uint32_t cA = (uint32_t)(lane >> 4);
    const uint32_t swA = (uint32_t)((rowA >> 1) & 3);
    const uint32_t aoff = (uint32_t)rowA * 64;
    const int rowB = warp_n + ((lane >> 4) << 3) + (lane & 7);
    const uint32_t cB = (uint32_t)((lane >> 3) & 1);
    const uint32_t swB = (uint32_t)((rowB >> 1) & 3);
    const uint32_t boff = (uint32_t)rowB * 64;

    const char* gA = (const char*)g_oang8 + (size_t)mt * 4 * BLOB;
    const char* gB = (const char*)g_Bb8 + (size_t)ng * 32 * BLOB;

    const int qr = lane >> 2;
    const int qc = (lane & 3) * 2;

    if (tid == 0) {
        #pragma unroll
        for (int s = 0; s < 5; s++) MBAR_INIT(mb + s * 8, 1);
    }
    __syncthreads();
    if (tid == 0) {
        MBAR_EXPECT_TX(mb + 32, 4 * BLOB);
        #pragma unroll
        for (int c = 0; c < 4; c++)
            CPBULK(sbase + c * BLOB, gA + (size_t)c * BLOB, BLOB, mb + 32);
        #pragma unroll
        for (int j = 0; j < 3; j++) {
            MBAR_EXPECT_TX(mb + j * 8, SIMS_STG);
            CPBULK(sbase + SIMS_B_OFF + j * SIMS_STG,        gB + (size_t)(2*j)     * BLOB, BLOB, mb + j * 8);
            CPBULK(sbase + SIMS_B_OFF + j * SIMS_STG + BLOB, gB + (size_t)(2*j + 1) * BLOB, BLOB, mb + j * 8);
        }
    }
    MBAR_WAIT(mb + 32, 0);

    float bv[4];
    int bidx[4];
    #pragma unroll
    for (int i = 0; i < 4; i++) { bv[i] = -3.0e38f; bidx[i] = 0; }
    float acc[2][8][4];

    for (int jj = 0; jj < 16; jj++) {
        const int half = jj & 1;
        const int g = jj >> 1;
        if (half == 0) {
            #pragma unroll
            for (int i = 0; i < 2; i++)
                #pragma unroll
                for (int j2 = 0; j2 < 8; j2++)
                    #pragma unroll
                    for (int k = 0; k < 4; k++) acc[i][j2][k] = 0.0f;
        }
        MBAR_WAIT(mb + (jj & 3) * 8, (jj >> 2) & 1);
        __syncthreads();
        if (tid == 0 && jj + 3 < 16) {
            const int s = (jj + 3) & 3;
            const uint32_t st = sbase + SIMS_B_OFF + s * SIMS_STG;
            MBAR_EXPECT_TX(mb + s * 8, SIMS_STG);
            CPBULK(st,        gB + (size_t)(2*(jj+3))     * BLOB, BLOB, mb + s * 8);
            CPBULK(st + BLOB, gB + (size_t)(2*(jj+3) + 1) * BLOB, BLOB, mb + s * 8);
        }
        const uint32_t uBs = sbase + SIMS_B_OFF + (uint32_t)(jj & 3) * SIMS_STG;
        #pragma unroll
        for (int h = 0; h < 2; h++) {
            const uint32_t uA = sbase + (uint32_t)(2 * half + h) * BLOB;
            const uint32_t uB = uBs + (uint32_t)h * BLOB;
            #pragma unroll
            for (int ks = 0; ks < 2; ks++) {
                const uint32_t oa = ((cA | (ks << 1)) ^ swA) << 4;
                const uint32_t ob = ((cB | (ks << 1)) ^ swB) << 4;
                uint32_t a[2][4];
                LDSM4(a[0][0], a[0][1], a[0][2], a[0][3], uA + aoff + oa);
                LDSM4(a[1][0], a[1][1], a[1][2], a[1][3], uA + aoff + 1024 + oa);
                uint32_t b[8][2];
                #pragma unroll
                for (int jp = 0; jp < 4; jp++) {
                    LDSM4(b[2*jp][0], b[2*jp][1], b[2*jp+1][0], b[2*jp+1][1],
                          uB + boff + (uint32_t)jp * 1024 + ob);
                }
                #pragma unroll
                for (int mt2 = 0; mt2 < 2; mt2++)
                    #pragma unroll
                    for (int nj = 0; nj < 8; nj++)
                        MMA_F8(acc[mt2][nj], a[mt2], b[nj]);
            }
        }
        if (half == 1) {
            const int ib = n_base + g * 128 + warp_n + qc;
            #pragma unroll
            for (int mt2 = 0; mt2 < 2; mt2++) {
                float v0 = bv[mt2 * 2], v1 = bv[mt2 * 2 + 1];
                int i0 = bidx[mt2 * 2], i1 = bidx[mt2 * 2 + 1];
                #pragma unroll
                for (int nj = 0; nj < 8; nj++) {
                    #pragma unroll
                    for (int p = 0; p < 2; p++) {
                        const int ix = ib + nj * 8 + p;
                        float x0 = acc[mt2][nj][p];
                        if (x0 > v0) { v0 = x0; i0 = ix; }
                        float x1 = acc[mt2][nj][2 + p];
                        if (x1 > v1) { v1 = x1; i1 = ix; }
                    }
                }
                bv[mt2 * 2] = v0;  bidx[mt2 * 2] = i0;
                bv[mt2 * 2 + 1] = v1; bidx[mt2 * 2 + 1] = i1;
            }
        }
    }

    #pragma unroll
    for (int h = 0; h < 4; h++) {
        float v = bv[h];
        int i = bidx[h];
        #pragma unroll
        for (int off = 1; off <= 2; off <<= 1) {
            float v2 = __shfl_xor_sync(0xffffffffu, v, off);
            int i2 = __shfl_xor_sync(0xffffffffu, i, off);
            if (v2 > v || (v2 == v && i2 < i)) { v = v2; i = i2; }
        }
        if ((lane & 3) == 0) {
            const int mt2 = h >> 1;
            const int row = m0 + warp_m + mt2 * 16 + ((h & 1) ? 8 : 0) + qr;
            unsigned long long q = ((unsigned long long)enc_f(v) << 32)
                                 | (0xFFFFFFFFu - (unsigned)i);
            atomicMax(&g_best[row], q);
        }
    }
}

// ---------------- finalize ----------------
__global__ __launch_bounds__(256) void finalize1_kernel(
    const float* __restrict__ bg2, const float* __restrict__ bp2,
    float* __restrict__ out_obs, float* __restrict__ out_meaning, int write_extra)
{
    __shared__ float sred[256];
    __shared__ float s_pm, s_inv, s_rinv;
    int t = blockIdx.x;
    int d = threadIdx.x;
    float v = g_obs_mean[(size_t)t * Dc + d];

    sred[d] = v * v;
    __syncthreads();
    for (int s = 128; s > 0; s >>= 1) {
        if (d < s) sred[d] += sred[d + s];
        __syncthreads();
    }
    if (d == 0) {
        float pm = 0.0f;
        float bg2v = bg2[0], bp2v = bp2[0];
        #pragma unroll
        for (int b = 0; b < Bc; b++) {
            int row = b * Tc + t;
            float gl = bg2v, pl = bp2v;
            #pragma unroll
            for (int jt = 0; jt < 4; jt++) gl += g_part[jt * MGP + row];
            #pragma unroll
            for (int jt = 4; jt < 8; jt++) pl += g_part[jt * MGP + row];
            pm += sigmoidf_(gl) * softplusf_(pl);
        }
        pm *= 0.25f;
        s_pm = pm;
        s_inv = 1.0f / fmaxf(sqrtf(sred[0]), EPSC);
    }
    __syncthreads();
    float ob = v * s_inv * s_pm;
    out_obs[(size_t)t * Dc + d] = ob;

    __syncthreads();
    sred[d] = ob * ob;
    __syncthreads();
    for (int s = 128; s > 0; s >>= 1) {
        if (d < s) sred[d] += sred[d + s];
        __syncthreads();
    }
    if (d == 0) {
        float rr = sqrtf(sred[0]);
        g_rad[t] = rr;
        s_rinv = 1.0f / fmaxf(rr, EPSC);
        if (write_extra) out_meaning[t] = (rr > 0.05f) ? 1.0f : 0.0f;
    }
    __syncthreads();
    {
        uint16_t pk = pack_e4m3(ob * s_rinv * 16.0f, 0.0f);
        int mt = t >> 7, r = t & 127, sw = (r >> 1) & 3;
        int c = d >> 6;
        int pos = d & 63;
        int k16 = pos >> 4;
        size_t off = ((size_t)(mt * 4 + c)) * BLOB + r * 64 + ((k16 ^ sw) << 4) + (pos & 15);
        g_oang8[off] = (unsigned char)(pk & 0xFF);
    }
}

__global__ void finalize2_kernel(float* __restrict__ out_sims, float* __restrict__ out_slots) {
    int t = blockIdx.x * blockDim.x + threadIdx.x;
    if (t >= Tc) return;
    unsigned long long b = g_best[t];
    float sim = 0.0f;
    int idx = -1;
    bool has = (b != 0ULL);
    if (has) {
        sim = dec_f((unsigned)(b >> 32)) * 0.00390625f;
        unsigned slot = 0xFFFFFFFFu - (unsigned)(b & 0xFFFFFFFFu);
        idx = g_origidx[slot & (Nc - 1)];
    }
    bool matched = has && (g_rad[t] > 0.05f) && (sim > 0.5f);
    out_sims[t]  = matched ? sim : 0.0f;
    out_slots[t] = matched ? (float)idx : -1.0f;
}

// ---------------- launcher ----------------
extern "C" void kernel_launch(void* const* d_in, const int* in_sizes, int n_in,
                              void* d_out, int out_size)
{
    const float* hidden  = (const float*)d_in[0];
    const float* beliefs = (const float*)d_in[1];
    const void*  maskp   = d_in[2];
    const float* W_obs   = (const float*)d_in[3];
    const float* W_g1    = (const float*)d_in[4];
    const float* b_g1    = (const float*)d_in[5];
    const float* W_g2    = (const float*)d_in[6];
    const float* b_g2    = (const float*)d_in[7];
    const float* W_p1    = (const float*)d_in[8];
    const float* b_p1    = (const float*)d_in[9];
    const float* W_p2    = (const float*)d_in[10];
    const float* b_p2    = (const float*)d_in[11];
    float* out = (float*)d_out;

    static cudaStream_t s2 = nullptr;
    static cudaEvent_t evF = nullptr, evJ = nullptr;
    static int attr_set = 0;
    if (!attr_set) {
        cudaFuncSetAttribute(gpobs_mma_kernel, cudaFuncAttributeMaxDynamicSharedMemorySize, DYN_SMEM);
        cudaFuncSetAttribute(sims_mma_kernel, cudaFuncAttributeMaxDynamicSharedMemorySize, SIMS_SMEM);
        cudaStreamCreateWithFlags(&s2, cudaStreamNonBlocking);
        cudaEventCreateWithFlags(&evF, cudaEventDisableTiming);
        cudaEventCreateWithFlags(&evJ, cudaEventDisableTiming);
        attr_set = 1;
    }

    const size_t base = (size_t)Tc * Dc;
    const int write_extra = (out_size >= (int)(base + 3 * Tc)) ? 1 : 0;
    float* out_obs     = out;
    float* out_sims    = out + base;
    float* out_slots   = out + base + Tc;
    float* out_meaning = out + base + 2 * Tc;

    // stream 0: heavy preps first
    init_best_kernel<<<Tc / 256, 256>>>(b_g1, b_p1, W_g2, W_p2);
    prep_hidden_kernel<<<(Tc * 64) / 256, 256>>>(hidden);
    prep_weights_kernel<<<(1280 * 64) / 256, 256>>>(W_g1, W_p1, W_obs);

    // fork s2 AFTER the DRAM-heavy preps: its DRAM-bound chain overlaps tensor-bound gpobs
    cudaEventRecord(evF, 0);
    cudaStreamWaitEvent(s2, evF, 0);
    zero_flags_kernel<<<1, 1, 0, s2>>>();
    detect_mask_kernel<<<Nc / 256, 256, 0, s2>>>((const unsigned char*)maskp);
    convert_mask_kernel<<<Nc / 256, 256, 0, s2>>>(maskp);
    scan1_kernel<<<128, 256, 0, s2>>>();
    scan2_kernel<<<1, 128, 0, s2>>>();
    posmap_kernel<<<128, 256, 0, s2>>>();
    binv_kernel<<<Nc / 8, 256, 0, s2>>>(beliefs);
    prep_beliefs_kernel<<<(Nc * 4) / 256, 256, 0, s2>>>(beliefs);

    gpobs_mma_kernel<<<dim3(9, MGP / 128), 256, DYN_SMEM>>>();
    finalize1_kernel<<<Tc, 256>>>(b_g2, b_p2, out_obs, out_meaning, write_extra);

    // join before sims (needs compacted beliefs + counts from s2)
    cudaEventRecord(evJ, s2);
    cudaStreamWaitEvent(0, evJ, 0);
    sims_mma_kernel<<<dim3(32, 32), 256, SIMS_SMEM>>>();
    if (write_extra) {
        finalize2_kernel<<<Tc / 256, 256>>>(out_sims, out_slots);
    }
}

// round 17
// speedup vs baseline: 1.4627x; 1.1109x over previous
#include <cuda_runtime.h>
#include <cuda_fp16.h>
#include <cstdint>

#define Bc 4
#define Tc 4096
#define Hc 2048
#define Dc 256
#define Nc 32768
#define MGP (Bc*Tc)
#define EPSC 1e-8f
#define BLOB 8192            // one operand tile-chunk: 128 rows x 64B, SW64 swizzled

// ---------------- device scratch ----------------
__device__ unsigned char g_Af[(size_t)128 * 64 * BLOB];
__device__ unsigned char g_Hmhi[(size_t)32 * 64 * BLOB];
__device__ unsigned char g_Hmlo[(size_t)32 * 64 * BLOB];
__device__ unsigned char g_Wcf[(size_t)8 * 64 * BLOB];
__device__ unsigned char g_Wohi[(size_t)2 * 64 * BLOB];
__device__ unsigned char g_Wolo[(size_t)2 * 64 * BLOB];
__device__ unsigned char g_Bb8[(size_t)256 * 4 * BLOB];    // COMPACTED normalized beliefs e4m3 (x16)
__device__ unsigned char g_oang8[(size_t)32 * 4 * BLOB];
__device__ float g_bc1[1024];
__device__ float g_wc2[1024];
__device__ float g_obs_mean[(size_t)Tc * Dc];
__device__ float g_part[8 * MGP];
__device__ float g_binv[Nc];
__device__ unsigned char g_active[Nc];
__device__ unsigned long long g_best[Tc];
__device__ float g_rad[Tc];
__device__ int g_weird;
__device__ int g_off4;
// compaction
__device__ int g_lpos[Nc];
__device__ int g_bcnt[128];
__device__ int g_boff[128];
__device__ int g_nact;
__device__ int g_ngroups;
__device__ int g_origidx[Nc];

// ---------------- helpers ----------------
__device__ __forceinline__ uint32_t smem_u32(const void* p) {
    uint32_t a;
    asm("{ .reg .u64 t; cvta.to.shared.u64 t, %1; cvt.u32.u64 %0, t; }" : "=r"(a) : "l"(p));
    return a;
}
#define LDSM4(R0, R1, R2, R3, A) \
    asm volatile("ldmatrix.sync.aligned.m8n8.x4.shared.b16 {%0,%1,%2,%3}, [%4];" \
        : "=r"(R0), "=r"(R1), "=r"(R2), "=r"(R3) : "r"(A))
#define MMA_F16(D, A, B) \
    asm volatile("mma.sync.aligned.m16n8k16.row.col.f32.f16.f16.f32 " \
        "{%0,%1,%2,%3}, {%4,%5,%6,%7}, {%8,%9}, {%0,%1,%2,%3};" \
        : "+f"((D)[0]), "+f"((D)[1]), "+f"((D)[2]), "+f"((D)[3]) \
        : "r"((A)[0]), "r"((A)[1]), "r"((A)[2]), "r"((A)[3]), "r"((B)[0]), "r"((B)[1]))
#define MMA_F8(D, A, B) \
    asm volatile("mma.sync.aligned.m16n8k32.row.col.f32.e4m3.e4m3.f32 " \
        "{%0,%1,%2,%3}, {%4,%5,%6,%7}, {%8,%9}, {%0,%1,%2,%3};" \
        : "+f"((D)[0]), "+f"((D)[1]), "+f"((D)[2]), "+f"((D)[3]) \
        : "r"((A)[0]), "r"((A)[1]), "r"((A)[2]), "r"((A)[3]), "r"((B)[0]), "r"((B)[1]))
#define CPBULK(DST, SRC, BYTES, MBAR) \
    asm volatile("cp.async.bulk.shared::cta.global.mbarrier::complete_tx::bytes [%0], [%1], %2, [%3];" \
        :: "r"((uint32_t)(DST)), "l"(SRC), "r"((uint32_t)(BYTES)), "r"((uint32_t)(MBAR)) : "memory")
#define MBAR_INIT(mb, n) \
    asm volatile("mbarrier.init.shared.b64 [%0], %1;" :: "r"((uint32_t)(mb)), "r"((uint32_t)(n)) : "memory")
#define MBAR_EXPECT_TX(mb, bytes) \
    asm volatile("mbarrier.arrive.expect_tx.shared.b64 _, [%0], %1;" \
        :: "r"((uint32_t)(mb)), "r"((uint32_t)(bytes)) : "memory")
#define MBAR_WAIT(mb, ph) do { \
    uint32_t _m = (uint32_t)(mb); uint32_t _p = (uint32_t)(ph); uint32_t _d; \
    asm volatile("{\n\t.reg .pred p;\n\t" \
        "mbarrier.try_wait.parity.acquire.cta.shared::cta.b64 p, [%1], %2;\n\t" \
        "selp.b32 %0, 1, 0, p;\n\t}" : "=r"(_d) : "r"(_m), "r"(_p) : "memory"); \
    if (!_d) { \
        asm volatile("{\n\t.reg .pred P1;\n\t" \
            "WL_%=:\n\t" \
            "mbarrier.try_wait.parity.acquire.cta.shared::cta.b64 P1, [%0], %1, 0x989680;\n\t" \
            "@P1 bra.uni WD_%=;\n\t" \
            "bra.uni WL_%=;\n\t" \
            "WD_%=:\n\t}" :: "r"(_m), "r"(_p) : "memory"); \
    } } while (0)

__device__ __forceinline__ unsigned enc_f(float f) {
    unsigned u = __float_as_uint(f);
    return (u & 0x80000000u) ? ~u : (u | 0x80000000u);
}
__device__ __forceinline__ float dec_f(unsigned e) {
    unsigned u = (e & 0x80000000u) ? (e ^ 0x80000000u) : ~e;
    return __uint_as_float(u);
}
__device__ __forceinline__ float sigmoidf_(float x) { return 1.0f / (1.0f + expf(-x)); }
__device__ __forceinline__ float softplusf_(float x) {
    return fmaxf(x, 0.0f) + log1pf(expf(-fabsf(x)));
}
__device__ __forceinline__ uint16_t pack_e4m3(float lo, float hi) {
    uint16_t r;
    asm("cvt.rn.satfinite.e4m3x2.f32 %0, %1, %2;" : "=h"(r) : "f"(hi), "f"(lo));
    return r;
}
// packed f32x2 -> f16x2 (lo in low half, hi in high half)
__device__ __forceinline__ uint32_t pk_h2(float lo, float hi) {
    uint32_t r;
    asm("cvt.rn.f16x2.f32 %0, %1, %2;" : "=r"(r) : "f"(hi), "f"(lo));
    return r;
}

// ---------------- prep kernels (t-fastest mapping: warp writes 2KB contiguous) ----------------
__global__ void prep_hidden_kernel(const float* __restrict__ hidden) {
    int idx = blockIdx.x * blockDim.x + threadIdx.x;   // Tc*64
    int tl = idx & 127;
    int c = (idx >> 7) & 63;
    int t = ((idx >> 13) << 7) | tl;
    const int r = tl;
    const int sw = (r >> 1) & 3;
    float acc[32];
    #pragma unroll
    for (int j = 0; j < 32; j++) acc[j] = 0.0f;
    #pragma unroll
    for (int b = 0; b < Bc; b++) {
        const float* src = hidden + ((size_t)(b * Tc + t)) * Hc + c * 32;
        float v[32];
        #pragma unroll
        for (int q = 0; q < 8; q++) {
            float4 f = *(const float4*)(src + q * 4);
            v[q*4+0] = f.x; v[q*4+1] = f.y; v[q*4+2] = f.z; v[q*4+3] = f.w;
        }
        #pragma unroll
        for (int j = 0; j < 32; j++) acc[j] += v[j];
        char* dst = (char*)g_Af + ((size_t)(((b * Tc + t) >> 7) * 64 + c)) * BLOB + r * 64;
        #pragma unroll
        for (int k16 = 0; k16 < 4; k16++) {
            uint4 u = make_uint4(pk_h2(v[k16*8+0], v[k16*8+1]), pk_h2(v[k16*8+2], v[k16*8+3]),
                                 pk_h2(v[k16*8+4], v[k16*8+5]), pk_h2(v[k16*8+6], v[k16*8+7]));
            *(uint4*)(dst + ((k16 ^ sw) << 4)) = u;
        }
    }
    float hi[32], lo[32];
    #pragma unroll
    for (int j = 0; j < 32; j++) {
        float m = acc[j] * 0.25f;
        float h = __half2float(__float2half_rn(m));
        hi[j] = m;
        lo[j] = m - h;
    }
    size_t boff = ((size_t)((t >> 7) * 64 + c)) * BLOB + r * 64;
    char* dh = (char*)g_Hmhi + boff;
    char* dl = (char*)g_Hmlo + boff;
    #pragma unroll
    for (int k16 = 0; k16 < 4; k16++) {
        uint4 uh = make_uint4(pk_h2(hi[k16*8+0], hi[k16*8+1]), pk_h2(hi[k16*8+2], hi[k16*8+3]),
                              pk_h2(hi[k16*8+4], hi[k16*8+5]), pk_h2(hi[k16*8+6], hi[k16*8+7]));
        uint4 ul = make_uint4(pk_h2(lo[k16*8+0], lo[k16*8+1]), pk_h2(lo[k16*8+2], lo[k16*8+3]),
                              pk_h2(lo[k16*8+4], lo[k16*8+5]), pk_h2(lo[k16*8+6], lo[k16*8+7]));
        *(uint4*)(dh + ((k16 ^ sw) << 4)) = uh;
        *(uint4*)(dl + ((k16 ^ sw) << 4)) = ul;
    }
}

__global__ void prep_weights_kernel(const float* __restrict__ Wg1, const float* __restrict__ Wp1,
                                    const float* __restrict__ Wobs) {
    int idx = blockIdx.x * blockDim.x + threadIdx.x;   // 1280*64
    int tl = idx & 127;
    int c = (idx >> 7) & 63;
    int row = ((idx >> 13) << 7) | tl;
    float v[32];
    const float* src;
    if (row < 512)        src = Wg1 + (size_t)row * Hc + c * 32;
    else if (row < 1024)  src = Wp1 + (size_t)(row - 512) * Hc + c * 32;
    else                  src = Wobs + (size_t)(row - 1024) * Hc + c * 32;
    #pragma unroll
    for (int q = 0; q < 8; q++) {
        float4 f = *(const float4*)(src + q * 4);
        v[q*4+0] = f.x; v[q*4+1] = f.y; v[q*4+2] = f.z; v[q*4+3] = f.w;
    }
    if (row < 1024) {
        int r = row & 127, sw = (r >> 1) & 3;
        char* dst = (char*)g_Wcf + ((size_t)((row >> 7) * 64 + c)) * BLOB + r * 64;
        #pragma unroll
        for (int k16 = 0; k16 < 4; k16++) {
            uint4 u = make_uint4(pk_h2(v[k16*8+0], v[k16*8+1]), pk_h2(v[k16*8+2], v[k16*8+3]),
                                 pk_h2(v[k16*8+4], v[k16*8+5]), pk_h2(v[k16*8+6], v[k16*8+7]));
            *(uint4*)(dst + ((k16 ^ sw) << 4)) = u;
        }
    } else {
        int r2 = row - 1024;
        int r = r2 & 127, sw = (r >> 1) & 3;
        size_t boff = ((size_t)((r2 >> 7) * 64 + c)) * BLOB + r * 64;
        char* dh = (char*)g_Wohi + boff;
        char* dl = (char*)g_Wolo + boff;
        float hi[32], lo[32];
        #pragma unroll
        for (int j = 0; j < 32; j++) {
            float h = __half2float(__float2half_rn(v[j]));
            hi[j] = v[j];
            lo[j] = v[j] - h;
        }
        #pragma unroll
        for (int k16 = 0; k16 < 4; k16++) {
            uint4 uh = make_uint4(pk_h2(hi[k16*8+0], hi[k16*8+1]), pk_h2(hi[k16*8+2], hi[k16*8+3]),
                                  pk_h2(hi[k16*8+4], hi[k16*8+5]), pk_h2(hi[k16*8+6], hi[k16*8+7]));
            uint4 ul = make_uint4(pk_h2(lo[k16*8+0], lo[k16*8+1]), pk_h2(lo[k16*8+2], lo[k16*8+3]),
                                  pk_h2(lo[k16*8+4], lo[k16*8+5]), pk_h2(lo[k16*8+6], lo[k16*8+7]));
            *(uint4*)(dh + ((k16 ^ sw) << 4)) = uh;
            *(uint4*)(dl + ((k16 ^ sw) << 4)) = ul;
        }
    }
}

// init: zero best array + fill small vectors + zero detect flags
__global__ void init_best_kernel(const float* __restrict__ bg1, const float* __restrict__ bp1,
                                 const float* __restrict__ Wg2, const float* __restrict__ Wp2) {
    int i = blockIdx.x * blockDim.x + threadIdx.x;
    if (i < Tc) g_best[i] = 0ULL;
    if (i < 1024) {
        g_bc1[i] = (i < 512) ? bg1[i] : bp1[i - 512];
        g_wc2[i] = (i < 512) ? Wg2[i] : Wp2[i - 512];
    }
    if (i == 0) { g_weird = 0; g_off4 = 0; }
}

__global__ void detect_mask_kernel(const unsigned char* __restrict__ m) {
    int i = blockIdx.x * blockDim.x + threadIdx.x;
    unsigned char c = m[i];
    int w = 0, o = 0;
    if (c > 1) w = 1;
    if (c != 0 && (i & 3)) o = 1;
    w = __reduce_or_sync(0xffffffffu, w);
    o = __reduce_or_sync(0xffffffffu, o);
    if ((threadIdx.x & 31) == 0) {
        if (w) atomicOr(&g_weird, 1);
        if (o) atomicOr(&g_off4, 1);
    }
}
__global__ void convert_mask_kernel(const void* __restrict__ m) {
    int i = blockIdx.x * blockDim.x + threadIdx.x;
    if (i >= Nc) return;
    int fmt = g_weird ? 2 : (g_off4 ? 1 : 0);
    unsigned char a;
    if (fmt == 0)      a = (((const int*)m)[i] != 0);
    else if (fmt == 1) a = (((const unsigned char*)m)[i] != 0);
    else               a = (((const float*)m)[i] != 0.0f);
    g_active[i] = a;
}

// stable block-level scan of active flags
__global__ void scan1_kernel() {
    __shared__ int sdata[256];
    int n = blockIdx.x * 256 + threadIdx.x;
    int a = g_active[n];
    sdata[threadIdx.x] = a;
    __syncthreads();
    for (int off = 1; off < 256; off <<= 1) {
        int v = (threadIdx.x >= off) ? sdata[threadIdx.x - off] : 0;
        __syncthreads();
        sdata[threadIdx.x] += v;
        __syncthreads();
    }
    g_lpos[n] = sdata[threadIdx.x] - a;
    if (threadIdx.x == 255) g_bcnt[blockIdx.x] = sdata[255];
}

__global__ void scan2_kernel() {
    __shared__ int sdata[128];
    int i = threadIdx.x;
    int cnt = g_bcnt[i];
    sdata[i] = cnt;
    __syncthreads();
    for (int off = 1; off < 128; off <<= 1) {
        int v = (i >= off) ? sdata[i - off] : 0;
        __syncthreads();
        sdata[i] += v;
        __syncthreads();
    }
    g_boff[i] = sdata[i] - cnt;
    if (i == 127) {
        g_nact = sdata[127];
        g_ngroups = (sdata[127] + 1023) >> 10;
    }
}

__global__ void posmap_kernel() {
    int n = blockIdx.x * 256 + threadIdx.x;
    if (g_active[n]) g_origidx[g_boff[n >> 8] + g_lpos[n]] = n;
}

__global__ void binv_kernel(const float* __restrict__ beliefs) {
    int row = blockIdx.x * 8 + (threadIdx.x >> 5);
    int lane = threadIdx.x & 31;
    const float4* p = reinterpret_cast<const float4*>(beliefs + (size_t)row * Dc);
    float s = 0.0f;
    #pragma unroll
    for (int r = 0; r < 2; r++) {
        float4 v = p[lane + r * 32];
        s += v.x * v.x + v.y * v.y + v.z * v.z + v.w * v.w;
    }
    #pragma unroll
    for (int o = 16; o > 0; o >>= 1) s += __shfl_down_sync(0xffffffffu, s, o);
    if (lane == 0)
        g_binv[row] = 16.0f / fmaxf(sqrtf(s), EPSC);
}

// write compacted normalized beliefs; zero-pad last partial group
__global__ void prep_beliefs_kernel(const float* __restrict__ beliefs) {
    int idx = blockIdx.x * blockDim.x + threadIdx.x;   // Nc*4
    int s = idx >> 2, c = idx & 3;
    const int nact = g_nact;
    const int lim = g_ngroups << 10;
    if (s >= lim) return;
    int r = s & 127, sw = (r >> 1) & 3;
    char* dst = (char*)g_Bb8 + ((size_t)((s >> 7) * 4 + c)) * BLOB + r * 64;
    if (s < nact) {
        int n = g_origidx[s];
        float bi = g_binv[n];
        const float* src = beliefs + (size_t)n * Dc + c * 64;
        #pragma unroll
        for (int k16 = 0; k16 < 4; k16++) {
            uint32_t w[4];
            #pragma unroll
            for (int q = 0; q < 4; q++) {
                float4 f = *(const float4*)(src + k16 * 16 + q * 4);
                uint16_t a = pack_e4m3(f.x * bi, f.y * bi);
                uint16_t b = pack_e4m3(f.z * bi, f.w * bi);
                w[q] = ((uint32_t)b << 16) | a;
            }
            *(uint4*)(dst + ((k16 ^ sw) << 4)) = make_uint4(w[0], w[1], w[2], w[3]);
        }
    } else {
        uint4 z = make_uint4(0, 0, 0, 0);
        *(uint4*)(dst)      = z;
        *(uint4*)(dst + 16) = z;
        *(uint4*)(dst + 32) = z;
        *(uint4*)(dst + 48) = z;
    }
}

// ============ merged gate/prec + obs GEMM kernel ============
#define GP_STAGE2 32768
#define OB_STAGE 32768
#define DYN_SMEM 98304

__global__ __launch_bounds__(256, 2) void gpobs_mma_kernel() {
    extern __shared__ __align__(128) char dsm[];
    __shared__ float s_b1[128], s_w2[128], s_red[128];
    __shared__ __align__(8) unsigned long long s_mbar[4];

    const int tid = threadIdx.x, lane = tid & 31, wid = tid >> 5;
    const int warp_m = (wid >> 1) * 32;
    const int warp_n = (wid & 1) * 64;
    const uint32_t sbase = smem_u32(dsm);
    const uint32_t mb = smem_u32(s_mbar);

    const int rowA = warp_m + (lane & 15);
    const uint32_t cA = (uint32_t)(lane >> 4);
    const uint32_t swA = (uint32_t)((rowA >> 1) & 3);
    const uint32_t aoff = (uint32_t)rowA * 64;
    const int rowB = warp_n + ((lane >> 4) << 3) + (lane & 7);
    const uint32_t cB = (uint32_t)((lane >> 3) & 1);
    const uint32_t swB = (uint32_t)((rowB >> 1) & 3);
    const uint32_t boff = (uint32_t)rowB * 64;

    float acc[2][8][4];
    #pragma unroll
    for (int i = 0; i < 2; i++)
        #pragma unroll
        for (int j = 0; j < 8; j++)
            #pragma unroll
            for (int k = 0; k < 4; k++) acc[i][j][k] = 0.0f;

    const int qr = lane >> 2;
    const int qc = (lane & 3) * 2;

    if (blockIdx.x < 8) {
        const int nt = blockIdx.x;
        const int mt = blockIdx.y;
        const int m0 = mt * 128, nbase = nt * 128;
        if (tid < 128) {
            s_b1[tid] = g_bc1[nbase + tid];
            s_w2[tid] = g_wc2[nbase + tid];
            s_red[tid] = 0.0f;
        }
        const char* gA = (const char*)g_Af + (size_t)mt * 64 * BLOB;
        const char* gB = (const char*)g_Wcf + (size_t)nt * 64 * BLOB;

        if (tid == 0) {
            #pragma unroll
            for (int s = 0; s < 3; s++) MBAR_INIT(mb + s * 8, 1);
        }
        __syncthreads();
        if (tid == 0) {
            #pragma unroll
            for (int c = 0; c < 2; c++) {
                const uint32_t st = sbase + c * GP_STAGE2;
                MBAR_EXPECT_TX(mb + c * 8, GP_STAGE2);
                CPBULK(st,         gA + (size_t)(2*c)     * BLOB, BLOB, mb + c * 8);
                CPBULK(st + 8192,  gA + (size_t)(2*c + 1) * BLOB, BLOB, mb + c * 8);
                CPBULK(st + 16384, gB + (size_t)(2*c)     * BLOB, BLOB, mb + c * 8);
                CPBULK(st + 24576, gB + (size_t)(2*c + 1) * BLOB, BLOB, mb + c * 8);
            }
        }

        for (int c = 0; c < 32; c++) {
            MBAR_WAIT(mb + (c % 3) * 8, (c / 3) & 1);
            __syncthreads();
            if (tid == 0 && c + 2 < 32) {
                const int s = (c + 2) % 3;
                const uint32_t st = sbase + s * GP_STAGE2;
                MBAR_EXPECT_TX(mb + s * 8, GP_STAGE2);
                CPBULK(st,         gA + (size_t)(2*(c+2))     * BLOB, BLOB, mb + s * 8);
                CPBULK(st + 8192,  gA + (size_t)(2*(c+2) + 1) * BLOB, BLOB, mb + s * 8);
                CPBULK(st + 16384, gB + (size_t)(2*(c+2))     * BLOB, BLOB, mb + s * 8);
                CPBULK(st + 24576, gB + (size_t)(2*(c+2) + 1) * BLOB, BLOB, mb + s * 8);
            }
            const uint32_t uS = sbase + (c % 3) * GP_STAGE2;
            #pragma unroll
            for (int h = 0; h < 2; h++) {
                const uint32_t uA = uS + (uint32_t)h * 8192;
                const uint32_t uB = uS + 16384 + (uint32_t)h * 8192;
                #pragma unroll
                for (int ks = 0; ks < 2; ks++) {
                    const uint32_t oa = ((cA | (ks << 1)) ^ swA) << 4;
                    const uint32_t ob = ((cB | (ks << 1)) ^ swB) << 4;
                    uint32_t a[2][4];
                    LDSM4(a[0][0], a[0][1], a[0][2], a[0][3], uA + aoff + oa);
                    LDSM4(a[1][0], a[1][1], a[1][2], a[1][3], uA + aoff + 1024 + oa);
                    uint32_t b[8][2];
                    #pragma unroll
                    for (int jp = 0; jp < 4; jp++) {
                        LDSM4(b[2*jp][0], b[2*jp][1], b[2*jp+1][0], b[2*jp+1][1],
                              uB + boff + (uint32_t)jp * 1024 + ob);
                    }
                    #pragma unroll
                    for (int mt2 = 0; mt2 < 2; mt2++)
                        #pragma unroll
                        for (int nj = 0; nj < 8; nj++)
                            MMA_F16(acc[mt2][nj], a[mt2], b[nj]);
                }
            }
        }
        __syncthreads();

        #pragma unroll
        for (int mt2 = 0; mt2 < 2; mt2++) {
            float p0 = 0.0f, p1 = 0.0f;
            #pragma unroll
            for (int nj = 0; nj < 8; nj++) {
                int col = warp_n + nj * 8 + qc;
                p0 += fmaxf(acc[mt2][nj][0] + s_b1[col], 0.0f) * s_w2[col]
                    + fmaxf(acc[mt2][nj][1] + s_b1[col + 1], 0.0f) * s_w2[col + 1];
                p1 += fmaxf(acc[mt2][nj][2] + s_b1[col], 0.0f) * s_w2[col]
                    + fmaxf(acc[mt2][nj][3] + s_b1[col + 1], 0.0f) * s_w2[col + 1];
            }
            p0 += __shfl_xor_sync(0xffffffffu, p0, 1);
            p0 += __shfl_xor_sync(0xffffffffu, p0, 2);
            p1 += __shfl_xor_sync(0xffffffffu, p1, 1);
            p1 += __shfl_xor_sync(0xffffffffu, p1, 2);
            if ((lane & 3) == 0) {
                atomicAdd(&s_red[warp_m + mt2 * 16 + qr], p0);
                atomicAdd(&s_red[warp_m + mt2 * 16 + 8 + qr], p1);
            }
        }
        __syncthreads();
        if (tid < 128) g_part[nt * MGP + m0 + tid] = s_red[tid];
    } else {
        const int id = blockIdx.y;
        if (id >= 64) return;
        const int nt = id & 1;
        const int mt = id >> 1;
        const int m0 = mt * 128, nbase = nt * 128;
        const char* gAh = (const char*)g_Hmhi + (size_t)mt * 64 * BLOB;
        const char* gAl = (const char*)g_Hmlo + (size_t)mt * 64 * BLOB;
        const char* gBh = (const char*)g_Wohi + (size_t)nt * 64 * BLOB;
        const char* gBl = (const char*)g_Wolo + (size_t)nt * 64 * BLOB;

        if (tid == 0) {
            MBAR_INIT(mb, 1);
            MBAR_INIT(mb + 8, 1);
        }
        __syncthreads();
        if (tid == 0) {
            MBAR_EXPECT_TX(mb, OB_STAGE);
            CPBULK(sbase,         gAh, BLOB, mb);
            CPBULK(sbase + 8192,  gAl, BLOB, mb);
            CPBULK(sbase + 16384, gBh, BLOB, mb);
            CPBULK(sbase + 24576, gBl, BLOB, mb);
        }

        for (int c = 0; c < 64; c++) {
            MBAR_WAIT(mb + (c & 1) * 8, (c >> 1) & 1);
            __syncthreads();
            if (tid == 0 && c + 1 < 64) {
                const int s = (c + 1) & 1;
                const uint32_t st = sbase + s * OB_STAGE;
                MBAR_EXPECT_TX(mb + s * 8, OB_STAGE);
                CPBULK(st,         gAh + (size_t)(c + 1) * BLOB, BLOB, mb + s * 8);
                CPBULK(st + 8192,  gAl + (size_t)(c + 1) * BLOB, BLOB, mb + s * 8);
                CPBULK(st + 16384, gBh + (size_t)(c + 1) * BLOB, BLOB, mb + s * 8);
                CPBULK(st + 24576, gBl + (size_t)(c + 1) * BLOB, BLOB, mb + s * 8);
            }
            const uint32_t uS = sbase + (c & 1) * OB_STAGE;
            #pragma unroll
            for (int tr = 0; tr < 3; tr++) {
                const uint32_t uA = uS + (tr == 2 ? 8192u : 0u);
                const uint32_t uB = uS + 16384u + (tr == 1 ? 8192u : 0u);
                #pragma unroll
                for (int ks = 0; ks < 2; ks++) {
                    const uint32_t oa = ((cA | (ks << 1)) ^ swA) << 4;
                    const uint32_t ob = ((cB | (ks << 1)) ^ swB) << 4;
                    uint32_t a[2][4];
                    LDSM4(a[0][0], a[0][1], a[0][2], a[0][3], uA + aoff + oa);
                    LDSM4(a[1][0], a[1][1], a[1][2], a[1][3], uA + aoff + 1024 + oa);
                    uint32_t b[8][2];
                    #pragma unroll
                    for (int jp = 0; jp < 4; jp++) {
                        LDSM4(b[2*jp][0], b[2*jp][1], b[2*jp+1][0], b[2*jp+1][1],
                              uB + boff + (uint32_t)jp * 1024 + ob);
                    }
                    #pragma unroll
                    for (int mt2 = 0; mt2 < 2; mt2++)
                        #pragma unroll
                        for (int nj = 0; nj < 8; nj++)
                            MMA_F16(acc[mt2][nj], a[mt2], b[nj]);
                }
            }
        }

        #pragma unroll
        for (int mt2 = 0; mt2 < 2; mt2++)
            #pragma unroll
            for (int nj = 0; nj < 8; nj++) {
                int row = m0 + warp_m + mt2 * 16 + qr;
                int col = nbase + warp_n + nj * 8 + qc;
                *(float2*)(g_obs_mean + (size_t)row * Dc + col) = make_float2(acc[mt2][nj][0], acc[mt2][nj][1]);
                *(float2*)(g_obs_mean + (size_t)(row + 8) * Dc + col) = make_float2(acc[mt2][nj][2], acc[mt2][nj][3]);
            }
    }
}

// ============ sims GEMM: compacted B, 16KB stages, float/idx fold ============
#define SIMS_B_OFF 32768
#define SIMS_STG 16384
#define SIMS_SMEM 98304
__global__ __launch_bounds__(256, 2) void sims_mma_kernel() {
    extern __shared__ __align__(128) char dsm[];
    __shared__ __align__(8) unsigned long long s_mbar[5];

    const int ng = blockIdx.x;
    if (ng >= g_ngroups) return;
    const int tid = threadIdx.x, lane = tid & 31, wid = tid >> 5;
    const int mt = blockIdx.y;
    const int n_base = ng * 1024, m0 = mt * 128;
    const int warp_m = (wid >> 1) * 32;
    const int warp_n = (wid & 1) * 64;
    const uint32_t sbase = smem_u32(dsm);
    const uint32_t mb = smem_u32(s_mbar);

    const int rowA = warp_m + (lane & 15);
    const uint32_t cA = (uint32_t)(lane >> 4);
    const uint32_t swA = (uint32_t)((rowA >> 1) & 3);
    const uint32_t aoff = (uint32_t)rowA * 64;
    const int rowB = warp_n + ((lane >> 4) << 3) + (lane & 7);
    const uint32_t cB = (uint32_t)((lane >> 3) & 1);
    const uint32_t swB = (uint32_t)((rowB >> 1) & 3);
    const uint32_t boff = (uint32_t)rowB * 64;

    const char* gA = (const char*)g_oang8 + (size_t)mt * 4 * BLOB;
    const char* gB = (const char*)g_Bb8 + (size_t)ng * 32 * BLOB;

    const int qr = lane >> 2;
    const int qc = (lane & 3) * 2;

    if (tid == 0) {
        #pragma unroll
        for (int s = 0; s < 5; s++) MBAR_INIT(mb + s * 8, 1);
    }
    __syncthreads();
    if (tid == 0) {
        MBAR_EXPECT_TX(mb + 32, 4 * BLOB);
        #pragma unroll
        for (int c = 0; c < 4; c++)
            CPBULK(sbase + c * BLOB, gA + (size_t)c * BLOB, BLOB, mb + 32);
        #pragma unroll
        for (int j = 0; j < 3; j++) {
            MBAR_EXPECT_TX(mb + j * 8, SIMS_STG);
            CPBULK(sbase + SIMS_B_OFF + j * SIMS_STG,        gB + (size_t)(2*j)     * BLOB, BLOB, mb + j * 8);
            CPBULK(sbase + SIMS_B_OFF + j * SIMS_STG + BLOB, gB + (size_t)(2*j + 1) * BLOB, BLOB, mb + j * 8);
        }
    }
    MBAR_WAIT(mb + 32, 0);

    float bv[4];
    int bidx[4];
    #pragma unroll
    for (int i = 0; i < 4; i++) { bv[i] = -3.0e38f; bidx[i] = 0; }
    float acc[2][8][4];

    for (int jj = 0; jj < 16; jj++) {
        const int half = jj & 1;
        const int g = jj >> 1;
        if (half == 0) {
            #pragma unroll
            for (int i = 0; i < 2; i++)
                #pragma unroll
                for (int j2 = 0; j2 < 8; j2++)
                    #pragma unroll
                    for (int k = 0; k < 4; k++) acc[i][j2][k] = 0.0f;
        }
        MBAR_WAIT(mb + (jj & 3) * 8, (jj >> 2) & 1);
        __syncthreads();
        if (tid == 0 && jj + 3 < 16) {
            const int s = (jj + 3) & 3;
            const uint32_t st = sbase + SIMS_B_OFF + s * SIMS_STG;
            MBAR_EXPECT_TX(mb + s * 8, SIMS_STG);
            CPBULK(st,        gB + (size_t)(2*(jj+3))     * BLOB, BLOB, mb + s * 8);
            CPBULK(st + BLOB, gB + (size_t)(2*(jj+3) + 1) * BLOB, BLOB, mb + s * 8);
        }
        const uint32_t uBs = sbase + SIMS_B_OFF + (uint32_t)(jj & 3) * SIMS_STG;
        #pragma unroll
        for (int h = 0; h < 2; h++) {
            const uint32_t uA = sbase + (uint32_t)(2 * half + h) * BLOB;
            const uint32_t uB = uBs + (uint32_t)h * BLOB;
            #pragma unroll
            for (int ks = 0; ks < 2; ks++) {
                const uint32_t oa = ((cA | (ks << 1)) ^ swA) << 4;
                const uint32_t ob = ((cB | (ks << 1)) ^ swB) << 4;
                uint32_t a[2][4];
                LDSM4(a[0][0], a[0][1], a[0][2], a[0][3], uA + aoff + oa);
                LDSM4(a[1][0], a[1][1], a[1][2], a[1][3], uA + aoff + 1024 + oa);
                uint32_t b[8][2];
                #pragma unroll
                for (int jp = 0; jp < 4; jp++) {
                    LDSM4(b[2*jp][0], b[2*jp][1], b[2*jp+1][0], b[2*jp+1][1],
                          uB + boff + (uint32_t)jp * 1024 + ob);
                }
                #pragma unroll
                for (int mt2 = 0; mt2 < 2; mt2++)
                    #pragma unroll
                    for (int nj = 0; nj < 8; nj++)
                        MMA_F8(acc[mt2][nj], a[mt2], b[nj]);
            }
        }
        if (half == 1) {
            const int ib = n_base + g * 128 + warp_n + qc;
            #pragma unroll
            for (int mt2 = 0; mt2 < 2; mt2++) {
                float v0 = bv[mt2 * 2], v1 = bv[mt2 * 2 + 1];
                int i0 = bidx[mt2 * 2], i1 = bidx[mt2 * 2 + 1];
                #pragma unroll
                for (int nj = 0; nj < 8; nj++) {
                    #pragma unroll
                    for (int p = 0; p < 2; p++) {
                        const int ix = ib + nj * 8 + p;
                        float x0 = acc[mt2][nj][p];
                        if (x0 > v0) { v0 = x0; i0 = ix; }
                        float x1 = acc[mt2][nj][2 + p];
                        if (x1 > v1) { v1 = x1; i1 = ix; }
                    }
                }
                bv[mt2 * 2] = v0;  bidx[mt2 * 2] = i0;
                bv[mt2 * 2 + 1] = v1; bidx[mt2 * 2 + 1] = i1;
            }
        }
    }

    #pragma unroll
    for (int h = 0; h < 4; h++) {
        float v = bv[h];
        int i = bidx[h];
        #pragma unroll
        for (int off = 1; off <= 2; off <<= 1) {
            float v2 = __shfl_xor_sync(0xffffffffu, v, off);
            int i2 = __shfl_xor_sync(0xffffffffu, i, off);
            if (v2 > v || (v2 == v && i2 < i)) { v = v2; i = i2; }
        }
        if ((lane & 3) == 0) {
            const int mt2 = h >> 1;
            const int row = m0 + warp_m + mt2 * 16 + ((h & 1) ? 8 : 0) + qr;
            unsigned long long q = ((unsigned long long)enc_f(v) << 32)
                                 | (0xFFFFFFFFu - (unsigned)i);
            atomicMax(&g_best[row], q);
        }
    }
}

// ---------------- finalize1 v2: warp-per-row, shuffle-only ----------------
__global__ __launch_bounds__(256) void finalize1_kernel(
    const float* __restrict__ bg2, const float* __restrict__ bp2,
    float* __restrict__ out_obs, float* __restrict__ out_meaning, int write_extra)
{
    const int w = threadIdx.x >> 5, lane = threadIdx.x & 31;
    const int t = blockIdx.x * 8 + w;
    const float* src = g_obs_mean + (size_t)t * Dc + lane * 8;
    float4 v0 = *(const float4*)(src);
    float4 v1 = *(const float4*)(src + 4);
    float ss = v0.x*v0.x + v0.y*v0.y + v0.z*v0.z + v0.w*v0.w
             + v1.x*v1.x + v1.y*v1.y + v1.z*v1.z + v1.w*v1.w;
    #pragma unroll
    for (int o = 16; o > 0; o >>= 1) ss += __shfl_xor_sync(0xffffffffu, ss, o);

    float pv = 0.0f;
    if (lane < 4) {
        int row = lane * Tc + t;
        float gl = bg2[0], pl = bp2[0];
        #pragma unroll
        for (int jt = 0; jt < 4; jt++) gl += g_part[jt * MGP + row];
        #pragma unroll
        for (int jt = 4; jt < 8; jt++) pl += g_part[jt * MGP + row];
        pv = sigmoidf_(gl) * softplusf_(pl);
    }
    pv += __shfl_xor_sync(0xffffffffu, pv, 1);
    pv += __shfl_xor_sync(0xffffffffu, pv, 2);
    float pm = __shfl_sync(0xffffffffu, pv, 0) * 0.25f;

    float nrm = sqrtf(ss);
    float inv = 1.0f / fmaxf(nrm, EPSC);
    float sc = inv * pm;
    float ob[8] = {v0.x*sc, v0.y*sc, v0.z*sc, v0.w*sc, v1.x*sc, v1.y*sc, v1.z*sc, v1.w*sc};
    float* dsto = out_obs + (size_t)t * Dc + lane * 8;
    *(float4*)(dsto)     = make_float4(ob[0], ob[1], ob[2], ob[3]);
    *(float4*)(dsto + 4) = make_float4(ob[4], ob[5], ob[6], ob[7]);

    float rr = nrm * sc;                       // ||obs_beliefs||
    if (lane == 0) {
        g_rad[t] = rr;
        if (write_extra) out_meaning[t] = (rr > 0.05f) ? 1.0f : 0.0f;
    }
    float rinv = 1.0f / fmaxf(rr, EPSC);
    float asc = rinv * 16.0f;
    uint16_t p0 = pack_e4m3(ob[0]*asc, ob[1]*asc);
    uint16_t p1 = pack_e4m3(ob[2]*asc, ob[3]*asc);
    uint16_t p2 = pack_e4m3(ob[4]*asc, ob[5]*asc);
    uint16_t p3 = pack_e4m3(ob[6]*asc, ob[7]*asc);
    unsigned long long val = (unsigned long long)p0
                           | ((unsigned long long)p1 << 16)
                           | ((unsigned long long)p2 << 32)
                           | ((unsigned long long)p3 << 48);
    int col0 = lane * 8;
    int mt = t >> 7, r = t & 127, sw = (r >> 1) & 3;
    int c = col0 >> 6;
    int pos = col0 & 63;
    int k16 = pos >> 4;
    size_t off = ((size_t)(mt * 4 + c)) * BLOB + r * 64 + ((k16 ^ sw) << 4) + (pos & 15);
    *(unsigned long long*)(g_oang8 + off) = val;
}

__global__ void finalize2_kernel(float* __restrict__ out_sims, float* __restrict__ out_slots) {
    int t = blockIdx.x * blockDim.x + threadIdx.x;
    if (t >= Tc) return;
    unsigned long long b = g_best[t];
    float sim = 0.0f;
    int idx = -1;
    bool has = (b != 0ULL);
    if (has) {
        sim = dec_f((unsigned)(b >> 32)) * 0.00390625f;
        unsigned slot = 0xFFFFFFFFu - (unsigned)(b & 0xFFFFFFFFu);
        idx = g_origidx[slot & (Nc - 1)];
    }
    bool matched = has && (g_rad[t] > 0.05f) && (sim > 0.5f);
    out_sims[t]  = matched ? sim : 0.0f;
    out_slots[t] = matched ? (float)idx : -1.0f;
}

// ---------------- launcher ----------------
extern "C" void kernel_launch(void* const* d_in, const int* in_sizes, int n_in,
                              void* d_out, int out_size)
{
    const float* hidden  = (const float*)d_in[0];
    const float* beliefs = (const float*)d_in[1];
    const void*  maskp   = d_in[2];
    const float* W_obs   = (const float*)d_in[3];
    const float* W_g1    = (const float*)d_in[4];
    const float* b_g1    = (const float*)d_in[5];
    const float* W_g2    = (const float*)d_in[6];
    const float* b_g2    = (const float*)d_in[7];
    const float* W_p1    = (const float*)d_in[8];
    const float* b_p1    = (const float*)d_in[9];
    const float* W_p2    = (const float*)d_in[10];
    const float* b_p2    = (const float*)d_in[11];
    float* out = (float*)d_out;

    static cudaStream_t s2 = nullptr;
    static cudaEvent_t evF = nullptr, evJ = nullptr;
    static int attr_set = 0;
    if (!attr_set) {
        cudaFuncSetAttribute(gpobs_mma_kernel, cudaFuncAttributeMaxDynamicSharedMemorySize, DYN_SMEM);
        cudaFuncSetAttribute(sims_mma_kernel, cudaFuncAttributeMaxDynamicSharedMemorySize, SIMS_SMEM);
        cudaStreamCreateWithFlags(&s2, cudaStreamNonBlocking);
        cudaEventCreateWithFlags(&evF, cudaEventDisableTiming);
        cudaEventCreateWithFlags(&evJ, cudaEventDisableTiming);
        attr_set = 1;
    }

    const size_t base = (size_t)Tc * Dc;
    const int write_extra = (out_size >= (int)(base + 3 * Tc)) ? 1 : 0;
    float* out_obs     = out;
    float* out_sims    = out + base;
    float* out_slots   = out + base + Tc;
    float* out_meaning = out + base + 2 * Tc;

    // stream 0: heavy preps first
    init_best_kernel<<<Tc / 256, 256>>>(b_g1, b_p1, W_g2, W_p2);
    prep_hidden_kernel<<<(Tc * 64) / 256, 256>>>(hidden);
    prep_weights_kernel<<<(1280 * 64) / 256, 256>>>(W_g1, W_p1, W_obs);

    // fork s2 AFTER the DRAM-heavy preps: its DRAM-bound chain overlaps tensor-bound gpobs
    cudaEventRecord(evF, 0);
    cudaStreamWaitEvent(s2, evF, 0);
    detect_mask_kernel<<<Nc / 256, 256, 0, s2>>>((const unsigned char*)maskp);
    convert_mask_kernel<<<Nc / 256, 256, 0, s2>>>(maskp);
    scan1_kernel<<<128, 256, 0, s2>>>();
    scan2_kernel<<<1, 128, 0, s2>>>();
    posmap_kernel<<<128, 256, 0, s2>>>();
    binv_kernel<<<Nc / 8, 256, 0, s2>>>(beliefs);
    prep_beliefs_kernel<<<(Nc * 4) / 256, 256, 0, s2>>>(beliefs);

    gpobs_mma_kernel<<<dim3(9, MGP / 128), 256, DYN_SMEM>>>();
    finalize1_kernel<<<Tc / 8, 256>>>(b_g2, b_p2, out_obs, out_meaning, write_extra);

    // join before sims (needs compacted beliefs + counts from s2)
    cudaEventRecord(evJ, s2);
    cudaStreamWaitEvent(0, evJ, 0);
    sims_mma_kernel<<<dim3(32, 32), 256, SIMS_SMEM>>>();
    if (write_extra) {
        finalize2_kernel<<<Tc / 256, 256>>>(out_sims, out_slots);
    }
}